// round 1
// baseline (speedup 1.0000x reference)
#include <cuda_runtime.h>
#include <math.h>

#define NSEQ 3136
#define CD   768
#define NH   12
#define HD   64
#define HID  3072
#define C3   2304

// ---------------- scratch (static device globals; no allocation) -------------
__device__ float g_xn[NSEQ * CD];
__device__ float g_qkv[NSEQ * C3];
__device__ float g_attn[(long)NH * NSEQ * NSEQ];   // 472 MB
__device__ float g_attout[NSEQ * CD];
__device__ float g_x2[NSEQ * CD];
__device__ float g_h0[NSEQ * CD];
__device__ float g_h1[NSEQ * HID];
__device__ int   g_maskByte;

// ---------------- helpers ----------------------------------------------------
__device__ __forceinline__ float warpSum(float v) {
#pragma unroll
    for (int o = 16; o; o >>= 1) v += __shfl_xor_sync(0xffffffffu, v, o);
    return v;
}
__device__ __forceinline__ float warpMax(float v) {
#pragma unroll
    for (int o = 16; o; o >>= 1) v = fmaxf(v, __shfl_xor_sync(0xffffffffu, v, o));
    return v;
}

// ---------------- mask dtype detection ---------------------------------------
// bool bytes packed into u32 give values >1 with overwhelming probability;
// an int32 mask of {0,1} never does. Deterministic each call.
__global__ void mask_detect_kernel(const unsigned int* __restrict__ m) {
    __shared__ int flag;
    if (threadIdx.x == 0) flag = 0;
    __syncthreads();
    for (int i = threadIdx.x; i < NSEQ / 4; i += 256)
        if (m[i] > 1u) flag = 1;
    __syncthreads();
    if (threadIdx.x == 0) g_maskByte = flag;
}

__device__ __forceinline__ bool mask_at(const void* mask, int col) {
    if (g_maskByte) return ((const unsigned char*)mask)[col] != 0;
    return ((const int*)mask)[col] != 0;
}

// ---------------- layernorm ---------------------------------------------------
__global__ void __launch_bounds__(256) ln_kernel(
    const float* __restrict__ x, const float* __restrict__ sc,
    const float* __restrict__ bi, float* __restrict__ y)
{
    int row = blockIdx.x;
    const float* xr = x + (long)row * CD;
    float* yr = y + (long)row * CD;
    int t = threadIdx.x;
    float v[3];
    float s = 0.f, s2 = 0.f;
#pragma unroll
    for (int i = 0; i < 3; i++) {
        float a = xr[t + i * 256];
        v[i] = a; s += a; s2 += a * a;
    }
    __shared__ float sh[32], sh2[32];
    float ws = warpSum(s), ws2 = warpSum(s2);
    int lane = t & 31, wid = t >> 5;
    if (lane == 0) { sh[wid] = ws; sh2[wid] = ws2; }
    __syncthreads();
    if (wid == 0) {
        float a = lane < 8 ? sh[lane] : 0.f;
        float b = lane < 8 ? sh2[lane] : 0.f;
        a = warpSum(a); b = warpSum(b);
        if (lane == 0) { sh[0] = a; sh2[0] = b; }
    }
    __syncthreads();
    float mu  = sh[0] * (1.f / CD);
    float var = sh2[0] * (1.f / CD) - mu * mu;
    float inv = rsqrtf(var + 1e-5f);
#pragma unroll
    for (int i = 0; i < 3; i++) {
        int c = t + i * 256;
        yr[c] = (v[i] - mu) * inv * sc[c] + bi[c];
    }
}

// ---------------- softmax over rows of g_attn ---------------------------------
__global__ void __launch_bounds__(256) softmax_kernel(float* __restrict__ attn)
{
    long row = blockIdx.x;
    float* p = attn + row * (long)NSEQ;
    __shared__ float buf[NSEQ];
    __shared__ float red[32];
    int t = threadIdx.x;
    float mx = -3.4e38f;
    for (int i = t; i < NSEQ; i += 256) {
        float v = p[i]; buf[i] = v; mx = fmaxf(mx, v);
    }
    mx = warpMax(mx);
    if ((t & 31) == 0) red[t >> 5] = mx;
    __syncthreads();
    if (t < 32) {
        float v = t < 8 ? red[t] : -3.4e38f;
        v = warpMax(v);
        if (t == 0) red[0] = v;
    }
    __syncthreads();
    mx = red[0];
    __syncthreads();
    float s = 0.f;
    for (int i = t; i < NSEQ; i += 256) {
        float e = expf(buf[i] - mx);
        buf[i] = e; s += e;
    }
    s = warpSum(s);
    if ((t & 31) == 0) red[t >> 5] = s;
    __syncthreads();
    if (t < 32) {
        float v = t < 8 ? red[t] : 0.f;
        v = warpSum(v);
        if (t == 0) red[0] = v;
    }
    __syncthreads();
    float inv = 1.f / red[0];
    for (int i = t; i < NSEQ; i += 256) p[i] = buf[i] * inv;
}

// ---------------- tiled GEMM with fused epilogues ------------------------------
// C[M,N] = A[M,K] * op(B) (+ epilogue). TB=true: B is [N,K] row-major (C=A*B^T).
// TB=false: B is [K,N] row-major. All of M,N multiples of 64; K multiple of 16.
#define BM 64
#define BN 64
#define BK 16

enum { EPI_PLAIN = 0, EPI_BIAS = 1, EPI_QKV = 2, EPI_SM = 3, EPI_GELU = 4, EPI_RES = 5 };

template<int EPI, bool TB>
__global__ void __launch_bounds__(256) gemm_kernel(
    const float* __restrict__ A, const float* __restrict__ B, float* __restrict__ Cc,
    int M, int N, int K, int lda, int ldb, int ldc,
    long sAb, long sBb, long sCb,
    const float* __restrict__ bias, const float* __restrict__ bias2,
    const float* __restrict__ res, const float* __restrict__ gamma,
    float alpha, const void* __restrict__ mask)
{
    int bz = blockIdx.z;
    A  += (long)bz * sAb;
    B  += (long)bz * sBb;
    Cc += (long)bz * sCb;

    __shared__ float As[BK][BM + 4];
    __shared__ float Bs[BK][BN + 4];

    int tid = threadIdx.x;
    int tx = tid & 15, ty = tid >> 4;
    int m0 = blockIdx.x * BM, n0 = blockIdx.y * BN;

    int ra = tid >> 2,  ca = (tid & 3) * 4;    // A / TB-B loads: 64 rows x 16 k
    int rb = tid >> 4,  cb = (tid & 15) * 4;   // NN-B loads: 16 k x 64 n

    float acc[4][4];
#pragma unroll
    for (int i = 0; i < 4; i++)
#pragma unroll
        for (int j = 0; j < 4; j++) acc[i][j] = 0.f;

    for (int k0 = 0; k0 < K; k0 += BK) {
        float4 a4 = *(const float4*)&A[(long)(m0 + ra) * lda + k0 + ca];
        As[ca + 0][ra] = a4.x; As[ca + 1][ra] = a4.y;
        As[ca + 2][ra] = a4.z; As[ca + 3][ra] = a4.w;
        if (TB) {
            float4 b4 = *(const float4*)&B[(long)(n0 + ra) * ldb + k0 + ca];
            Bs[ca + 0][ra] = b4.x; Bs[ca + 1][ra] = b4.y;
            Bs[ca + 2][ra] = b4.z; Bs[ca + 3][ra] = b4.w;
        } else {
            float4 b4 = *(const float4*)&B[(long)(k0 + rb) * ldb + n0 + cb];
            *(float4*)&Bs[rb][cb] = b4;
        }
        __syncthreads();
#pragma unroll
        for (int kk = 0; kk < BK; kk++) {
            float4 av = *(const float4*)&As[kk][ty * 4];
            float4 bv = *(const float4*)&Bs[kk][tx * 4];
            float a0 = av.x, a1 = av.y, a2 = av.z, a3 = av.w;
            float b0 = bv.x, b1 = bv.y, b2 = bv.z, b3 = bv.w;
            acc[0][0] += a0 * b0; acc[0][1] += a0 * b1; acc[0][2] += a0 * b2; acc[0][3] += a0 * b3;
            acc[1][0] += a1 * b0; acc[1][1] += a1 * b1; acc[1][2] += a1 * b2; acc[1][3] += a1 * b3;
            acc[2][0] += a2 * b0; acc[2][1] += a2 * b1; acc[2][2] += a2 * b2; acc[2][3] += a2 * b3;
            acc[3][0] += a3 * b0; acc[3][1] += a3 * b1; acc[3][2] += a3 * b2; acc[3][3] += a3 * b3;
        }
        __syncthreads();
    }

#pragma unroll
    for (int i = 0; i < 4; i++) {
        int row = m0 + ty * 4 + i;
#pragma unroll
        for (int j = 0; j < 4; j++) {
            int col = n0 + tx * 4 + j;
            float v = acc[i][j];
            if (EPI == EPI_BIAS) {
                v += bias[col];
            } else if (EPI == EPI_QKV) {
                float bb = (col < CD) ? bias[col]
                         : (col < 2 * CD) ? 0.f : bias2[col - 2 * CD];
                v += bb;
            } else if (EPI == EPI_SM) {
                v *= alpha;
                if (mask_at(mask, col)) v = -1e30f;
            } else if (EPI == EPI_GELU) {
                v += bias[col];
                v = 0.5f * v * (1.f + erff(v * 0.70710678118654752f));
            } else if (EPI == EPI_RES) {
                v = res[(long)row * ldc + col] + gamma[col] * (v + bias[col]);
            }
            Cc[(long)row * ldc + col] = v;
        }
    }
}

// ---------------- launch -------------------------------------------------------
extern "C" void kernel_launch(void* const* d_in, const int* in_sizes, int n_in,
                              void* d_out, int out_size)
{
    const float* x      = (const float*)d_in[0];
    const void*  mask   = d_in[1];
    const float* qkv_w  = (const float*)d_in[2];
    const float* q_bias = (const float*)d_in[3];
    const float* v_bias = (const float*)d_in[4];
    const float* proj_w = (const float*)d_in[5];
    const float* proj_b = (const float*)d_in[6];
    const float* n1s    = (const float*)d_in[7];
    const float* n1b    = (const float*)d_in[8];
    const float* n2s    = (const float*)d_in[9];
    const float* n2b    = (const float*)d_in[10];
    const float* w1     = (const float*)d_in[11];
    const float* b1     = (const float*)d_in[12];
    const float* w2     = (const float*)d_in[13];
    const float* b2     = (const float*)d_in[14];
    const float* g1     = (const float*)d_in[15];
    const float* g2     = (const float*)d_in[16];
    float* out = (float*)d_out;

    float *xn, *qkv, *attn, *attout, *x2, *h0, *h1;
    cudaGetSymbolAddress((void**)&xn,     g_xn);
    cudaGetSymbolAddress((void**)&qkv,    g_qkv);
    cudaGetSymbolAddress((void**)&attn,   g_attn);
    cudaGetSymbolAddress((void**)&attout, g_attout);
    cudaGetSymbolAddress((void**)&x2,     g_x2);
    cudaGetSymbolAddress((void**)&h0,     g_h0);
    cudaGetSymbolAddress((void**)&h1,     g_h1);

    const long NN = (long)NSEQ * NSEQ;
    const float scale = 0.125f;  // 64^-0.5

    // 1. LN1
    ln_kernel<<<NSEQ, 256>>>(x, n1s, n1b, xn);
    // mask dtype detection
    mask_detect_kernel<<<1, 256>>>((const unsigned int*)mask);

    // 2. QKV: [3136,2304] = xn @ qkv_w^T + [q_bias, 0, v_bias]
    gemm_kernel<EPI_QKV, true><<<dim3(NSEQ / 64, C3 / 64, 1), 256>>>(
        xn, qkv_w, qkv, NSEQ, C3, CD, CD, CD, C3,
        0, 0, 0, q_bias, v_bias, nullptr, nullptr, 1.f, nullptr);

    // 3. S[h] = scale * q_h @ k_h^T, masked
    gemm_kernel<EPI_SM, true><<<dim3(NSEQ / 64, NSEQ / 64, NH), 256>>>(
        qkv, qkv + CD, attn, NSEQ, NSEQ, HD, C3, C3, NSEQ,
        HD, HD, NN, nullptr, nullptr, nullptr, nullptr, scale, mask);

    // 4. softmax over keys
    softmax_kernel<<<NH * NSEQ, 256>>>(attn);

    // 5. O[h] = P_h @ v_h   (NN GEMM), scattered into [3136, 768]
    gemm_kernel<EPI_PLAIN, false><<<dim3(NSEQ / 64, 1, NH), 256>>>(
        attn, qkv + 2 * CD, attout, NSEQ, HD, NSEQ, NSEQ, C3, CD,
        NN, HD, HD, nullptr, nullptr, nullptr, nullptr, 1.f, nullptr);

    // 6. proj + residual: x2 = x + gamma1 * (attout @ proj_w^T + proj_b)
    gemm_kernel<EPI_RES, true><<<dim3(NSEQ / 64, CD / 64, 1), 256>>>(
        attout, proj_w, x2, NSEQ, CD, CD, CD, CD, CD,
        0, 0, 0, proj_b, nullptr, x, g1, 1.f, nullptr);

    // 7. LN2
    ln_kernel<<<NSEQ, 256>>>(x2, n2s, n2b, h0);

    // 8. MLP1 + exact GELU
    gemm_kernel<EPI_GELU, true><<<dim3(NSEQ / 64, HID / 64, 1), 256>>>(
        h0, w1, h1, NSEQ, HID, CD, CD, CD, HID,
        0, 0, 0, b1, nullptr, nullptr, nullptr, 1.f, nullptr);

    // 9. MLP2 + final residual: out = x2 + gamma2 * (h1 @ mlp_w2^T + b2)
    gemm_kernel<EPI_RES, true><<<dim3(NSEQ / 64, CD / 64, 1), 256>>>(
        h1, w2, out, NSEQ, CD, HID, HID, HID, CD,
        0, 0, 0, b2, nullptr, x2, g2, 1.f, nullptr);
}

// round 2
// speedup vs baseline: 1.9075x; 1.9075x over previous
#include <cuda_runtime.h>
#include <math.h>

#define NSEQ 3136
#define CD   768
#define NH   12
#define HD   64
#define HID  3072
#define C3   2304

// ---------------- scratch (static device globals; no allocation) -------------
__device__ float g_xn[NSEQ * CD];
__device__ float g_qkv[NSEQ * C3];
__device__ float g_attn[(long)NH * NSEQ * NSEQ];   // 472 MB
__device__ float g_attout[NSEQ * CD];
__device__ float g_x2[NSEQ * CD];
__device__ float g_h0[NSEQ * CD];
__device__ float g_h1[NSEQ * HID];
__device__ int   g_maskByte;

// ---------------- helpers ----------------------------------------------------
__device__ __forceinline__ float warpSum(float v) {
#pragma unroll
    for (int o = 16; o; o >>= 1) v += __shfl_xor_sync(0xffffffffu, v, o);
    return v;
}
__device__ __forceinline__ float warpMax(float v) {
#pragma unroll
    for (int o = 16; o; o >>= 1) v = fmaxf(v, __shfl_xor_sync(0xffffffffu, v, o));
    return v;
}

__device__ __forceinline__ unsigned f2tf(float x) {
    unsigned r;
    asm("cvt.rna.tf32.f32 %0, %1;" : "=r"(r) : "f"(x));
    return r;
}
__device__ __forceinline__ void cp16(void* s, const void* g) {
    unsigned a = (unsigned)__cvta_generic_to_shared(s);
    asm volatile("cp.async.ca.shared.global [%0], [%1], 16;" :: "r"(a), "l"(g));
}
__device__ __forceinline__ void mma_tf32(float* c, const unsigned* a, unsigned b0, unsigned b1) {
    asm volatile(
        "mma.sync.aligned.m16n8k8.row.col.f32.tf32.tf32.f32 "
        "{%0,%1,%2,%3}, {%4,%5,%6,%7}, {%8,%9}, {%0,%1,%2,%3};"
        : "+f"(c[0]), "+f"(c[1]), "+f"(c[2]), "+f"(c[3])
        : "r"(a[0]), "r"(a[1]), "r"(a[2]), "r"(a[3]), "r"(b0), "r"(b1));
}

// ---------------- mask dtype detection ---------------------------------------
__global__ void mask_detect_kernel(const unsigned int* __restrict__ m) {
    __shared__ int flag;
    if (threadIdx.x == 0) flag = 0;
    __syncthreads();
    for (int i = threadIdx.x; i < NSEQ / 4; i += 256)
        if (m[i] > 1u) flag = 1;
    __syncthreads();
    if (threadIdx.x == 0) g_maskByte = flag;
}

__device__ __forceinline__ bool mask_at(const void* mask, int col, int mbyte) {
    if (mbyte) return ((const unsigned char*)mask)[col] != 0;
    return ((const int*)mask)[col] != 0;
}

// ---------------- layernorm ---------------------------------------------------
__global__ void __launch_bounds__(256) ln_kernel(
    const float* __restrict__ x, const float* __restrict__ sc,
    const float* __restrict__ bi, float* __restrict__ y)
{
    int row = blockIdx.x;
    const float* xr = x + (long)row * CD;
    float* yr = y + (long)row * CD;
    int t = threadIdx.x;
    float v[3];
    float s = 0.f, s2 = 0.f;
#pragma unroll
    for (int i = 0; i < 3; i++) {
        float a = xr[t + i * 256];
        v[i] = a; s += a; s2 += a * a;
    }
    __shared__ float sh[32], sh2[32];
    float ws = warpSum(s), ws2 = warpSum(s2);
    int lane = t & 31, wid = t >> 5;
    if (lane == 0) { sh[wid] = ws; sh2[wid] = ws2; }
    __syncthreads();
    if (wid == 0) {
        float a = lane < 8 ? sh[lane] : 0.f;
        float b = lane < 8 ? sh2[lane] : 0.f;
        a = warpSum(a); b = warpSum(b);
        if (lane == 0) { sh[0] = a; sh2[0] = b; }
    }
    __syncthreads();
    float mu  = sh[0] * (1.f / CD);
    float var = sh2[0] * (1.f / CD) - mu * mu;
    float inv = rsqrtf(var + 1e-5f);
#pragma unroll
    for (int i = 0; i < 3; i++) {
        int c = t + i * 256;
        yr[c] = (v[i] - mu) * inv * sc[c] + bi[c];
    }
}

// ---------------- softmax over rows of g_attn ---------------------------------
__global__ void __launch_bounds__(256) softmax_kernel(float* __restrict__ attn)
{
    long row = blockIdx.x;
    float* p = attn + row * (long)NSEQ;
    __shared__ float buf[NSEQ];
    __shared__ float red[32];
    int t = threadIdx.x;
    float mx = -3.4e38f;
    for (int i = t; i < NSEQ; i += 256) {
        float v = p[i]; buf[i] = v; mx = fmaxf(mx, v);
    }
    mx = warpMax(mx);
    if ((t & 31) == 0) red[t >> 5] = mx;
    __syncthreads();
    if (t < 32) {
        float v = t < 8 ? red[t] : -3.4e38f;
        v = warpMax(v);
        if (t == 0) red[0] = v;
    }
    __syncthreads();
    mx = red[0];
    __syncthreads();
    float s = 0.f;
    for (int i = t; i < NSEQ; i += 256) {
        float e = __expf(buf[i] - mx);
        buf[i] = e; s += e;
    }
    s = warpSum(s);
    if ((t & 31) == 0) red[t >> 5] = s;
    __syncthreads();
    if (t < 32) {
        float v = t < 8 ? red[t] : 0.f;
        v = warpSum(v);
        if (t == 0) red[0] = v;
    }
    __syncthreads();
    float inv = 1.f / red[0];
    for (int i = t; i < NSEQ; i += 256) p[i] = buf[i] * inv;
}

// ---------------- tf32 mma.sync GEMM with fused epilogues ----------------------
// C[M,N] = A[M,K] * op(B) (+ epilogue).
// TB=true: B is [N,K] row-major (C = A @ B^T). TB=false: B is [K,N] row-major.
// K must be a multiple of 16. M, N handled with clamped loads / guarded stores.
enum { EPI_PLAIN = 0, EPI_QKV = 2, EPI_SM = 3, EPI_GELU = 4, EPI_RES = 5 };

template<int EPI, bool TB, int BM, int BN>
__global__ void __launch_bounds__(256) mmgemm(
    const float* __restrict__ A, const float* __restrict__ B, float* __restrict__ Cc,
    int M, int N, int K, int lda, int ldb, int ldc,
    long sAb, long sBb, long sCb,
    const float* __restrict__ bias, const float* __restrict__ bias2,
    const float* __restrict__ res, const float* __restrict__ gamma,
    float alpha, const void* __restrict__ mask)
{
    constexpr int BK = 16;
    constexpr int WM = BM / 4;          // warp tile M (warps arranged 4 x 2)
    constexpr int WN = BN / 2;          // warp tile N
    constexpr int MI = WM / 16;
    constexpr int NI = WN / 8;
    constexpr int LDAS = BK + 4;        // 20 floats: conflict-free for frag loads
    constexpr int LDBS = TB ? (BK + 4) : (BN + 8);
    constexpr int BSZ  = TB ? BN * LDBS : BK * LDBS;

    __shared__ float As[2][BM * LDAS];
    __shared__ float Bs[2][BSZ];

    int bz = blockIdx.z;
    A  += (long)bz * sAb;
    B  += (long)bz * sBb;
    Cc += (long)bz * sCb;

    int tid  = threadIdx.x;
    int wid  = tid >> 5;
    int lane = tid & 31;
    int g = lane >> 2, t = lane & 3;
    int wm = (wid & 3) * WM;
    int wn = (wid >> 2) * WN;
    int m0 = blockIdx.x * BM, n0 = blockIdx.y * BN;
    int mbyte = (EPI == EPI_SM) ? g_maskByte : 0;

    auto ldA = [&](int buf, int k0) {
#pragma unroll
        for (int i = 0; i < BM * 4 / 256; i++) {
            int idx = tid + i * 256;
            int r = idx >> 2, c = (idx & 3) * 4;
            int row = m0 + r; if (row >= M) row = M - 1;
            cp16(&As[buf][r * LDAS + c], &A[(long)row * lda + k0 + c]);
        }
    };
    auto ldB = [&](int buf, int k0) {
        if (TB) {
#pragma unroll
            for (int i = 0; i < BN * 4 / 256; i++) {
                int idx = tid + i * 256;
                int r = idx >> 2, c = (idx & 3) * 4;
                int row = n0 + r; if (row >= N) row = N - 1;
                cp16(&Bs[buf][r * LDBS + c], &B[(long)row * ldb + k0 + c]);
            }
        } else {
            constexpr int CPR = BN / 4;      // 16B chunks per row
#pragma unroll
            for (int i = 0; i < BK * BN / 4 / 256; i++) {
                int idx = tid + i * 256;
                int r = idx / CPR, c = (idx % CPR) * 4;
                cp16(&Bs[buf][r * LDBS + c], &B[(long)(k0 + r) * ldb + n0 + c]);
            }
        }
    };

    float acc[MI][NI][4];
#pragma unroll
    for (int mi = 0; mi < MI; mi++)
#pragma unroll
        for (int ni = 0; ni < NI; ni++)
#pragma unroll
            for (int e = 0; e < 4; e++) acc[mi][ni][e] = 0.f;

    int KT = K / BK;
    ldA(0, 0); ldB(0, 0);
    asm volatile("cp.async.commit_group;");

    for (int kt = 0; kt < KT; kt++) {
        int cur = kt & 1;
        if (kt + 1 < KT) {
            ldA(cur ^ 1, (kt + 1) * BK);
            ldB(cur ^ 1, (kt + 1) * BK);
            asm volatile("cp.async.commit_group;");
            asm volatile("cp.async.wait_group 1;");
        } else {
            asm volatile("cp.async.wait_group 0;");
        }
        __syncthreads();

        const float* as = As[cur];
        const float* bs = Bs[cur];
#pragma unroll
        for (int kk = 0; kk < BK; kk += 8) {
            unsigned af[MI][4], bf[NI][2];
#pragma unroll
            for (int mi = 0; mi < MI; mi++) {
                int r = wm + mi * 16 + g;
                af[mi][0] = f2tf(as[r * LDAS + kk + t]);
                af[mi][1] = f2tf(as[(r + 8) * LDAS + kk + t]);
                af[mi][2] = f2tf(as[r * LDAS + kk + t + 4]);
                af[mi][3] = f2tf(as[(r + 8) * LDAS + kk + t + 4]);
            }
#pragma unroll
            for (int ni = 0; ni < NI; ni++) {
                int n = wn + ni * 8 + g;
                if (TB) {
                    bf[ni][0] = f2tf(bs[n * LDBS + kk + t]);
                    bf[ni][1] = f2tf(bs[n * LDBS + kk + t + 4]);
                } else {
                    bf[ni][0] = f2tf(bs[(kk + t) * LDBS + n]);
                    bf[ni][1] = f2tf(bs[(kk + t + 4) * LDBS + n]);
                }
            }
#pragma unroll
            for (int mi = 0; mi < MI; mi++)
#pragma unroll
                for (int ni = 0; ni < NI; ni++)
                    mma_tf32(acc[mi][ni], af[mi], bf[ni][0], bf[ni][1]);
        }
        __syncthreads();
    }

    // ---------------- epilogue ----------------
#pragma unroll
    for (int mi = 0; mi < MI; mi++) {
#pragma unroll
        for (int ni = 0; ni < NI; ni++) {
            int col = n0 + wn + ni * 8 + 2 * t;
            if (col >= N) continue;
#pragma unroll
            for (int half = 0; half < 2; half++) {
                int row = m0 + wm + mi * 16 + g + half * 8;
                if (row >= M) continue;
                float v0 = acc[mi][ni][half * 2 + 0];
                float v1 = acc[mi][ni][half * 2 + 1];
                if (EPI == EPI_QKV) {
                    float b0 = (col < CD) ? bias[col]
                             : (col < 2 * CD) ? 0.f : bias2[col - 2 * CD];
                    int c1 = col + 1;
                    float b1 = (c1 < CD) ? bias[c1]
                             : (c1 < 2 * CD) ? 0.f : bias2[c1 - 2 * CD];
                    v0 += b0; v1 += b1;
                } else if (EPI == EPI_SM) {
                    v0 *= alpha; v1 *= alpha;
                    if (mask_at(mask, col, mbyte))     v0 = -1e30f;
                    if (mask_at(mask, col + 1, mbyte)) v1 = -1e30f;
                } else if (EPI == EPI_GELU) {
                    v0 += bias[col]; v1 += bias[col + 1];
                    v0 = 0.5f * v0 * (1.f + erff(v0 * 0.70710678118654752f));
                    v1 = 0.5f * v1 * (1.f + erff(v1 * 0.70710678118654752f));
                } else if (EPI == EPI_RES) {
                    const float* rr = &res[(long)row * ldc + col];
                    v0 = rr[0] + gamma[col]     * (v0 + bias[col]);
                    v1 = rr[1] + gamma[col + 1] * (v1 + bias[col + 1]);
                }
                float2 o; o.x = v0; o.y = v1;
                *(float2*)&Cc[(long)row * ldc + col] = o;
            }
        }
    }
}

// ---------------- launch -------------------------------------------------------
extern "C" void kernel_launch(void* const* d_in, const int* in_sizes, int n_in,
                              void* d_out, int out_size)
{
    const float* x      = (const float*)d_in[0];
    const void*  mask   = d_in[1];
    const float* qkv_w  = (const float*)d_in[2];
    const float* q_bias = (const float*)d_in[3];
    const float* v_bias = (const float*)d_in[4];
    const float* proj_w = (const float*)d_in[5];
    const float* proj_b = (const float*)d_in[6];
    const float* n1s    = (const float*)d_in[7];
    const float* n1b    = (const float*)d_in[8];
    const float* n2s    = (const float*)d_in[9];
    const float* n2b    = (const float*)d_in[10];
    const float* w1     = (const float*)d_in[11];
    const float* b1     = (const float*)d_in[12];
    const float* w2     = (const float*)d_in[13];
    const float* b2     = (const float*)d_in[14];
    const float* g1     = (const float*)d_in[15];
    const float* g2     = (const float*)d_in[16];
    float* out = (float*)d_out;

    float *xn, *qkv, *attn, *attout, *x2, *h0, *h1;
    cudaGetSymbolAddress((void**)&xn,     g_xn);
    cudaGetSymbolAddress((void**)&qkv,    g_qkv);
    cudaGetSymbolAddress((void**)&attn,   g_attn);
    cudaGetSymbolAddress((void**)&attout, g_attout);
    cudaGetSymbolAddress((void**)&x2,     g_x2);
    cudaGetSymbolAddress((void**)&h0,     g_h0);
    cudaGetSymbolAddress((void**)&h1,     g_h1);

    const long NN = (long)NSEQ * NSEQ;
    const float scale = 0.125f;  // 64^-0.5
    const int GM = (NSEQ + 127) / 128;   // 25

    // 1. LN1 + mask dtype detection
    ln_kernel<<<NSEQ, 256>>>(x, n1s, n1b, xn);
    mask_detect_kernel<<<1, 256>>>((const unsigned int*)mask);

    // 2. QKV: [3136,2304] = xn @ qkv_w^T + [q_bias, 0, v_bias]
    mmgemm<EPI_QKV, true, 128, 128><<<dim3(GM, C3 / 128, 1), 256>>>(
        xn, qkv_w, qkv, NSEQ, C3, CD, CD, CD, C3,
        0, 0, 0, q_bias, v_bias, nullptr, nullptr, 1.f, nullptr);

    // 3. S[h] = scale * q_h @ k_h^T, masked
    mmgemm<EPI_SM, true, 128, 128><<<dim3(GM, GM, NH), 256>>>(
        qkv, qkv + CD, attn, NSEQ, NSEQ, HD, C3, C3, NSEQ,
        HD, HD, NN, nullptr, nullptr, nullptr, nullptr, scale, mask);

    // 4. softmax over keys
    softmax_kernel<<<NH * NSEQ, 256>>>(attn);

    // 5. O[h] = P_h @ v_h
    mmgemm<EPI_PLAIN, false, 128, 64><<<dim3(GM, 1, NH), 256>>>(
        attn, qkv + 2 * CD, attout, NSEQ, HD, NSEQ, NSEQ, C3, CD,
        NN, HD, HD, nullptr, nullptr, nullptr, nullptr, 1.f, nullptr);

    // 6. proj + residual: x2 = x + gamma1 * (attout @ proj_w^T + proj_b)
    mmgemm<EPI_RES, true, 128, 128><<<dim3(GM, CD / 128, 1), 256>>>(
        attout, proj_w, x2, NSEQ, CD, CD, CD, CD, CD,
        0, 0, 0, proj_b, nullptr, x, g1, 1.f, nullptr);

    // 7. LN2
    ln_kernel<<<NSEQ, 256>>>(x2, n2s, n2b, h0);

    // 8. MLP1 + exact GELU
    mmgemm<EPI_GELU, true, 128, 128><<<dim3(GM, HID / 128, 1), 256>>>(
        h0, w1, h1, NSEQ, HID, CD, CD, CD, HID,
        0, 0, 0, b1, nullptr, nullptr, nullptr, 1.f, nullptr);

    // 9. MLP2 + final residual: out = x2 + gamma2 * (h1 @ mlp_w2^T + b2)
    mmgemm<EPI_RES, true, 128, 128><<<dim3(GM, CD / 128, 1), 256>>>(
        h1, w2, out, NSEQ, CD, HID, HID, HID, CD,
        0, 0, 0, b2, nullptr, x2, g2, 1.f, nullptr);
}

// round 3
// speedup vs baseline: 2.3058x; 1.2088x over previous
#include <cuda_runtime.h>
#include <math.h>

#define NSEQ 3136
#define CD   768
#define NH   12
#define HD   64
#define HID  3072
#define C3   2304

// ---------------- scratch (static device globals; no allocation) -------------
__device__ float g_xn[NSEQ * CD];
__device__ float g_qkv[NSEQ * C3];
__device__ float g_attout[NSEQ * CD];
__device__ float g_x2[NSEQ * CD];
__device__ float g_h0[NSEQ * CD];
__device__ float g_h1[NSEQ * HID];
__device__ float g_maskf[NSEQ];
__device__ int   g_maskByte;

// ---------------- helpers ----------------------------------------------------
__device__ __forceinline__ float warpSum(float v) {
#pragma unroll
    for (int o = 16; o; o >>= 1) v += __shfl_xor_sync(0xffffffffu, v, o);
    return v;
}

__device__ __forceinline__ unsigned f2tf(float x) {
    unsigned r;
    asm("cvt.rna.tf32.f32 %0, %1;" : "=r"(r) : "f"(x));
    return r;
}
__device__ __forceinline__ void cp16(void* s, const void* g) {
    unsigned a = (unsigned)__cvta_generic_to_shared(s);
    asm volatile("cp.async.ca.shared.global [%0], [%1], 16;" :: "r"(a), "l"(g));
}
__device__ __forceinline__ void mma_tf32(float* c, const unsigned* a, unsigned b0, unsigned b1) {
    asm volatile(
        "mma.sync.aligned.m16n8k8.row.col.f32.tf32.tf32.f32 "
        "{%0,%1,%2,%3}, {%4,%5,%6,%7}, {%8,%9}, {%0,%1,%2,%3};"
        : "+f"(c[0]), "+f"(c[1]), "+f"(c[2]), "+f"(c[3])
        : "r"(a[0]), "r"(a[1]), "r"(a[2]), "r"(a[3]), "r"(b0), "r"(b1));
}

// ---------------- mask prep ---------------------------------------------------
__global__ void mask_detect_kernel(const unsigned int* __restrict__ m) {
    __shared__ int flag;
    if (threadIdx.x == 0) flag = 0;
    __syncthreads();
    for (int i = threadIdx.x; i < NSEQ / 4; i += 256)
        if (m[i] > 1u) flag = 1;
    __syncthreads();
    if (threadIdx.x == 0) g_maskByte = flag;
}

__global__ void mask_prep_kernel(const void* __restrict__ mask, float* __restrict__ mf) {
    int i = blockIdx.x * 256 + threadIdx.x;
    if (i < NSEQ) {
        bool m = g_maskByte ? (((const unsigned char*)mask)[i] != 0)
                            : (((const int*)mask)[i] != 0);
        mf[i] = m ? -1e30f : 0.f;
    }
}

// ---------------- layernorm ---------------------------------------------------
__global__ void __launch_bounds__(256) ln_kernel(
    const float* __restrict__ x, const float* __restrict__ sc,
    const float* __restrict__ bi, float* __restrict__ y)
{
    int row = blockIdx.x;
    const float* xr = x + (long)row * CD;
    float* yr = y + (long)row * CD;
    int t = threadIdx.x;
    float v[3];
    float s = 0.f, s2 = 0.f;
#pragma unroll
    for (int i = 0; i < 3; i++) {
        float a = xr[t + i * 256];
        v[i] = a; s += a; s2 += a * a;
    }
    __shared__ float sh[32], sh2[32];
    float ws = warpSum(s), ws2 = warpSum(s2);
    int lane = t & 31, wid = t >> 5;
    if (lane == 0) { sh[wid] = ws; sh2[wid] = ws2; }
    __syncthreads();
    if (wid == 0) {
        float a = lane < 8 ? sh[lane] : 0.f;
        float b = lane < 8 ? sh2[lane] : 0.f;
        a = warpSum(a); b = warpSum(b);
        if (lane == 0) { sh[0] = a; sh2[0] = b; }
    }
    __syncthreads();
    float mu  = sh[0] * (1.f / CD);
    float var = sh2[0] * (1.f / CD) - mu * mu;
    float inv = rsqrtf(var + 1e-5f);
#pragma unroll
    for (int i = 0; i < 3; i++) {
        int c = t + i * 256;
        yr[c] = (v[i] - mu) * inv * sc[c] + bi[c];
    }
}

// ---------------- flash attention ---------------------------------------------
// One block = one (q-tile of 128, head). 8 warps, warp owns 16 query rows.
// Streams K/V in 64-key tiles (double-buffered cp.async). Online softmax.
#define LDK 68
#define LDV 72
#define LDP 68
#define FLASH_SMEM ((2*64*LDK + 2*64*LDV + 8*16*LDP + 2*64) * 4)

__global__ void __launch_bounds__(256) flash_kernel(
    const float* __restrict__ qkv, const float* __restrict__ maskf,
    float* __restrict__ attout)
{
    extern __shared__ float sm[];
    float* Ks = sm;                       // 2 * 64*LDK
    float* Vs = Ks + 2 * 64 * LDK;        // 2 * 64*LDV
    float* Ps = Vs + 2 * 64 * LDV;        // 8 * 16*LDP
    float* Ms = Ps + 8 * 16 * LDP;        // 2 * 64

    int h  = blockIdx.y;
    int m0 = blockIdx.x * 128;
    int tid = threadIdx.x, wid = tid >> 5, lane = tid & 31;
    int g = lane >> 2, t = lane & 3;

    const float* Qp = qkv + h * HD;
    const float* Kp = qkv + CD + h * HD;
    const float* Vp = qkv + 2 * CD + h * HD;

    // Q fragments, pre-scaled by 1/sqrt(hd)
    unsigned qf[8][4];
    {
        int r0 = m0 + wid * 16 + g; if (r0 >= NSEQ) r0 = NSEQ - 1;
        int r1 = r0 + 8;            if (r1 >= NSEQ) r1 = NSEQ - 1;
        const float* q0 = Qp + (long)r0 * C3;
        const float* q1 = Qp + (long)r1 * C3;
#pragma unroll
        for (int kb = 0; kb < 8; kb++) {
            qf[kb][0] = f2tf(q0[kb * 8 + t]     * 0.125f);
            qf[kb][1] = f2tf(q1[kb * 8 + t]     * 0.125f);
            qf[kb][2] = f2tf(q0[kb * 8 + t + 4] * 0.125f);
            qf[kb][3] = f2tf(q1[kb * 8 + t + 4] * 0.125f);
        }
    }

    float o[8][4];
#pragma unroll
    for (int ni = 0; ni < 8; ni++)
#pragma unroll
        for (int e = 0; e < 4; e++) o[ni][e] = 0.f;
    float mr0 = -3.4e38f, mr1 = -3.4e38f, lr0 = 0.f, lr1 = 0.f;

    auto loadKV = [&](int buf, int j0) {
#pragma unroll
        for (int i = 0; i < 4; i++) {
            int idx = tid + i * 256;           // 0..1023
            int r = idx >> 4, c = (idx & 15) * 4;
            cp16(&Ks[buf * 64 * LDK + r * LDK + c], &Kp[(long)(j0 + r) * C3 + c]);
            cp16(&Vs[buf * 64 * LDV + r * LDV + c], &Vp[(long)(j0 + r) * C3 + c]);
        }
        if (tid < 16) cp16(&Ms[buf * 64 + tid * 4], &maskf[j0 + tid * 4]);
    };

    loadKV(0, 0);
    asm volatile("cp.async.commit_group;");

    const int NJ = NSEQ / 64;   // 49
    float* pw = Ps + wid * 16 * LDP;

    for (int j = 0; j < NJ; j++) {
        int cur = j & 1;
        if (j + 1 < NJ) {
            loadKV(cur ^ 1, (j + 1) * 64);
            asm volatile("cp.async.commit_group;");
            asm volatile("cp.async.wait_group 1;");
        } else {
            asm volatile("cp.async.wait_group 0;");
        }
        __syncthreads();

        const float* ks = Ks + cur * 64 * LDK;
        const float* vs = Vs + cur * 64 * LDV;
        const float* ms = Ms + cur * 64;

        // S = Qs @ K^T
        float s[8][4];
#pragma unroll
        for (int ni = 0; ni < 8; ni++) { s[ni][0] = s[ni][1] = s[ni][2] = s[ni][3] = 0.f; }
#pragma unroll
        for (int kb = 0; kb < 8; kb++) {
#pragma unroll
            for (int ni = 0; ni < 8; ni++) {
                unsigned b0 = f2tf(ks[(ni * 8 + g) * LDK + kb * 8 + t]);
                unsigned b1 = f2tf(ks[(ni * 8 + g) * LDK + kb * 8 + t + 4]);
                mma_tf32(s[ni], qf[kb], b0, b1);
            }
        }

        // mask bias + row max
        float rm0 = -3.4e38f, rm1 = -3.4e38f;
#pragma unroll
        for (int ni = 0; ni < 8; ni++) {
            int c0 = ni * 8 + 2 * t;
            float a0 = ms[c0], a1 = ms[c0 + 1];
            s[ni][0] += a0; s[ni][1] += a1; s[ni][2] += a0; s[ni][3] += a1;
            rm0 = fmaxf(rm0, fmaxf(s[ni][0], s[ni][1]));
            rm1 = fmaxf(rm1, fmaxf(s[ni][2], s[ni][3]));
        }
        rm0 = fmaxf(rm0, __shfl_xor_sync(0xffffffffu, rm0, 1));
        rm0 = fmaxf(rm0, __shfl_xor_sync(0xffffffffu, rm0, 2));
        rm1 = fmaxf(rm1, __shfl_xor_sync(0xffffffffu, rm1, 1));
        rm1 = fmaxf(rm1, __shfl_xor_sync(0xffffffffu, rm1, 2));
        float mn0 = fmaxf(mr0, rm0), mn1 = fmaxf(mr1, rm1);
        float f0 = __expf(mr0 - mn0), f1 = __expf(mr1 - mn1);
        mr0 = mn0; mr1 = mn1;

        // P = exp(S - m), to per-warp smem; accumulate row sums
        float rs0 = 0.f, rs1 = 0.f;
#pragma unroll
        for (int ni = 0; ni < 8; ni++) {
            float p00 = __expf(s[ni][0] - mn0), p01 = __expf(s[ni][1] - mn0);
            float p10 = __expf(s[ni][2] - mn1), p11 = __expf(s[ni][3] - mn1);
            rs0 += p00 + p01; rs1 += p10 + p11;
            int c0 = ni * 8 + 2 * t;
            *(float2*)&pw[g * LDP + c0]       = make_float2(p00, p01);
            *(float2*)&pw[(g + 8) * LDP + c0] = make_float2(p10, p11);
        }
        rs0 += __shfl_xor_sync(0xffffffffu, rs0, 1);
        rs0 += __shfl_xor_sync(0xffffffffu, rs0, 2);
        rs1 += __shfl_xor_sync(0xffffffffu, rs1, 1);
        rs1 += __shfl_xor_sync(0xffffffffu, rs1, 2);
        lr0 = lr0 * f0 + rs0; lr1 = lr1 * f1 + rs1;

        // rescale O
#pragma unroll
        for (int ni = 0; ni < 8; ni++) {
            o[ni][0] *= f0; o[ni][1] *= f0; o[ni][2] *= f1; o[ni][3] *= f1;
        }
        __syncwarp();

        // O += P @ V
#pragma unroll
        for (int kb = 0; kb < 8; kb++) {
            unsigned af[4];
            af[0] = f2tf(pw[g * LDP + kb * 8 + t]);
            af[1] = f2tf(pw[(g + 8) * LDP + kb * 8 + t]);
            af[2] = f2tf(pw[g * LDP + kb * 8 + t + 4]);
            af[3] = f2tf(pw[(g + 8) * LDP + kb * 8 + t + 4]);
#pragma unroll
            for (int ni = 0; ni < 8; ni++) {
                unsigned b0 = f2tf(vs[(kb * 8 + t) * LDV + ni * 8 + g]);
                unsigned b1 = f2tf(vs[(kb * 8 + t + 4) * LDV + ni * 8 + g]);
                mma_tf32(o[ni], af, b0, b1);
            }
        }
        __syncthreads();   // protect K/V buffers before next prefetch overwrites
    }

    // normalize + store
    float inv0 = 1.f / lr0, inv1 = 1.f / lr1;
    int r0 = m0 + wid * 16 + g, r1 = r0 + 8;
#pragma unroll
    for (int ni = 0; ni < 8; ni++) {
        int col = h * HD + ni * 8 + 2 * t;
        if (r0 < NSEQ)
            *(float2*)&attout[(long)r0 * CD + col] = make_float2(o[ni][0] * inv0, o[ni][1] * inv0);
        if (r1 < NSEQ)
            *(float2*)&attout[(long)r1 * CD + col] = make_float2(o[ni][2] * inv1, o[ni][3] * inv1);
    }
}

// ---------------- tf32 mma.sync GEMM with fused epilogues ----------------------
enum { EPI_PLAIN = 0, EPI_QKV = 2, EPI_GELU = 4, EPI_RES = 5 };

template<int EPI, bool TB, int BM, int BN>
__global__ void __launch_bounds__(256) mmgemm(
    const float* __restrict__ A, const float* __restrict__ B, float* __restrict__ Cc,
    int M, int N, int K, int lda, int ldb, int ldc,
    const float* __restrict__ bias, const float* __restrict__ bias2,
    const float* __restrict__ res, const float* __restrict__ gamma)
{
    constexpr int BK = 16;
    constexpr int WM = BM / 4;
    constexpr int WN = BN / 2;
    constexpr int MI = WM / 16;
    constexpr int NI = WN / 8;
    constexpr int LDAS = BK + 4;
    constexpr int LDBS = TB ? (BK + 4) : (BN + 8);
    constexpr int BSZ  = TB ? BN * LDBS : BK * LDBS;

    __shared__ float As[2][BM * LDAS];
    __shared__ float Bs[2][BSZ];

    int tid  = threadIdx.x;
    int wid  = tid >> 5;
    int lane = tid & 31;
    int g = lane >> 2, t = lane & 3;
    int wm = (wid & 3) * WM;
    int wn = (wid >> 2) * WN;
    int m0 = blockIdx.x * BM, n0 = blockIdx.y * BN;

    auto ldA = [&](int buf, int k0) {
#pragma unroll
        for (int i = 0; i < BM * 4 / 256; i++) {
            int idx = tid + i * 256;
            int r = idx >> 2, c = (idx & 3) * 4;
            int row = m0 + r; if (row >= M) row = M - 1;
            cp16(&As[buf][r * LDAS + c], &A[(long)row * lda + k0 + c]);
        }
    };
    auto ldB = [&](int buf, int k0) {
        if (TB) {
#pragma unroll
            for (int i = 0; i < BN * 4 / 256; i++) {
                int idx = tid + i * 256;
                int r = idx >> 2, c = (idx & 3) * 4;
                int row = n0 + r; if (row >= N) row = N - 1;
                cp16(&Bs[buf][r * LDBS + c], &B[(long)row * ldb + k0 + c]);
            }
        } else {
            constexpr int CPR = BN / 4;
#pragma unroll
            for (int i = 0; i < BK * BN / 4 / 256; i++) {
                int idx = tid + i * 256;
                int r = idx / CPR, c = (idx % CPR) * 4;
                cp16(&Bs[buf][r * LDBS + c], &B[(long)(k0 + r) * ldb + n0 + c]);
            }
        }
    };

    float acc[MI][NI][4];
#pragma unroll
    for (int mi = 0; mi < MI; mi++)
#pragma unroll
        for (int ni = 0; ni < NI; ni++)
#pragma unroll
            for (int e = 0; e < 4; e++) acc[mi][ni][e] = 0.f;

    int KT = K / BK;
    ldA(0, 0); ldB(0, 0);
    asm volatile("cp.async.commit_group;");

    for (int kt = 0; kt < KT; kt++) {
        int cur = kt & 1;
        if (kt + 1 < KT) {
            ldA(cur ^ 1, (kt + 1) * BK);
            ldB(cur ^ 1, (kt + 1) * BK);
            asm volatile("cp.async.commit_group;");
            asm volatile("cp.async.wait_group 1;");
        } else {
            asm volatile("cp.async.wait_group 0;");
        }
        __syncthreads();

        const float* as = As[cur];
        const float* bs = Bs[cur];
#pragma unroll
        for (int kk = 0; kk < BK; kk += 8) {
            unsigned af[MI][4], bf[NI][2];
#pragma unroll
            for (int mi = 0; mi < MI; mi++) {
                int r = wm + mi * 16 + g;
                af[mi][0] = f2tf(as[r * LDAS + kk + t]);
                af[mi][1] = f2tf(as[(r + 8) * LDAS + kk + t]);
                af[mi][2] = f2tf(as[r * LDAS + kk + t + 4]);
                af[mi][3] = f2tf(as[(r + 8) * LDAS + kk + t + 4]);
            }
#pragma unroll
            for (int ni = 0; ni < NI; ni++) {
                int n = wn + ni * 8 + g;
                if (TB) {
                    bf[ni][0] = f2tf(bs[n * LDBS + kk + t]);
                    bf[ni][1] = f2tf(bs[n * LDBS + kk + t + 4]);
                } else {
                    bf[ni][0] = f2tf(bs[(kk + t) * LDBS + n]);
                    bf[ni][1] = f2tf(bs[(kk + t + 4) * LDBS + n]);
                }
            }
#pragma unroll
            for (int mi = 0; mi < MI; mi++)
#pragma unroll
                for (int ni = 0; ni < NI; ni++)
                    mma_tf32(acc[mi][ni], af[mi], bf[ni][0], bf[ni][1]);
        }
        __syncthreads();
    }

#pragma unroll
    for (int mi = 0; mi < MI; mi++) {
#pragma unroll
        for (int ni = 0; ni < NI; ni++) {
            int col = n0 + wn + ni * 8 + 2 * t;
            if (col >= N) continue;
#pragma unroll
            for (int half = 0; half < 2; half++) {
                int row = m0 + wm + mi * 16 + g + half * 8;
                if (row >= M) continue;
                float v0 = acc[mi][ni][half * 2 + 0];
                float v1 = acc[mi][ni][half * 2 + 1];
                if (EPI == EPI_QKV) {
                    float b0 = (col < CD) ? bias[col]
                             : (col < 2 * CD) ? 0.f : bias2[col - 2 * CD];
                    int c1 = col + 1;
                    float b1 = (c1 < CD) ? bias[c1]
                             : (c1 < 2 * CD) ? 0.f : bias2[c1 - 2 * CD];
                    v0 += b0; v1 += b1;
                } else if (EPI == EPI_GELU) {
                    v0 += bias[col]; v1 += bias[col + 1];
                    v0 = 0.5f * v0 * (1.f + erff(v0 * 0.70710678118654752f));
                    v1 = 0.5f * v1 * (1.f + erff(v1 * 0.70710678118654752f));
                } else if (EPI == EPI_RES) {
                    const float* rr = &res[(long)row * ldc + col];
                    v0 = rr[0] + gamma[col]     * (v0 + bias[col]);
                    v1 = rr[1] + gamma[col + 1] * (v1 + bias[col + 1]);
                }
                float2 ov; ov.x = v0; ov.y = v1;
                *(float2*)&Cc[(long)row * ldc + col] = ov;
            }
        }
    }
}

// ---------------- launch -------------------------------------------------------
extern "C" void kernel_launch(void* const* d_in, const int* in_sizes, int n_in,
                              void* d_out, int out_size)
{
    const float* x      = (const float*)d_in[0];
    const void*  mask   = d_in[1];
    const float* qkv_w  = (const float*)d_in[2];
    const float* q_bias = (const float*)d_in[3];
    const float* v_bias = (const float*)d_in[4];
    const float* proj_w = (const float*)d_in[5];
    const float* proj_b = (const float*)d_in[6];
    const float* n1s    = (const float*)d_in[7];
    const float* n1b    = (const float*)d_in[8];
    const float* n2s    = (const float*)d_in[9];
    const float* n2b    = (const float*)d_in[10];
    const float* w1     = (const float*)d_in[11];
    const float* b1     = (const float*)d_in[12];
    const float* w2     = (const float*)d_in[13];
    const float* b2     = (const float*)d_in[14];
    const float* g1     = (const float*)d_in[15];
    const float* g2     = (const float*)d_in[16];
    float* out = (float*)d_out;

    float *xn, *qkv, *attout, *x2, *h0, *h1, *maskf;
    cudaGetSymbolAddress((void**)&xn,     g_xn);
    cudaGetSymbolAddress((void**)&qkv,    g_qkv);
    cudaGetSymbolAddress((void**)&attout, g_attout);
    cudaGetSymbolAddress((void**)&x2,     g_x2);
    cudaGetSymbolAddress((void**)&h0,     g_h0);
    cudaGetSymbolAddress((void**)&h1,     g_h1);
    cudaGetSymbolAddress((void**)&maskf,  g_maskf);

    static int smem_set = 0;
    if (!smem_set) {
        cudaFuncSetAttribute(flash_kernel,
                             cudaFuncAttributeMaxDynamicSharedMemorySize, FLASH_SMEM);
        smem_set = 1;
    }

    const int GM = (NSEQ + 127) / 128;   // 25

    // 1. LN1 + mask prep
    ln_kernel<<<NSEQ, 256>>>(x, n1s, n1b, xn);
    mask_detect_kernel<<<1, 256>>>((const unsigned int*)mask);
    mask_prep_kernel<<<(NSEQ + 255) / 256, 256>>>(mask, maskf);

    // 2. QKV projection
    mmgemm<EPI_QKV, true, 128, 128><<<dim3(GM, C3 / 128, 1), 256>>>(
        xn, qkv_w, qkv, NSEQ, C3, CD, CD, CD, C3,
        q_bias, v_bias, nullptr, nullptr);

    // 3-5. flash attention (QK^T + mask + softmax + PV fused)
    flash_kernel<<<dim3(GM, NH), 256, FLASH_SMEM>>>(qkv, maskf, attout);

    // 6. proj + residual
    mmgemm<EPI_RES, true, 128, 128><<<dim3(GM, CD / 128, 1), 256>>>(
        attout, proj_w, x2, NSEQ, CD, CD, CD, CD, CD,
        proj_b, nullptr, x, g1);

    // 7. LN2
    ln_kernel<<<NSEQ, 256>>>(x2, n2s, n2b, h0);

    // 8. MLP1 + exact GELU
    mmgemm<EPI_GELU, true, 128, 128><<<dim3(GM, HID / 128, 1), 256>>>(
        h0, w1, h1, NSEQ, HID, CD, CD, CD, HID,
        b1, nullptr, nullptr, nullptr);

    // 9. MLP2 + final residual
    mmgemm<EPI_RES, true, 128, 128><<<dim3(GM, CD / 128, 1), 256>>>(
        h1, w2, out, NSEQ, CD, HID, HID, HID, CD,
        b2, nullptr, x2, g2);
}

// round 5
// speedup vs baseline: 2.3892x; 1.0362x over previous
#include <cuda_runtime.h>
#include <math.h>

#define NSEQ 3136
#define CD   768
#define NH   12
#define HD   64
#define HID  3072
#define C3   2304

// ---------------- scratch (static device globals; no allocation) -------------
__device__ float g_xn[NSEQ * CD];
__device__ float g_qkv[NSEQ * C3];
__device__ float g_attout[NSEQ * CD];
__device__ float g_x2[NSEQ * CD];
__device__ float g_h0[NSEQ * CD];
__device__ float g_h1[NSEQ * HID];
__device__ float g_maskf[NSEQ];
__device__ int   g_maskByte;

// ---------------- helpers ----------------------------------------------------
__device__ __forceinline__ float warpSum(float v) {
#pragma unroll
    for (int o = 16; o; o >>= 1) v += __shfl_xor_sync(0xffffffffu, v, o);
    return v;
}

__device__ __forceinline__ unsigned f2tf(float x) {
    unsigned r;
    asm("cvt.rna.tf32.f32 %0, %1;" : "=r"(r) : "f"(x));
    return r;
}
__device__ __forceinline__ void cp16(void* s, const void* g) {
    unsigned a = (unsigned)__cvta_generic_to_shared(s);
    asm volatile("cp.async.ca.shared.global [%0], [%1], 16;" :: "r"(a), "l"(g));
}
__device__ __forceinline__ void mma_tf32(float* c, const unsigned* a, unsigned b0, unsigned b1) {
    asm volatile(
        "mma.sync.aligned.m16n8k8.row.col.f32.tf32.tf32.f32 "
        "{%0,%1,%2,%3}, {%4,%5,%6,%7}, {%8,%9}, {%0,%1,%2,%3};"
        : "+f"(c[0]), "+f"(c[1]), "+f"(c[2]), "+f"(c[3])
        : "r"(a[0]), "r"(a[1]), "r"(a[2]), "r"(a[3]), "r"(b0), "r"(b1));
}

// ---------------- mask prep ---------------------------------------------------
__global__ void mask_detect_kernel(const unsigned int* __restrict__ m) {
    __shared__ int flag;
    if (threadIdx.x == 0) flag = 0;
    __syncthreads();
    for (int i = threadIdx.x; i < NSEQ / 4; i += 256)
        if (m[i] > 1u) flag = 1;
    __syncthreads();
    if (threadIdx.x == 0) g_maskByte = flag;
}

__global__ void mask_prep_kernel(const void* __restrict__ mask, float* __restrict__ mf) {
    int i = blockIdx.x * 256 + threadIdx.x;
    if (i < NSEQ) {
        bool m = g_maskByte ? (((const unsigned char*)mask)[i] != 0)
                            : (((const int*)mask)[i] != 0);
        mf[i] = m ? -1e30f : 0.f;
    }
}

// ---------------- layernorm ---------------------------------------------------
__global__ void __launch_bounds__(256) ln_kernel(
    const float* __restrict__ x, const float* __restrict__ sc,
    const float* __restrict__ bi, float* __restrict__ y)
{
    int row = blockIdx.x;
    const float* xr = x + (long)row * CD;
    float* yr = y + (long)row * CD;
    int t = threadIdx.x;
    float v[3];
    float s = 0.f, s2 = 0.f;
#pragma unroll
    for (int i = 0; i < 3; i++) {
        float a = xr[t + i * 256];
        v[i] = a; s += a; s2 += a * a;
    }
    __shared__ float sh[32], sh2[32];
    float ws = warpSum(s), ws2 = warpSum(s2);
    int lane = t & 31, wid = t >> 5;
    if (lane == 0) { sh[wid] = ws; sh2[wid] = ws2; }
    __syncthreads();
    if (wid == 0) {
        float a = lane < 8 ? sh[lane] : 0.f;
        float b = lane < 8 ? sh2[lane] : 0.f;
        a = warpSum(a); b = warpSum(b);
        if (lane == 0) { sh[0] = a; sh2[0] = b; }
    }
    __syncthreads();
    float mu  = sh[0] * (1.f / CD);
    float var = sh2[0] * (1.f / CD) - mu * mu;
    float inv = rsqrtf(var + 1e-5f);
#pragma unroll
    for (int i = 0; i < 3; i++) {
        int c = t + i * 256;
        yr[c] = (v[i] - mu) * inv * sc[c] + bi[c];
    }
}

// ---------------- flash attention ---------------------------------------------
// One block = one (q-tile of 128, head). 8 warps, warp owns 16 query rows.
// K/V double-buffered via cp.async, pre-converted to tf32 bits in smem once
// per tile. Online softmax. 2 blocks/SM.
#define LDK 68
#define LDV 72
#define LDP 68
#define FLASH_SMEM ((2*64*LDK + 2*64*LDV + 8*16*LDP + 2*64) * 4)

__global__ void __launch_bounds__(256, 2) flash_kernel(
    const float* __restrict__ qkv, const float* __restrict__ maskf,
    float* __restrict__ attout)
{
    extern __shared__ float sm[];
    float* Ks = sm;                       // 2 * 64*LDK
    float* Vs = Ks + 2 * 64 * LDK;        // 2 * 64*LDV
    float* Ps = Vs + 2 * 64 * LDV;        // 8 * 16*LDP  (tf32 bits)
    float* Ms = Ps + 8 * 16 * LDP;        // 2 * 64

    int h  = blockIdx.y;
    int m0 = blockIdx.x * 128;
    int tid = threadIdx.x, wid = tid >> 5, lane = tid & 31;
    int g = lane >> 2, t = lane & 3;

    const float* Qp = qkv + h * HD;
    const float* Kp = qkv + CD + h * HD;
    const float* Vp = qkv + 2 * CD + h * HD;

    // Q fragments, pre-scaled by 1/sqrt(hd)
    unsigned qf[8][4];
    {
        int r0 = m0 + wid * 16 + g; if (r0 >= NSEQ) r0 = NSEQ - 1;
        int r1 = r0 + 8;            if (r1 >= NSEQ) r1 = NSEQ - 1;
        const float* q0 = Qp + (long)r0 * C3;
        const float* q1 = Qp + (long)r1 * C3;
#pragma unroll
        for (int kb = 0; kb < 8; kb++) {
            qf[kb][0] = f2tf(q0[kb * 8 + t]     * 0.125f);
            qf[kb][1] = f2tf(q1[kb * 8 + t]     * 0.125f);
            qf[kb][2] = f2tf(q0[kb * 8 + t + 4] * 0.125f);
            qf[kb][3] = f2tf(q1[kb * 8 + t + 4] * 0.125f);
        }
    }

    float o[8][4];
#pragma unroll
    for (int ni = 0; ni < 8; ni++)
#pragma unroll
        for (int e = 0; e < 4; e++) o[ni][e] = 0.f;
    float mr0 = -3.4e38f, mr1 = -3.4e38f, lr0 = 0.f, lr1 = 0.f;

    auto loadKV = [&](int buf, int j0) {
#pragma unroll
        for (int i = 0; i < 4; i++) {
            int idx = tid + i * 256;           // 0..1023
            int r = idx >> 4, c = (idx & 15) * 4;
            cp16(&Ks[buf * 64 * LDK + r * LDK + c], &Kp[(long)(j0 + r) * C3 + c]);
            cp16(&Vs[buf * 64 * LDV + r * LDV + c], &Vp[(long)(j0 + r) * C3 + c]);
        }
        if (tid < 16) cp16(&Ms[buf * 64 + tid * 4], &maskf[j0 + tid * 4]);
    };

    loadKV(0, 0);
    asm volatile("cp.async.commit_group;");

    const int NJ = NSEQ / 64;   // 49
    unsigned* pw = (unsigned*)(Ps + wid * 16 * LDP);

    for (int j = 0; j < NJ; j++) {
        int cur = j & 1;
        asm volatile("cp.async.wait_group 0;");
        __syncthreads();                       // data ready + prev compute done
        if (j + 1 < NJ) {
            loadKV(cur ^ 1, (j + 1) * 64);     // overlaps convert + compute
            asm volatile("cp.async.commit_group;");
        }

        float* kbuf = Ks + cur * 64 * LDK;
        float* vbuf = Vs + cur * 64 * LDV;
        // one-pass in-place conversion to tf32 bits (cooperative, no redundancy)
#pragma unroll
        for (int i = 0; i < 4; i++) {
            int idx = tid + i * 256;
            int r = idx >> 4, c = (idx & 15) * 4;
            float4 kv = *(float4*)&kbuf[r * LDK + c];
            *(uint4*)&kbuf[r * LDK + c] =
                make_uint4(f2tf(kv.x), f2tf(kv.y), f2tf(kv.z), f2tf(kv.w));
            float4 vv = *(float4*)&vbuf[r * LDV + c];
            *(uint4*)&vbuf[r * LDV + c] =
                make_uint4(f2tf(vv.x), f2tf(vv.y), f2tf(vv.z), f2tf(vv.w));
        }
        __syncthreads();                       // converted data visible

        const unsigned* ks = (const unsigned*)kbuf;
        const unsigned* vs = (const unsigned*)vbuf;
        const float* ms = Ms + cur * 64;

        // S = Qs @ K^T
        float s[8][4];
#pragma unroll
        for (int ni = 0; ni < 8; ni++) { s[ni][0] = s[ni][1] = s[ni][2] = s[ni][3] = 0.f; }
#pragma unroll
        for (int kb = 0; kb < 8; kb++) {
#pragma unroll
            for (int ni = 0; ni < 8; ni++) {
                unsigned b0 = ks[(ni * 8 + g) * LDK + kb * 8 + t];
                unsigned b1 = ks[(ni * 8 + g) * LDK + kb * 8 + t + 4];
                mma_tf32(s[ni], qf[kb], b0, b1);
            }
        }

        // mask bias + row max
        float rm0 = -3.4e38f, rm1 = -3.4e38f;
#pragma unroll
        for (int ni = 0; ni < 8; ni++) {
            int c0 = ni * 8 + 2 * t;
            float a0 = ms[c0], a1 = ms[c0 + 1];
            s[ni][0] += a0; s[ni][1] += a1; s[ni][2] += a0; s[ni][3] += a1;
            rm0 = fmaxf(rm0, fmaxf(s[ni][0], s[ni][1]));
            rm1 = fmaxf(rm1, fmaxf(s[ni][2], s[ni][3]));
        }
        rm0 = fmaxf(rm0, __shfl_xor_sync(0xffffffffu, rm0, 1));
        rm0 = fmaxf(rm0, __shfl_xor_sync(0xffffffffu, rm0, 2));
        rm1 = fmaxf(rm1, __shfl_xor_sync(0xffffffffu, rm1, 1));
        rm1 = fmaxf(rm1, __shfl_xor_sync(0xffffffffu, rm1, 2));
        float mn0 = fmaxf(mr0, rm0), mn1 = fmaxf(mr1, rm1);
        float f0 = __expf(mr0 - mn0), f1 = __expf(mr1 - mn1);
        mr0 = mn0; mr1 = mn1;

        // P = exp(S - m), stored to per-warp smem as tf32 bits; row sums
        float rs0 = 0.f, rs1 = 0.f;
#pragma unroll
        for (int ni = 0; ni < 8; ni++) {
            float p00 = __expf(s[ni][0] - mn0), p01 = __expf(s[ni][1] - mn0);
            float p10 = __expf(s[ni][2] - mn1), p11 = __expf(s[ni][3] - mn1);
            rs0 += p00 + p01; rs1 += p10 + p11;
            int c0 = ni * 8 + 2 * t;
            *(uint2*)&pw[g * LDP + c0]       = make_uint2(f2tf(p00), f2tf(p01));
            *(uint2*)&pw[(g + 8) * LDP + c0] = make_uint2(f2tf(p10), f2tf(p11));
        }
        rs0 += __shfl_xor_sync(0xffffffffu, rs0, 1);
        rs0 += __shfl_xor_sync(0xffffffffu, rs0, 2);
        rs1 += __shfl_xor_sync(0xffffffffu, rs1, 1);
        rs1 += __shfl_xor_sync(0xffffffffu, rs1, 2);
        lr0 = lr0 * f0 + rs0; lr1 = lr1 * f1 + rs1;

        // rescale O
#pragma unroll
        for (int ni = 0; ni < 8; ni++) {
            o[ni][0] *= f0; o[ni][1] *= f0; o[ni][2] *= f1; o[ni][3] *= f1;
        }
        __syncwarp();

        // O += P @ V
#pragma unroll
        for (int kb = 0; kb < 8; kb++) {
            unsigned af[4];
            af[0] = pw[g * LDP + kb * 8 + t];
            af[1] = pw[(g + 8) * LDP + kb * 8 + t];
            af[2] = pw[g * LDP + kb * 8 + t + 4];
            af[3] = pw[(g + 8) * LDP + kb * 8 + t + 4];
#pragma unroll
            for (int ni = 0; ni < 8; ni++) {
                unsigned b0 = vs[(kb * 8 + t) * LDV + ni * 8 + g];
                unsigned b1 = vs[(kb * 8 + t + 4) * LDV + ni * 8 + g];
                mma_tf32(o[ni], af, b0, b1);
            }
        }
        // no bottom sync: next iteration's top barrier provides WAR protection
    }

    // normalize + store
    float inv0 = 1.f / lr0, inv1 = 1.f / lr1;
    int r0 = m0 + wid * 16 + g, r1 = r0 + 8;
#pragma unroll
    for (int ni = 0; ni < 8; ni++) {
        int col = h * HD + ni * 8 + 2 * t;
        if (r0 < NSEQ)
            *(float2*)&attout[(long)r0 * CD + col] = make_float2(o[ni][0] * inv0, o[ni][1] * inv0);
        if (r1 < NSEQ)
            *(float2*)&attout[(long)r1 * CD + col] = make_float2(o[ni][2] * inv1, o[ni][3] * inv1);
    }
}

// ---------------- tf32 mma.sync GEMM with fused epilogues ----------------------
enum { EPI_PLAIN = 0, EPI_QKV = 2, EPI_GELU = 4, EPI_RES = 5 };

template<int EPI, bool TB, int BM, int BN>
__global__ void __launch_bounds__(256) mmgemm(
    const float* __restrict__ A, const float* __restrict__ B, float* __restrict__ Cc,
    int M, int N, int K, int lda, int ldb, int ldc,
    const float* __restrict__ bias, const float* __restrict__ bias2,
    const float* __restrict__ res, const float* __restrict__ gamma)
{
    constexpr int BK = 16;
    constexpr int WM = BM / 4;
    constexpr int WN = BN / 2;
    constexpr int MI = WM / 16;
    constexpr int NI = WN / 8;
    constexpr int LDAS = BK + 4;
    constexpr int LDBS = TB ? (BK + 4) : (BN + 8);
    constexpr int BSZ  = TB ? BN * LDBS : BK * LDBS;

    __shared__ float As[2][BM * LDAS];
    __shared__ float Bs[2][BSZ];

    int tid  = threadIdx.x;
    int wid  = tid >> 5;
    int lane = tid & 31;
    int g = lane >> 2, t = lane & 3;
    int wm = (wid & 3) * WM;
    int wn = (wid >> 2) * WN;
    int m0 = blockIdx.x * BM, n0 = blockIdx.y * BN;

    auto ldA = [&](int buf, int k0) {
#pragma unroll
        for (int i = 0; i < BM * 4 / 256; i++) {
            int idx = tid + i * 256;
            int r = idx >> 2, c = (idx & 3) * 4;
            int row = m0 + r; if (row >= M) row = M - 1;
            cp16(&As[buf][r * LDAS + c], &A[(long)row * lda + k0 + c]);
        }
    };
    auto ldB = [&](int buf, int k0) {
        if (TB) {
#pragma unroll
            for (int i = 0; i < BN * 4 / 256; i++) {
                int idx = tid + i * 256;
                int r = idx >> 2, c = (idx & 3) * 4;
                int row = n0 + r; if (row >= N) row = N - 1;
                cp16(&Bs[buf][r * LDBS + c], &B[(long)row * ldb + k0 + c]);
            }
        } else {
            constexpr int CPR = BN / 4;
#pragma unroll
            for (int i = 0; i < BK * BN / 4 / 256; i++) {
                int idx = tid + i * 256;
                int r = idx / CPR, c = (idx % CPR) * 4;
                cp16(&Bs[buf][r * LDBS + c], &B[(long)(k0 + r) * ldb + n0 + c]);
            }
        }
    };

    float acc[MI][NI][4];
#pragma unroll
    for (int mi = 0; mi < MI; mi++)
#pragma unroll
        for (int ni = 0; ni < NI; ni++)
#pragma unroll
            for (int e = 0; e < 4; e++) acc[mi][ni][e] = 0.f;

    int KT = K / BK;
    ldA(0, 0); ldB(0, 0);
    asm volatile("cp.async.commit_group;");

    for (int kt = 0; kt < KT; kt++) {
        int cur = kt & 1;
        asm volatile("cp.async.wait_group 0;");
        __syncthreads();                       // data ready + prev compute done
        if (kt + 1 < KT) {
            ldA(cur ^ 1, (kt + 1) * BK);
            ldB(cur ^ 1, (kt + 1) * BK);
            asm volatile("cp.async.commit_group;");
        }

        const float* as = As[cur];
        const float* bs = Bs[cur];
#pragma unroll
        for (int kk = 0; kk < BK; kk += 8) {
            unsigned af[MI][4], bf[NI][2];
#pragma unroll
            for (int mi = 0; mi < MI; mi++) {
                int r = wm + mi * 16 + g;
                af[mi][0] = f2tf(as[r * LDAS + kk + t]);
                af[mi][1] = f2tf(as[(r + 8) * LDAS + kk + t]);
                af[mi][2] = f2tf(as[r * LDAS + kk + t + 4]);
                af[mi][3] = f2tf(as[(r + 8) * LDAS + kk + t + 4]);
            }
#pragma unroll
            for (int ni = 0; ni < NI; ni++) {
                int n = wn + ni * 8 + g;
                if (TB) {
                    bf[ni][0] = f2tf(bs[n * LDBS + kk + t]);
                    bf[ni][1] = f2tf(bs[n * LDBS + kk + t + 4]);
                } else {
                    bf[ni][0] = f2tf(bs[(kk + t) * LDBS + n]);
                    bf[ni][1] = f2tf(bs[(kk + t + 4) * LDBS + n]);
                }
            }
#pragma unroll
            for (int mi = 0; mi < MI; mi++)
#pragma unroll
                for (int ni = 0; ni < NI; ni++)
                    mma_tf32(acc[mi][ni], af[mi], bf[ni][0], bf[ni][1]);
        }
        // no bottom sync: next top barrier protects buffers
    }

#pragma unroll
    for (int mi = 0; mi < MI; mi++) {
#pragma unroll
        for (int ni = 0; ni < NI; ni++) {
            int col = n0 + wn + ni * 8 + 2 * t;
            if (col >= N) continue;
#pragma unroll
            for (int half = 0; half < 2; half++) {
                int row = m0 + wm + mi * 16 + g + half * 8;
                if (row >= M) continue;
                float v0 = acc[mi][ni][half * 2 + 0];
                float v1 = acc[mi][ni][half * 2 + 1];
                if (EPI == EPI_QKV) {
                    float b0 = (col < CD) ? bias[col]
                             : (col < 2 * CD) ? 0.f : bias2[col - 2 * CD];
                    int c1 = col + 1;
                    float b1 = (c1 < CD) ? bias[c1]
                             : (c1 < 2 * CD) ? 0.f : bias2[c1 - 2 * CD];
                    v0 += b0; v1 += b1;
                } else if (EPI == EPI_GELU) {
                    v0 += bias[col]; v1 += bias[col + 1];
                    v0 = 0.5f * v0 * (1.f + erff(v0 * 0.70710678118654752f));
                    v1 = 0.5f * v1 * (1.f + erff(v1 * 0.70710678118654752f));
                } else if (EPI == EPI_RES) {
                    const float* rr = &res[(long)row * ldc + col];
                    v0 = rr[0] + gamma[col]     * (v0 + bias[col]);
                    v1 = rr[1] + gamma[col + 1] * (v1 + bias[col + 1]);
                }
                float2 ov; ov.x = v0; ov.y = v1;
                *(float2*)&Cc[(long)row * ldc + col] = ov;
            }
        }
    }
}

// ---------------- launch -------------------------------------------------------
extern "C" void kernel_launch(void* const* d_in, const int* in_sizes, int n_in,
                              void* d_out, int out_size)
{
    const float* x      = (const float*)d_in[0];
    const void*  mask   = d_in[1];
    const float* qkv_w  = (const float*)d_in[2];
    const float* q_bias = (const float*)d_in[3];
    const float* v_bias = (const float*)d_in[4];
    const float* proj_w = (const float*)d_in[5];
    const float* proj_b = (const float*)d_in[6];
    const float* n1s    = (const float*)d_in[7];
    const float* n1b    = (const float*)d_in[8];
    const float* n2s    = (const float*)d_in[9];
    const float* n2b    = (const float*)d_in[10];
    const float* w1     = (const float*)d_in[11];
    const float* b1     = (const float*)d_in[12];
    const float* w2     = (const float*)d_in[13];
    const float* b2     = (const float*)d_in[14];
    const float* g1     = (const float*)d_in[15];
    const float* g2     = (const float*)d_in[16];
    float* out = (float*)d_out;

    float *xn, *qkv, *attout, *x2, *h0, *h1, *maskf;
    cudaGetSymbolAddress((void**)&xn,     g_xn);
    cudaGetSymbolAddress((void**)&qkv,    g_qkv);
    cudaGetSymbolAddress((void**)&attout, g_attout);
    cudaGetSymbolAddress((void**)&x2,     g_x2);
    cudaGetSymbolAddress((void**)&h0,     g_h0);
    cudaGetSymbolAddress((void**)&h1,     g_h1);
    cudaGetSymbolAddress((void**)&maskf,  g_maskf);

    static int smem_set = 0;
    if (!smem_set) {
        cudaFuncSetAttribute(flash_kernel,
                             cudaFuncAttributeMaxDynamicSharedMemorySize, FLASH_SMEM);
        smem_set = 1;
    }

    const int GM = (NSEQ + 127) / 128;   // 25

    // 1. LN1 + mask prep
    ln_kernel<<<NSEQ, 256>>>(x, n1s, n1b, xn);
    mask_detect_kernel<<<1, 256>>>((const unsigned int*)mask);
    mask_prep_kernel<<<(NSEQ + 255) / 256, 256>>>(mask, maskf);

    // 2. QKV projection
    mmgemm<EPI_QKV, true, 128, 128><<<dim3(GM, C3 / 128, 1), 256>>>(
        xn, qkv_w, qkv, NSEQ, C3, CD, CD, CD, C3,
        q_bias, v_bias, nullptr, nullptr);

    // 3-5. flash attention (QK^T + mask + softmax + PV fused)
    flash_kernel<<<dim3(GM, NH), 256, FLASH_SMEM>>>(qkv, maskf, attout);

    // 6. proj + residual
    mmgemm<EPI_RES, true, 128, 128><<<dim3(GM, CD / 128, 1), 256>>>(
        attout, proj_w, x2, NSEQ, CD, CD, CD, CD, CD,
        proj_b, nullptr, x, g1);

    // 7. LN2
    ln_kernel<<<NSEQ, 256>>>(x2, n2s, n2b, h0);

    // 8. MLP1 + exact GELU
    mmgemm<EPI_GELU, true, 128, 128><<<dim3(GM, HID / 128, 1), 256>>>(
        h0, w1, h1, NSEQ, HID, CD, CD, CD, HID,
        b1, nullptr, nullptr, nullptr);

    // 9. MLP2 + final residual
    mmgemm<EPI_RES, true, 128, 128><<<dim3(GM, CD / 128, 1), 256>>>(
        h1, w2, out, NSEQ, CD, HID, HID, HID, CD,
        b2, nullptr, x2, g2);
}

// round 6
// speedup vs baseline: 2.5703x; 1.0758x over previous
#include <cuda_runtime.h>
#include <math.h>

#define NSEQ 3136
#define CD   768
#define NH   12
#define HD   64
#define HID  3072
#define C3   2304

// rounded-weight scratch offsets
#define WQKV_OFF 0
#define WPROJ_OFF 1769472               // 2304*768
#define W1_OFF   (WPROJ_OFF + 589824)   // +768*768
#define W2_OFF   (W1_OFF + 2359296)     // +3072*768
#define W_TOTAL  (W2_OFF + 2359296)

// ---------------- scratch (static device globals; no allocation) -------------
__device__ float g_xn[NSEQ * CD];
__device__ float g_qkv[NSEQ * C3];
__device__ float g_attout[NSEQ * CD];
__device__ float g_x2[NSEQ * CD];
__device__ float g_h0[NSEQ * CD];
__device__ float g_h1[NSEQ * HID];
__device__ float g_maskf[NSEQ];
__device__ float g_w[W_TOTAL];
__device__ int   g_maskByte;

// ---------------- helpers ----------------------------------------------------
__device__ __forceinline__ float warpSum(float v) {
#pragma unroll
    for (int o = 16; o; o >>= 1) v += __shfl_xor_sync(0xffffffffu, v, o);
    return v;
}

__device__ __forceinline__ unsigned f2tf(float x) {
    unsigned r;
    asm("cvt.rna.tf32.f32 %0, %1;" : "=r"(r) : "f"(x));
    return r;
}
__device__ __forceinline__ float tfround(float x) {          // round to tf32, keep as float
    return __uint_as_float(f2tf(x));
}
__device__ __forceinline__ void cp16(void* s, const void* g) {
    unsigned a = (unsigned)__cvta_generic_to_shared(s);
    asm volatile("cp.async.ca.shared.global [%0], [%1], 16;" :: "r"(a), "l"(g));
}
__device__ __forceinline__ void mma_tf32(float* c, const unsigned* a, unsigned b0, unsigned b1) {
    asm volatile(
        "mma.sync.aligned.m16n8k8.row.col.f32.tf32.tf32.f32 "
        "{%0,%1,%2,%3}, {%4,%5,%6,%7}, {%8,%9}, {%0,%1,%2,%3};"
        : "+f"(c[0]), "+f"(c[1]), "+f"(c[2]), "+f"(c[3])
        : "r"(a[0]), "r"(a[1]), "r"(a[2]), "r"(a[3]), "r"(b0), "r"(b1));
}

// ---------------- weight pre-rounding -----------------------------------------
__global__ void __launch_bounds__(256) round_copy_kernel(
    const float* __restrict__ in, float* __restrict__ out, int n4)
{
    int i = blockIdx.x * 256 + threadIdx.x;
    if (i < n4) {
        float4 v = ((const float4*)in)[i];
        v.x = tfround(v.x); v.y = tfround(v.y);
        v.z = tfround(v.z); v.w = tfround(v.w);
        ((float4*)out)[i] = v;
    }
}

// ---------------- mask prep ---------------------------------------------------
__global__ void mask_detect_kernel(const unsigned int* __restrict__ m) {
    __shared__ int flag;
    if (threadIdx.x == 0) flag = 0;
    __syncthreads();
    for (int i = threadIdx.x; i < NSEQ / 4; i += 256)
        if (m[i] > 1u) flag = 1;
    __syncthreads();
    if (threadIdx.x == 0) g_maskByte = flag;
}

__global__ void mask_prep_kernel(const void* __restrict__ mask, float* __restrict__ mf) {
    int i = blockIdx.x * 256 + threadIdx.x;
    if (i < NSEQ) {
        bool m = g_maskByte ? (((const unsigned char*)mask)[i] != 0)
                            : (((const int*)mask)[i] != 0);
        mf[i] = m ? -1e30f : 0.f;
    }
}

// ---------------- layernorm (tf32-rounded output) ------------------------------
__global__ void __launch_bounds__(256) ln_kernel(
    const float* __restrict__ x, const float* __restrict__ sc,
    const float* __restrict__ bi, float* __restrict__ y)
{
    int row = blockIdx.x;
    const float* xr = x + (long)row * CD;
    float* yr = y + (long)row * CD;
    int t = threadIdx.x;
    float v[3];
    float s = 0.f, s2 = 0.f;
#pragma unroll
    for (int i = 0; i < 3; i++) {
        float a = xr[t + i * 256];
        v[i] = a; s += a; s2 += a * a;
    }
    __shared__ float sh[32], sh2[32];
    float ws = warpSum(s), ws2 = warpSum(s2);
    int lane = t & 31, wid = t >> 5;
    if (lane == 0) { sh[wid] = ws; sh2[wid] = ws2; }
    __syncthreads();
    if (wid == 0) {
        float a = lane < 8 ? sh[lane] : 0.f;
        float b = lane < 8 ? sh2[lane] : 0.f;
        a = warpSum(a); b = warpSum(b);
        if (lane == 0) { sh[0] = a; sh2[0] = b; }
    }
    __syncthreads();
    float mu  = sh[0] * (1.f / CD);
    float var = sh2[0] * (1.f / CD) - mu * mu;
    float inv = rsqrtf(var + 1e-5f);
#pragma unroll
    for (int i = 0; i < 3; i++) {
        int c = t + i * 256;
        yr[c] = tfround((v[i] - mu) * inv * sc[c] + bi[c]);
    }
}

// ---------------- flash attention ---------------------------------------------
// One block = one (q-tile of 128, head). 8 warps, warp owns 16 query rows.
// K/V double-buffered via cp.async; inputs pre-rounded to tf32 → no convert
// pass, operands fed as raw u32. Online softmax. 2 blocks/SM.
#define LDK 68
#define LDV 72
#define LDP 68
#define FLASH_SMEM ((2*64*LDK + 2*64*LDV + 8*16*LDP + 2*64) * 4)

__global__ void __launch_bounds__(256, 2) flash_kernel(
    const float* __restrict__ qkv, const float* __restrict__ maskf,
    float* __restrict__ attout)
{
    extern __shared__ float sm[];
    float* Ks = sm;                       // 2 * 64*LDK
    float* Vs = Ks + 2 * 64 * LDK;        // 2 * 64*LDV
    float* Ps = Vs + 2 * 64 * LDV;        // 8 * 16*LDP  (tf32 bits)
    float* Ms = Ps + 8 * 16 * LDP;        // 2 * 64

    int h  = blockIdx.y;
    int m0 = blockIdx.x * 128;
    int tid = threadIdx.x, wid = tid >> 5, lane = tid & 31;
    int g = lane >> 2, t = lane & 3;

    const float* Qp = qkv + h * HD;
    const float* Kp = qkv + CD + h * HD;
    const float* Vp = qkv + 2 * CD + h * HD;

    // Q fragments: inputs pre-rounded to tf32; *0.125f is exact (power of 2)
    unsigned qf[8][4];
    {
        int r0 = m0 + wid * 16 + g; if (r0 >= NSEQ) r0 = NSEQ - 1;
        int r1 = r0 + 8;            if (r1 >= NSEQ) r1 = NSEQ - 1;
        const float* q0 = Qp + (long)r0 * C3;
        const float* q1 = Qp + (long)r1 * C3;
#pragma unroll
        for (int kb = 0; kb < 8; kb++) {
            qf[kb][0] = __float_as_uint(q0[kb * 8 + t]     * 0.125f);
            qf[kb][1] = __float_as_uint(q1[kb * 8 + t]     * 0.125f);
            qf[kb][2] = __float_as_uint(q0[kb * 8 + t + 4] * 0.125f);
            qf[kb][3] = __float_as_uint(q1[kb * 8 + t + 4] * 0.125f);
        }
    }

    float o[8][4];
#pragma unroll
    for (int ni = 0; ni < 8; ni++)
#pragma unroll
        for (int e = 0; e < 4; e++) o[ni][e] = 0.f;
    float mr0 = -3.4e38f, mr1 = -3.4e38f, lr0 = 0.f, lr1 = 0.f;

    auto loadKV = [&](int buf, int j0) {
#pragma unroll
        for (int i = 0; i < 4; i++) {
            int idx = tid + i * 256;           // 0..1023
            int r = idx >> 4, c = (idx & 15) * 4;
            cp16(&Ks[buf * 64 * LDK + r * LDK + c], &Kp[(long)(j0 + r) * C3 + c]);
            cp16(&Vs[buf * 64 * LDV + r * LDV + c], &Vp[(long)(j0 + r) * C3 + c]);
        }
        if (tid < 16) cp16(&Ms[buf * 64 + tid * 4], &maskf[j0 + tid * 4]);
    };

    loadKV(0, 0);
    asm volatile("cp.async.commit_group;");

    const int NJ = NSEQ / 64;   // 49
    unsigned* pw = (unsigned*)(Ps + wid * 16 * LDP);

    for (int j = 0; j < NJ; j++) {
        int cur = j & 1;
        asm volatile("cp.async.wait_group 0;");
        __syncthreads();                       // data ready + prev compute done
        if (j + 1 < NJ) {
            loadKV(cur ^ 1, (j + 1) * 64);     // overlaps compute
            asm volatile("cp.async.commit_group;");
        }

        const unsigned* ks = (const unsigned*)(Ks + cur * 64 * LDK);
        const unsigned* vs = (const unsigned*)(Vs + cur * 64 * LDV);
        const float* ms = Ms + cur * 64;

        // S = Qs @ K^T
        float s[8][4];
#pragma unroll
        for (int ni = 0; ni < 8; ni++) { s[ni][0] = s[ni][1] = s[ni][2] = s[ni][3] = 0.f; }
#pragma unroll
        for (int kb = 0; kb < 8; kb++) {
#pragma unroll
            for (int ni = 0; ni < 8; ni++) {
                unsigned b0 = ks[(ni * 8 + g) * LDK + kb * 8 + t];
                unsigned b1 = ks[(ni * 8 + g) * LDK + kb * 8 + t + 4];
                mma_tf32(s[ni], qf[kb], b0, b1);
            }
        }

        // mask bias + row max
        float rm0 = -3.4e38f, rm1 = -3.4e38f;
#pragma unroll
        for (int ni = 0; ni < 8; ni++) {
            int c0 = ni * 8 + 2 * t;
            float a0 = ms[c0], a1 = ms[c0 + 1];
            s[ni][0] += a0; s[ni][1] += a1; s[ni][2] += a0; s[ni][3] += a1;
            rm0 = fmaxf(rm0, fmaxf(s[ni][0], s[ni][1]));
            rm1 = fmaxf(rm1, fmaxf(s[ni][2], s[ni][3]));
        }
        rm0 = fmaxf(rm0, __shfl_xor_sync(0xffffffffu, rm0, 1));
        rm0 = fmaxf(rm0, __shfl_xor_sync(0xffffffffu, rm0, 2));
        rm1 = fmaxf(rm1, __shfl_xor_sync(0xffffffffu, rm1, 1));
        rm1 = fmaxf(rm1, __shfl_xor_sync(0xffffffffu, rm1, 2));
        float mn0 = fmaxf(mr0, rm0), mn1 = fmaxf(mr1, rm1);
        float f0 = __expf(mr0 - mn0), f1 = __expf(mr1 - mn1);
        mr0 = mn0; mr1 = mn1;

        // P = exp(S - m), stored to per-warp smem as tf32 bits; row sums
        float rs0 = 0.f, rs1 = 0.f;
#pragma unroll
        for (int ni = 0; ni < 8; ni++) {
            float p00 = __expf(s[ni][0] - mn0), p01 = __expf(s[ni][1] - mn0);
            float p10 = __expf(s[ni][2] - mn1), p11 = __expf(s[ni][3] - mn1);
            rs0 += p00 + p01; rs1 += p10 + p11;
            int c0 = ni * 8 + 2 * t;
            *(uint2*)&pw[g * LDP + c0]       = make_uint2(f2tf(p00), f2tf(p01));
            *(uint2*)&pw[(g + 8) * LDP + c0] = make_uint2(f2tf(p10), f2tf(p11));
        }
        rs0 += __shfl_xor_sync(0xffffffffu, rs0, 1);
        rs0 += __shfl_xor_sync(0xffffffffu, rs0, 2);
        rs1 += __shfl_xor_sync(0xffffffffu, rs1, 1);
        rs1 += __shfl_xor_sync(0xffffffffu, rs1, 2);
        lr0 = lr0 * f0 + rs0; lr1 = lr1 * f1 + rs1;

        // rescale O
#pragma unroll
        for (int ni = 0; ni < 8; ni++) {
            o[ni][0] *= f0; o[ni][1] *= f0; o[ni][2] *= f1; o[ni][3] *= f1;
        }
        __syncwarp();

        // O += P @ V
#pragma unroll
        for (int kb = 0; kb < 8; kb++) {
            unsigned af[4];
            af[0] = pw[g * LDP + kb * 8 + t];
            af[1] = pw[(g + 8) * LDP + kb * 8 + t];
            af[2] = pw[g * LDP + kb * 8 + t + 4];
            af[3] = pw[(g + 8) * LDP + kb * 8 + t + 4];
#pragma unroll
            for (int ni = 0; ni < 8; ni++) {
                unsigned b0 = vs[(kb * 8 + t) * LDV + ni * 8 + g];
                unsigned b1 = vs[(kb * 8 + t + 4) * LDV + ni * 8 + g];
                mma_tf32(o[ni], af, b0, b1);
            }
        }
        // no bottom sync: next iteration's top barrier provides WAR protection
    }

    // normalize + store (pre-rounded: attout is a GEMM input only)
    float inv0 = 1.f / lr0, inv1 = 1.f / lr1;
    int r0 = m0 + wid * 16 + g, r1 = r0 + 8;
#pragma unroll
    for (int ni = 0; ni < 8; ni++) {
        int col = h * HD + ni * 8 + 2 * t;
        if (r0 < NSEQ)
            *(float2*)&attout[(long)r0 * CD + col] =
                make_float2(tfround(o[ni][0] * inv0), tfround(o[ni][1] * inv0));
        if (r1 < NSEQ)
            *(float2*)&attout[(long)r1 * CD + col] =
                make_float2(tfround(o[ni][2] * inv1), tfround(o[ni][3] * inv1));
    }
}

// ---------------- tf32 mma.sync GEMM with fused epilogues ----------------------
// All inputs (A and B) are pre-rounded to tf32 → operands fed as raw u32.
enum { EPI_QKV = 2, EPI_GELU = 4, EPI_RES = 5 };

template<int EPI, int BM, int BN>
__global__ void __launch_bounds__(256) mmgemm(
    const float* __restrict__ A, const float* __restrict__ B, float* __restrict__ Cc,
    int M, int N, int K, int lda, int ldb, int ldc,
    const float* __restrict__ bias, const float* __restrict__ bias2,
    const float* __restrict__ res, const float* __restrict__ gamma)
{
    constexpr int BK = 16;
    constexpr int WM = BM / 4;
    constexpr int WN = BN / 2;
    constexpr int MI = WM / 16;
    constexpr int NI = WN / 8;
    constexpr int LDS_ = BK + 4;

    __shared__ float As[2][BM * LDS_];
    __shared__ float Bs[2][BN * LDS_];

    int tid  = threadIdx.x;
    int wid  = tid >> 5;
    int lane = tid & 31;
    int g = lane >> 2, t = lane & 3;
    int wm = (wid & 3) * WM;
    int wn = (wid >> 2) * WN;
    int m0 = blockIdx.x * BM, n0 = blockIdx.y * BN;

    auto ldA = [&](int buf, int k0) {
#pragma unroll
        for (int i = 0; i < BM * 4 / 256; i++) {
            int idx = tid + i * 256;
            int r = idx >> 2, c = (idx & 3) * 4;
            int row = m0 + r; if (row >= M) row = M - 1;
            cp16(&As[buf][r * LDS_ + c], &A[(long)row * lda + k0 + c]);
        }
    };
    auto ldB = [&](int buf, int k0) {
#pragma unroll
        for (int i = 0; i < BN * 4 / 256; i++) {
            int idx = tid + i * 256;
            int r = idx >> 2, c = (idx & 3) * 4;
            int row = n0 + r; if (row >= N) row = N - 1;
            cp16(&Bs[buf][r * LDS_ + c], &B[(long)row * ldb + k0 + c]);
        }
    };

    float acc[MI][NI][4];
#pragma unroll
    for (int mi = 0; mi < MI; mi++)
#pragma unroll
        for (int ni = 0; ni < NI; ni++)
#pragma unroll
            for (int e = 0; e < 4; e++) acc[mi][ni][e] = 0.f;

    int KT = K / BK;
    ldA(0, 0); ldB(0, 0);
    asm volatile("cp.async.commit_group;");

    for (int kt = 0; kt < KT; kt++) {
        int cur = kt & 1;
        asm volatile("cp.async.wait_group 0;");
        __syncthreads();                       // data ready + prev compute done
        if (kt + 1 < KT) {
            ldA(cur ^ 1, (kt + 1) * BK);
            ldB(cur ^ 1, (kt + 1) * BK);
            asm volatile("cp.async.commit_group;");
        }

        const unsigned* as = (const unsigned*)As[cur];
        const unsigned* bs = (const unsigned*)Bs[cur];
#pragma unroll
        for (int kk = 0; kk < BK; kk += 8) {
            unsigned af[MI][4], bf[NI][2];
#pragma unroll
            for (int mi = 0; mi < MI; mi++) {
                int r = wm + mi * 16 + g;
                af[mi][0] = as[r * LDS_ + kk + t];
                af[mi][1] = as[(r + 8) * LDS_ + kk + t];
                af[mi][2] = as[r * LDS_ + kk + t + 4];
                af[mi][3] = as[(r + 8) * LDS_ + kk + t + 4];
            }
#pragma unroll
            for (int ni = 0; ni < NI; ni++) {
                int n = wn + ni * 8 + g;
                bf[ni][0] = bs[n * LDS_ + kk + t];
                bf[ni][1] = bs[n * LDS_ + kk + t + 4];
            }
#pragma unroll
            for (int mi = 0; mi < MI; mi++)
#pragma unroll
                for (int ni = 0; ni < NI; ni++)
                    mma_tf32(acc[mi][ni], af[mi], bf[ni][0], bf[ni][1]);
        }
        // no bottom sync: next top barrier protects buffers
    }

#pragma unroll
    for (int mi = 0; mi < MI; mi++) {
#pragma unroll
        for (int ni = 0; ni < NI; ni++) {
            int col = n0 + wn + ni * 8 + 2 * t;
            if (col >= N) continue;
#pragma unroll
            for (int half = 0; half < 2; half++) {
                int row = m0 + wm + mi * 16 + g + half * 8;
                if (row >= M) continue;
                float v0 = acc[mi][ni][half * 2 + 0];
                float v1 = acc[mi][ni][half * 2 + 1];
                if (EPI == EPI_QKV) {
                    float b0 = (col < CD) ? bias[col]
                             : (col < 2 * CD) ? 0.f : bias2[col - 2 * CD];
                    int c1 = col + 1;
                    float b1 = (c1 < CD) ? bias[c1]
                             : (c1 < 2 * CD) ? 0.f : bias2[c1 - 2 * CD];
                    v0 = tfround(v0 + b0); v1 = tfround(v1 + b1);
                } else if (EPI == EPI_GELU) {
                    v0 += bias[col]; v1 += bias[col + 1];
                    v0 = tfround(0.5f * v0 * (1.f + erff(v0 * 0.70710678118654752f)));
                    v1 = tfround(0.5f * v1 * (1.f + erff(v1 * 0.70710678118654752f)));
                } else if (EPI == EPI_RES) {
                    const float* rr = &res[(long)row * ldc + col];
                    v0 = rr[0] + gamma[col]     * (v0 + bias[col]);
                    v1 = rr[1] + gamma[col + 1] * (v1 + bias[col + 1]);
                }
                float2 ov; ov.x = v0; ov.y = v1;
                *(float2*)&Cc[(long)row * ldc + col] = ov;
            }
        }
    }
}

// ---------------- launch -------------------------------------------------------
extern "C" void kernel_launch(void* const* d_in, const int* in_sizes, int n_in,
                              void* d_out, int out_size)
{
    const float* x      = (const float*)d_in[0];
    const void*  mask   = d_in[1];
    const float* qkv_w  = (const float*)d_in[2];
    const float* q_bias = (const float*)d_in[3];
    const float* v_bias = (const float*)d_in[4];
    const float* proj_w = (const float*)d_in[5];
    const float* proj_b = (const float*)d_in[6];
    const float* n1s    = (const float*)d_in[7];
    const float* n1b    = (const float*)d_in[8];
    const float* n2s    = (const float*)d_in[9];
    const float* n2b    = (const float*)d_in[10];
    const float* w1     = (const float*)d_in[11];
    const float* b1     = (const float*)d_in[12];
    const float* w2     = (const float*)d_in[13];
    const float* b2     = (const float*)d_in[14];
    const float* g1     = (const float*)d_in[15];
    const float* g2     = (const float*)d_in[16];
    float* out = (float*)d_out;

    float *xn, *qkv, *attout, *x2, *h0, *h1, *maskf, *w;
    cudaGetSymbolAddress((void**)&xn,     g_xn);
    cudaGetSymbolAddress((void**)&qkv,    g_qkv);
    cudaGetSymbolAddress((void**)&attout, g_attout);
    cudaGetSymbolAddress((void**)&x2,     g_x2);
    cudaGetSymbolAddress((void**)&h0,     g_h0);
    cudaGetSymbolAddress((void**)&h1,     g_h1);
    cudaGetSymbolAddress((void**)&maskf,  g_maskf);
    cudaGetSymbolAddress((void**)&w,      g_w);

    static int smem_set = 0;
    if (!smem_set) {
        cudaFuncSetAttribute(flash_kernel,
                             cudaFuncAttributeMaxDynamicSharedMemorySize, FLASH_SMEM);
        smem_set = 1;
    }

    const int GM = (NSEQ + 127) / 128;   // 25

    // 0. pre-round weights to tf32 (scratch)
    round_copy_kernel<<<(C3 * CD / 4 + 255) / 256, 256>>>(qkv_w, w + WQKV_OFF, C3 * CD / 4);
    round_copy_kernel<<<(CD * CD / 4 + 255) / 256, 256>>>(proj_w, w + WPROJ_OFF, CD * CD / 4);
    round_copy_kernel<<<(HID * CD / 4 + 255) / 256, 256>>>(w1, w + W1_OFF, HID * CD / 4);
    round_copy_kernel<<<(CD * HID / 4 + 255) / 256, 256>>>(w2, w + W2_OFF, CD * HID / 4);

    // 1. LN1 + mask prep
    ln_kernel<<<NSEQ, 256>>>(x, n1s, n1b, xn);
    mask_detect_kernel<<<1, 256>>>((const unsigned int*)mask);
    mask_prep_kernel<<<(NSEQ + 255) / 256, 256>>>(mask, maskf);

    // 2. QKV projection
    mmgemm<EPI_QKV, 128, 128><<<dim3(GM, C3 / 128, 1), 256>>>(
        xn, w + WQKV_OFF, qkv, NSEQ, C3, CD, CD, CD, C3,
        q_bias, v_bias, nullptr, nullptr);

    // 3-5. flash attention (QK^T + mask + softmax + PV fused)
    flash_kernel<<<dim3(GM, NH), 256, FLASH_SMEM>>>(qkv, maskf, attout);

    // 6. proj + residual
    mmgemm<EPI_RES, 128, 128><<<dim3(GM, CD / 128, 1), 256>>>(
        attout, w + WPROJ_OFF, x2, NSEQ, CD, CD, CD, CD, CD,
        proj_b, nullptr, x, g1);

    // 7. LN2
    ln_kernel<<<NSEQ, 256>>>(x2, n2s, n2b, h0);

    // 8. MLP1 + exact GELU
    mmgemm<EPI_GELU, 128, 128><<<dim3(GM, HID / 128, 1), 256>>>(
        h0, w + W1_OFF, h1, NSEQ, HID, CD, CD, CD, HID,
        b1, nullptr, nullptr, nullptr);

    // 9. MLP2 + final residual
    mmgemm<EPI_RES, 128, 128><<<dim3(GM, CD / 128, 1), 256>>>(
        h1, w + W2_OFF, out, NSEQ, CD, HID, HID, HID, CD,
        b2, nullptr, x2, g2);
}

// round 7
// speedup vs baseline: 2.6909x; 1.0469x over previous
#include <cuda_runtime.h>
#include <math.h>

#define NSEQ 3136
#define CD   768
#define NH   12
#define HD   64
#define HID  3072
#define C3   2304

// rounded-weight scratch offsets
#define WQKV_OFF 0
#define WPROJ_OFF 1769472               // 2304*768
#define W1_OFF   (WPROJ_OFF + 589824)   // +768*768
#define W2_OFF   (W1_OFF + 2359296)     // +3072*768
#define W_TOTAL  (W2_OFF + 2359296)

// ---------------- scratch (static device globals; no allocation) -------------
__device__ float g_xn[NSEQ * CD];
__device__ float g_qkv[NSEQ * C3];
__device__ float g_attout[NSEQ * CD];
__device__ float g_x2[NSEQ * CD];
__device__ float g_h0[NSEQ * CD];
__device__ float g_h1[NSEQ * HID];
__device__ float g_maskf[NSEQ];
__device__ float g_w[W_TOTAL];
__device__ int   g_maskByte;

// ---------------- helpers ----------------------------------------------------
__device__ __forceinline__ float warpSum(float v) {
#pragma unroll
    for (int o = 16; o; o >>= 1) v += __shfl_xor_sync(0xffffffffu, v, o);
    return v;
}

__device__ __forceinline__ unsigned f2tf(float x) {
    unsigned r;
    asm("cvt.rna.tf32.f32 %0, %1;" : "=r"(r) : "f"(x));
    return r;
}
__device__ __forceinline__ float tfround(float x) {
    return __uint_as_float(f2tf(x));
}
__device__ __forceinline__ void cp16(void* s, const void* g) {
    unsigned a = (unsigned)__cvta_generic_to_shared(s);
    asm volatile("cp.async.ca.shared.global [%0], [%1], 16;" :: "r"(a), "l"(g));
}
__device__ __forceinline__ void mma_tf32(float* c, const unsigned* a, unsigned b0, unsigned b1) {
    asm volatile(
        "mma.sync.aligned.m16n8k8.row.col.f32.tf32.tf32.f32 "
        "{%0,%1,%2,%3}, {%4,%5,%6,%7}, {%8,%9}, {%0,%1,%2,%3};"
        : "+f"(c[0]), "+f"(c[1]), "+f"(c[2]), "+f"(c[3])
        : "r"(a[0]), "r"(a[1]), "r"(a[2]), "r"(a[3]), "r"(b0), "r"(b1));
}

// ---------------- weight pre-rounding -----------------------------------------
__global__ void __launch_bounds__(256) round_copy_kernel(
    const float* __restrict__ in, float* __restrict__ out, int n4)
{
    int i = blockIdx.x * 256 + threadIdx.x;
    if (i < n4) {
        float4 v = ((const float4*)in)[i];
        v.x = tfround(v.x); v.y = tfround(v.y);
        v.z = tfround(v.z); v.w = tfround(v.w);
        ((float4*)out)[i] = v;
    }
}

// ---------------- mask prep ---------------------------------------------------
__global__ void mask_detect_kernel(const unsigned int* __restrict__ m) {
    __shared__ int flag;
    if (threadIdx.x == 0) flag = 0;
    __syncthreads();
    for (int i = threadIdx.x; i < NSEQ / 4; i += 256)
        if (m[i] > 1u) flag = 1;
    __syncthreads();
    if (threadIdx.x == 0) g_maskByte = flag;
}

__global__ void mask_prep_kernel(const void* __restrict__ mask, float* __restrict__ mf) {
    int i = blockIdx.x * 256 + threadIdx.x;
    if (i < NSEQ) {
        bool m = g_maskByte ? (((const unsigned char*)mask)[i] != 0)
                            : (((const int*)mask)[i] != 0);
        mf[i] = m ? -1e30f : 0.f;
    }
}

// ---------------- layernorm (tf32-rounded output) ------------------------------
__global__ void __launch_bounds__(256) ln_kernel(
    const float* __restrict__ x, const float* __restrict__ sc,
    const float* __restrict__ bi, float* __restrict__ y)
{
    int row = blockIdx.x;
    const float* xr = x + (long)row * CD;
    float* yr = y + (long)row * CD;
    int t = threadIdx.x;
    float v[3];
    float s = 0.f, s2 = 0.f;
#pragma unroll
    for (int i = 0; i < 3; i++) {
        float a = xr[t + i * 256];
        v[i] = a; s += a; s2 += a * a;
    }
    __shared__ float sh[32], sh2[32];
    float ws = warpSum(s), ws2 = warpSum(s2);
    int lane = t & 31, wid = t >> 5;
    if (lane == 0) { sh[wid] = ws; sh2[wid] = ws2; }
    __syncthreads();
    if (wid == 0) {
        float a = lane < 8 ? sh[lane] : 0.f;
        float b = lane < 8 ? sh2[lane] : 0.f;
        a = warpSum(a); b = warpSum(b);
        if (lane == 0) { sh[0] = a; sh2[0] = b; }
    }
    __syncthreads();
    float mu  = sh[0] * (1.f / CD);
    float var = sh2[0] * (1.f / CD) - mu * mu;
    float inv = rsqrtf(var + 1e-5f);
#pragma unroll
    for (int i = 0; i < 3; i++) {
        int c = t + i * 256;
        yr[c] = tfround((v[i] - mu) * inv * sc[c] + bi[c]);
    }
}

// ---------------- flash attention ---------------------------------------------
// One block = one (q-tile of 128, head). 4 warps, warp owns 32 query rows
// (MI=2): K/V fragments amortized over 2 row-fragments -> 1.25 LDS/MMA.
// K/V double-buffered cp.async, pre-rounded tf32 inputs. 2 blocks/SM.
#define LDK 68
#define LDV 72
#define LDP 68
#define FLASH_SMEM ((2*64*LDK + 2*64*LDV + 4*32*LDP + 2*64) * 4)

__global__ void __launch_bounds__(128, 2) flash_kernel(
    const float* __restrict__ qkv, const float* __restrict__ maskf,
    float* __restrict__ attout)
{
    extern __shared__ float sm[];
    float* Ks = sm;                       // 2 * 64*LDK
    float* Vs = Ks + 2 * 64 * LDK;        // 2 * 64*LDV
    float* Ps = Vs + 2 * 64 * LDV;        // 4 * 32*LDP  (tf32 bits)
    float* Ms = Ps + 4 * 32 * LDP;        // 2 * 64

    int h  = blockIdx.y;
    int m0 = blockIdx.x * 128;
    int tid = threadIdx.x, wid = tid >> 5, lane = tid & 31;
    int g = lane >> 2, t = lane & 3;

    const float* Qp = qkv + h * HD;
    const float* Kp = qkv + CD + h * HD;
    const float* Vp = qkv + 2 * CD + h * HD;

    // Q fragments (pre-rounded tf32; *0.125f exact)
    unsigned qf[8][2][4];
#pragma unroll
    for (int mi = 0; mi < 2; mi++) {
        int r0 = m0 + wid * 32 + mi * 16 + g; if (r0 >= NSEQ) r0 = NSEQ - 1;
        int r1 = r0 + 8;                      if (r1 >= NSEQ) r1 = NSEQ - 1;
        const float* q0 = Qp + (long)r0 * C3;
        const float* q1 = Qp + (long)r1 * C3;
#pragma unroll
        for (int kb = 0; kb < 8; kb++) {
            qf[kb][mi][0] = __float_as_uint(q0[kb * 8 + t]     * 0.125f);
            qf[kb][mi][1] = __float_as_uint(q1[kb * 8 + t]     * 0.125f);
            qf[kb][mi][2] = __float_as_uint(q0[kb * 8 + t + 4] * 0.125f);
            qf[kb][mi][3] = __float_as_uint(q1[kb * 8 + t + 4] * 0.125f);
        }
    }

    float o[2][8][4];
#pragma unroll
    for (int mi = 0; mi < 2; mi++)
#pragma unroll
        for (int ni = 0; ni < 8; ni++)
#pragma unroll
            for (int e = 0; e < 4; e++) o[mi][ni][e] = 0.f;
    float mr[2][2], lr[2][2];
#pragma unroll
    for (int mi = 0; mi < 2; mi++) {
        mr[mi][0] = mr[mi][1] = -3.4e38f;
        lr[mi][0] = lr[mi][1] = 0.f;
    }

    auto loadKV = [&](int buf, int j0) {
#pragma unroll
        for (int i = 0; i < 8; i++) {
            int idx = tid + i * 128;           // 0..1023
            int r = idx >> 4, c = (idx & 15) * 4;
            cp16(&Ks[buf * 64 * LDK + r * LDK + c], &Kp[(long)(j0 + r) * C3 + c]);
            cp16(&Vs[buf * 64 * LDV + r * LDV + c], &Vp[(long)(j0 + r) * C3 + c]);
        }
        if (tid < 16) cp16(&Ms[buf * 64 + tid * 4], &maskf[j0 + tid * 4]);
    };

    loadKV(0, 0);
    asm volatile("cp.async.commit_group;");

    const int NJ = NSEQ / 64;   // 49
    unsigned* pw = (unsigned*)(Ps + wid * 32 * LDP);

    for (int j = 0; j < NJ; j++) {
        int cur = j & 1;
        asm volatile("cp.async.wait_group 0;");
        __syncthreads();
        if (j + 1 < NJ) {
            loadKV(cur ^ 1, (j + 1) * 64);
            asm volatile("cp.async.commit_group;");
        }

        const unsigned* ks = (const unsigned*)(Ks + cur * 64 * LDK);
        const unsigned* vs = (const unsigned*)(Vs + cur * 64 * LDV);
        const float* ms = Ms + cur * 64;

        // S = Qs @ K^T   (b-fragments shared across both row fragments)
        float s[2][8][4];
#pragma unroll
        for (int mi = 0; mi < 2; mi++)
#pragma unroll
            for (int ni = 0; ni < 8; ni++)
                s[mi][ni][0] = s[mi][ni][1] = s[mi][ni][2] = s[mi][ni][3] = 0.f;
#pragma unroll
        for (int kb = 0; kb < 8; kb++) {
#pragma unroll
            for (int ni = 0; ni < 8; ni++) {
                unsigned b0 = ks[(ni * 8 + g) * LDK + kb * 8 + t];
                unsigned b1 = ks[(ni * 8 + g) * LDK + kb * 8 + t + 4];
                mma_tf32(s[0][ni], qf[kb][0], b0, b1);
                mma_tf32(s[1][ni], qf[kb][1], b0, b1);
            }
        }

        // mask bias + online softmax per row fragment
        float fsc[2][2];
#pragma unroll
        for (int mi = 0; mi < 2; mi++) {
            float rm0 = -3.4e38f, rm1 = -3.4e38f;
#pragma unroll
            for (int ni = 0; ni < 8; ni++) {
                int c0 = ni * 8 + 2 * t;
                float a0 = ms[c0], a1 = ms[c0 + 1];
                s[mi][ni][0] += a0; s[mi][ni][1] += a1;
                s[mi][ni][2] += a0; s[mi][ni][3] += a1;
                rm0 = fmaxf(rm0, fmaxf(s[mi][ni][0], s[mi][ni][1]));
                rm1 = fmaxf(rm1, fmaxf(s[mi][ni][2], s[mi][ni][3]));
            }
            rm0 = fmaxf(rm0, __shfl_xor_sync(0xffffffffu, rm0, 1));
            rm0 = fmaxf(rm0, __shfl_xor_sync(0xffffffffu, rm0, 2));
            rm1 = fmaxf(rm1, __shfl_xor_sync(0xffffffffu, rm1, 1));
            rm1 = fmaxf(rm1, __shfl_xor_sync(0xffffffffu, rm1, 2));
            float mn0 = fmaxf(mr[mi][0], rm0), mn1 = fmaxf(mr[mi][1], rm1);
            fsc[mi][0] = __expf(mr[mi][0] - mn0);
            fsc[mi][1] = __expf(mr[mi][1] - mn1);
            mr[mi][0] = mn0; mr[mi][1] = mn1;

            float rs0 = 0.f, rs1 = 0.f;
#pragma unroll
            for (int ni = 0; ni < 8; ni++) {
                float p00 = __expf(s[mi][ni][0] - mn0), p01 = __expf(s[mi][ni][1] - mn0);
                float p10 = __expf(s[mi][ni][2] - mn1), p11 = __expf(s[mi][ni][3] - mn1);
                rs0 += p00 + p01; rs1 += p10 + p11;
                int c0 = ni * 8 + 2 * t;
                *(uint2*)&pw[(mi * 16 + g) * LDP + c0]     = make_uint2(f2tf(p00), f2tf(p01));
                *(uint2*)&pw[(mi * 16 + g + 8) * LDP + c0] = make_uint2(f2tf(p10), f2tf(p11));
            }
            rs0 += __shfl_xor_sync(0xffffffffu, rs0, 1);
            rs0 += __shfl_xor_sync(0xffffffffu, rs0, 2);
            rs1 += __shfl_xor_sync(0xffffffffu, rs1, 1);
            rs1 += __shfl_xor_sync(0xffffffffu, rs1, 2);
            lr[mi][0] = lr[mi][0] * fsc[mi][0] + rs0;
            lr[mi][1] = lr[mi][1] * fsc[mi][1] + rs1;

            // rescale O
#pragma unroll
            for (int ni = 0; ni < 8; ni++) {
                o[mi][ni][0] *= fsc[mi][0]; o[mi][ni][1] *= fsc[mi][0];
                o[mi][ni][2] *= fsc[mi][1]; o[mi][ni][3] *= fsc[mi][1];
            }
        }
        __syncwarp();

        // O += P @ V  (V fragments shared across both row fragments)
#pragma unroll
        for (int kb = 0; kb < 8; kb++) {
            unsigned bv[8][2];
#pragma unroll
            for (int ni = 0; ni < 8; ni++) {
                bv[ni][0] = vs[(kb * 8 + t) * LDV + ni * 8 + g];
                bv[ni][1] = vs[(kb * 8 + t + 4) * LDV + ni * 8 + g];
            }
#pragma unroll
            for (int mi = 0; mi < 2; mi++) {
                unsigned af[4];
                af[0] = pw[(mi * 16 + g) * LDP + kb * 8 + t];
                af[1] = pw[(mi * 16 + g + 8) * LDP + kb * 8 + t];
                af[2] = pw[(mi * 16 + g) * LDP + kb * 8 + t + 4];
                af[3] = pw[(mi * 16 + g + 8) * LDP + kb * 8 + t + 4];
#pragma unroll
                for (int ni = 0; ni < 8; ni++)
                    mma_tf32(o[mi][ni], af, bv[ni][0], bv[ni][1]);
            }
        }
        // no bottom sync: next iteration's top barrier protects buffers
    }

    // normalize + store (pre-rounded: attout feeds only the proj GEMM)
#pragma unroll
    for (int mi = 0; mi < 2; mi++) {
        float inv0 = 1.f / lr[mi][0], inv1 = 1.f / lr[mi][1];
        int r0 = m0 + wid * 32 + mi * 16 + g, r1 = r0 + 8;
#pragma unroll
        for (int ni = 0; ni < 8; ni++) {
            int col = h * HD + ni * 8 + 2 * t;
            if (r0 < NSEQ)
                *(float2*)&attout[(long)r0 * CD + col] =
                    make_float2(tfround(o[mi][ni][0] * inv0), tfround(o[mi][ni][1] * inv0));
            if (r1 < NSEQ)
                *(float2*)&attout[(long)r1 * CD + col] =
                    make_float2(tfround(o[mi][ni][2] * inv1), tfround(o[mi][ni][3] * inv1));
        }
    }
}

// ---------------- tf32 mma.sync GEMM with fused epilogues ----------------------
// Inputs pre-rounded to tf32 -> raw u32 operands. Warp tile 64x32 (MI=4,NI=4):
// 1.5 LDS/MMA. Warps arranged 2(m) x 4(n).
enum { EPI_QKV = 2, EPI_GELU = 4, EPI_RES = 5 };

template<int EPI, int BM, int BN>
__global__ void __launch_bounds__(256, 2) mmgemm(
    const float* __restrict__ A, const float* __restrict__ B, float* __restrict__ Cc,
    int M, int N, int K, int lda, int ldb, int ldc,
    const float* __restrict__ bias, const float* __restrict__ bias2,
    const float* __restrict__ res, const float* __restrict__ gamma)
{
    constexpr int BK = 16;
    constexpr int WM = 64;
    constexpr int WN = 32;
    constexpr int MI = WM / 16;     // 4
    constexpr int NI = WN / 8;      // 4
    constexpr int LDS_ = BK + 4;

    __shared__ float As[2][BM * LDS_];
    __shared__ float Bs[2][BN * LDS_];

    int tid  = threadIdx.x;
    int wid  = tid >> 5;
    int lane = tid & 31;
    int g = lane >> 2, t = lane & 3;
    int wm = (wid & 1) * WM;
    int wn = (wid >> 1) * WN;
    int m0 = blockIdx.x * BM, n0 = blockIdx.y * BN;

    auto ldA = [&](int buf, int k0) {
#pragma unroll
        for (int i = 0; i < BM * 4 / 256; i++) {
            int idx = tid + i * 256;
            int r = idx >> 2, c = (idx & 3) * 4;
            int row = m0 + r; if (row >= M) row = M - 1;
            cp16(&As[buf][r * LDS_ + c], &A[(long)row * lda + k0 + c]);
        }
    };
    auto ldB = [&](int buf, int k0) {
#pragma unroll
        for (int i = 0; i < BN * 4 / 256; i++) {
            int idx = tid + i * 256;
            int r = idx >> 2, c = (idx & 3) * 4;
            int row = n0 + r; if (row >= N) row = N - 1;
            cp16(&Bs[buf][r * LDS_ + c], &B[(long)row * ldb + k0 + c]);
        }
    };

    float acc[MI][NI][4];
#pragma unroll
    for (int mi = 0; mi < MI; mi++)
#pragma unroll
        for (int ni = 0; ni < NI; ni++)
#pragma unroll
            for (int e = 0; e < 4; e++) acc[mi][ni][e] = 0.f;

    int KT = K / BK;
    ldA(0, 0); ldB(0, 0);
    asm volatile("cp.async.commit_group;");

    for (int kt = 0; kt < KT; kt++) {
        int cur = kt & 1;
        asm volatile("cp.async.wait_group 0;");
        __syncthreads();
        if (kt + 1 < KT) {
            ldA(cur ^ 1, (kt + 1) * BK);
            ldB(cur ^ 1, (kt + 1) * BK);
            asm volatile("cp.async.commit_group;");
        }

        const unsigned* as = (const unsigned*)As[cur];
        const unsigned* bs = (const unsigned*)Bs[cur];
#pragma unroll
        for (int kk = 0; kk < BK; kk += 8) {
            unsigned af[MI][4], bf[NI][2];
#pragma unroll
            for (int mi = 0; mi < MI; mi++) {
                int r = wm + mi * 16 + g;
                af[mi][0] = as[r * LDS_ + kk + t];
                af[mi][1] = as[(r + 8) * LDS_ + kk + t];
                af[mi][2] = as[r * LDS_ + kk + t + 4];
                af[mi][3] = as[(r + 8) * LDS_ + kk + t + 4];
            }
#pragma unroll
            for (int ni = 0; ni < NI; ni++) {
                int n = wn + ni * 8 + g;
                bf[ni][0] = bs[n * LDS_ + kk + t];
                bf[ni][1] = bs[n * LDS_ + kk + t + 4];
            }
#pragma unroll
            for (int mi = 0; mi < MI; mi++)
#pragma unroll
                for (int ni = 0; ni < NI; ni++)
                    mma_tf32(acc[mi][ni], af[mi], bf[ni][0], bf[ni][1]);
        }
        // no bottom sync: next top barrier protects buffers
    }

#pragma unroll
    for (int mi = 0; mi < MI; mi++) {
#pragma unroll
        for (int ni = 0; ni < NI; ni++) {
            int col = n0 + wn + ni * 8 + 2 * t;
            if (col >= N) continue;
#pragma unroll
            for (int half = 0; half < 2; half++) {
                int row = m0 + wm + mi * 16 + g + half * 8;
                if (row >= M) continue;
                float v0 = acc[mi][ni][half * 2 + 0];
                float v1 = acc[mi][ni][half * 2 + 1];
                if (EPI == EPI_QKV) {
                    float b0 = (col < CD) ? bias[col]
                             : (col < 2 * CD) ? 0.f : bias2[col - 2 * CD];
                    int c1 = col + 1;
                    float b1 = (c1 < CD) ? bias[c1]
                             : (c1 < 2 * CD) ? 0.f : bias2[c1 - 2 * CD];
                    v0 = tfround(v0 + b0); v1 = tfround(v1 + b1);
                } else if (EPI == EPI_GELU) {
                    v0 += bias[col]; v1 += bias[col + 1];
                    v0 = tfround(0.5f * v0 * (1.f + erff(v0 * 0.70710678118654752f)));
                    v1 = tfround(0.5f * v1 * (1.f + erff(v1 * 0.70710678118654752f)));
                } else if (EPI == EPI_RES) {
                    const float* rr = &res[(long)row * ldc + col];
                    v0 = rr[0] + gamma[col]     * (v0 + bias[col]);
                    v1 = rr[1] + gamma[col + 1] * (v1 + bias[col + 1]);
                }
                float2 ov; ov.x = v0; ov.y = v1;
                *(float2*)&Cc[(long)row * ldc + col] = ov;
            }
        }
    }
}

// ---------------- launch -------------------------------------------------------
extern "C" void kernel_launch(void* const* d_in, const int* in_sizes, int n_in,
                              void* d_out, int out_size)
{
    const float* x      = (const float*)d_in[0];
    const void*  mask   = d_in[1];
    const float* qkv_w  = (const float*)d_in[2];
    const float* q_bias = (const float*)d_in[3];
    const float* v_bias = (const float*)d_in[4];
    const float* proj_w = (const float*)d_in[5];
    const float* proj_b = (const float*)d_in[6];
    const float* n1s    = (const float*)d_in[7];
    const float* n1b    = (const float*)d_in[8];
    const float* n2s    = (const float*)d_in[9];
    const float* n2b    = (const float*)d_in[10];
    const float* w1     = (const float*)d_in[11];
    const float* b1     = (const float*)d_in[12];
    const float* w2     = (const float*)d_in[13];
    const float* b2     = (const float*)d_in[14];
    const float* g1     = (const float*)d_in[15];
    const float* g2     = (const float*)d_in[16];
    float* out = (float*)d_out;

    float *xn, *qkv, *attout, *x2, *h0, *h1, *maskf, *w;
    cudaGetSymbolAddress((void**)&xn,     g_xn);
    cudaGetSymbolAddress((void**)&qkv,    g_qkv);
    cudaGetSymbolAddress((void**)&attout, g_attout);
    cudaGetSymbolAddress((void**)&x2,     g_x2);
    cudaGetSymbolAddress((void**)&h0,     g_h0);
    cudaGetSymbolAddress((void**)&h1,     g_h1);
    cudaGetSymbolAddress((void**)&maskf,  g_maskf);
    cudaGetSymbolAddress((void**)&w,      g_w);

    static int smem_set = 0;
    if (!smem_set) {
        cudaFuncSetAttribute(flash_kernel,
                             cudaFuncAttributeMaxDynamicSharedMemorySize, FLASH_SMEM);
        smem_set = 1;
    }

    const int GM = (NSEQ + 127) / 128;   // 25

    // 0. pre-round weights to tf32 (scratch)
    round_copy_kernel<<<(C3 * CD / 4 + 255) / 256, 256>>>(qkv_w, w + WQKV_OFF, C3 * CD / 4);
    round_copy_kernel<<<(CD * CD / 4 + 255) / 256, 256>>>(proj_w, w + WPROJ_OFF, CD * CD / 4);
    round_copy_kernel<<<(HID * CD / 4 + 255) / 256, 256>>>(w1, w + W1_OFF, HID * CD / 4);
    round_copy_kernel<<<(CD * HID / 4 + 255) / 256, 256>>>(w2, w + W2_OFF, CD * HID / 4);

    // 1. LN1 + mask prep
    ln_kernel<<<NSEQ, 256>>>(x, n1s, n1b, xn);
    mask_detect_kernel<<<1, 256>>>((const unsigned int*)mask);
    mask_prep_kernel<<<(NSEQ + 255) / 256, 256>>>(mask, maskf);

    // 2. QKV projection
    mmgemm<EPI_QKV, 128, 128><<<dim3(GM, C3 / 128, 1), 256>>>(
        xn, w + WQKV_OFF, qkv, NSEQ, C3, CD, CD, CD, C3,
        q_bias, v_bias, nullptr, nullptr);

    // 3-5. flash attention (QK^T + mask + softmax + PV fused)
    flash_kernel<<<dim3(GM, NH), 128, FLASH_SMEM>>>(qkv, maskf, attout);

    // 6. proj + residual
    mmgemm<EPI_RES, 128, 128><<<dim3(GM, CD / 128, 1), 256>>>(
        attout, w + WPROJ_OFF, x2, NSEQ, CD, CD, CD, CD, CD,
        proj_b, nullptr, x, g1);

    // 7. LN2
    ln_kernel<<<NSEQ, 256>>>(x2, n2s, n2b, h0);

    // 8. MLP1 + exact GELU
    mmgemm<EPI_GELU, 128, 128><<<dim3(GM, HID / 128, 1), 256>>>(
        h0, w + W1_OFF, h1, NSEQ, HID, CD, CD, CD, HID,
        b1, nullptr, nullptr, nullptr);

    // 9. MLP2 + final residual
    mmgemm<EPI_RES, 128, 128><<<dim3(GM, CD / 128, 1), 256>>>(
        h1, w + W2_OFF, out, NSEQ, CD, HID, HID, HID, CD,
        b2, nullptr, x2, g2);
}

// round 9
// speedup vs baseline: 5.0920x; 1.8923x over previous
#include <cuda_runtime.h>
#include <cuda_bf16.h>
#include <math.h>

#define NSEQ 3136
#define CD   768
#define NH   12
#define HD   64
#define HID  3072
#define C3   2304

// rounded-weight scratch offsets (bf16 elements)
#define WQKV_OFF 0
#define WPROJ_OFF 1769472               // 2304*768
#define W1_OFF   (WPROJ_OFF + 589824)   // +768*768
#define W2_OFF   (W1_OFF + 2359296)     // +3072*768
#define W_TOTAL  (W2_OFF + 2359296)

// ---------------- scratch (static device globals; no allocation) -------------
__device__ __nv_bfloat16 g_xn[NSEQ * CD];
__device__ __nv_bfloat16 g_qkv[NSEQ * C3];
__device__ __nv_bfloat16 g_vt[CD * NSEQ];        // V transposed: [dim][token]
__device__ __nv_bfloat16 g_attout[NSEQ * CD];
__device__ __nv_bfloat16 g_h0[NSEQ * CD];
__device__ __nv_bfloat16 g_h1[NSEQ * HID];
__device__ __nv_bfloat16 g_w[W_TOTAL];
__device__ float g_x2[NSEQ * CD];
__device__ float g_maskf[NSEQ];
__device__ int   g_maskByte;

// ---------------- helpers ----------------------------------------------------
__device__ __forceinline__ float warpSum(float v) {
#pragma unroll
    for (int o = 16; o; o >>= 1) v += __shfl_xor_sync(0xffffffffu, v, o);
    return v;
}
__device__ __forceinline__ unsigned packbf(float lo, float hi) {
    unsigned r;
    asm("cvt.rn.bf16x2.f32 %0, %1, %2;" : "=r"(r) : "f"(hi), "f"(lo));
    return r;
}
__device__ __forceinline__ void cp16(void* s, const void* g) {
    unsigned a = (unsigned)__cvta_generic_to_shared(s);
    asm volatile("cp.async.ca.shared.global [%0], [%1], 16;" :: "r"(a), "l"(g));
}
__device__ __forceinline__ void mma_bf16(float* c, const unsigned* a, unsigned b0, unsigned b1) {
    asm volatile(
        "mma.sync.aligned.m16n8k16.row.col.f32.bf16.bf16.f32 "
        "{%0,%1,%2,%3}, {%4,%5,%6,%7}, {%8,%9}, {%0,%1,%2,%3};"
        : "+f"(c[0]), "+f"(c[1]), "+f"(c[2]), "+f"(c[3])
        : "r"(a[0]), "r"(a[1]), "r"(a[2]), "r"(a[3]), "r"(b0), "r"(b1));
}

// ---------------- weight conversion to bf16 ------------------------------------
__global__ void __launch_bounds__(256) round_copy_kernel(
    const float* __restrict__ in, unsigned* __restrict__ out, int n4)
{
    int i = blockIdx.x * 256 + threadIdx.x;
    if (i < n4) {
        float4 v = ((const float4*)in)[i];
        uint2 o;
        o.x = packbf(v.x, v.y);
        o.y = packbf(v.z, v.w);
        ((uint2*)out)[i] = o;
    }
}

// ---------------- mask prep ---------------------------------------------------
__global__ void mask_detect_kernel(const unsigned int* __restrict__ m) {
    __shared__ int flag;
    if (threadIdx.x == 0) flag = 0;
    __syncthreads();
    for (int i = threadIdx.x; i < NSEQ / 4; i += 256)
        if (m[i] > 1u) flag = 1;
    __syncthreads();
    if (threadIdx.x == 0) g_maskByte = flag;
}

__global__ void mask_prep_kernel(const void* __restrict__ mask, float* __restrict__ mf) {
    int i = blockIdx.x * 256 + threadIdx.x;
    if (i < NSEQ) {
        bool m = g_maskByte ? (((const unsigned char*)mask)[i] != 0)
                            : (((const int*)mask)[i] != 0);
        mf[i] = m ? -1e30f : 0.f;
    }
}

// ---------------- layernorm (bf16 output) --------------------------------------
__global__ void __launch_bounds__(256) ln_kernel(
    const float* __restrict__ x, const float* __restrict__ sc,
    const float* __restrict__ bi, __nv_bfloat16* __restrict__ y)
{
    int row = blockIdx.x;
    const float* xr = x + (long)row * CD;
    __nv_bfloat16* yr = y + (long)row * CD;
    int t = threadIdx.x;
    float v[3];
    float s = 0.f, s2 = 0.f;
#pragma unroll
    for (int i = 0; i < 3; i++) {
        float a = xr[t + i * 256];
        v[i] = a; s += a; s2 += a * a;
    }
    __shared__ float sh[32], sh2[32];
    float ws = warpSum(s), ws2 = warpSum(s2);
    int lane = t & 31, wid = t >> 5;
    if (lane == 0) { sh[wid] = ws; sh2[wid] = ws2; }
    __syncthreads();
    if (wid == 0) {
        float a = lane < 8 ? sh[lane] : 0.f;
        float b = lane < 8 ? sh2[lane] : 0.f;
        a = warpSum(a); b = warpSum(b);
        if (lane == 0) { sh[0] = a; sh2[0] = b; }
    }
    __syncthreads();
    float mu  = sh[0] * (1.f / CD);
    float var = sh2[0] * (1.f / CD) - mu * mu;
    float inv = rsqrtf(var + 1e-5f);
#pragma unroll
    for (int i = 0; i < 3; i++) {
        int c = t + i * 256;
        yr[c] = __float2bfloat16_rn((v[i] - mu) * inv * sc[c] + bi[c]);
    }
}

// ---------------- flash attention (bf16) ---------------------------------------
// One block = one (q-tile of 128, head). 4 warps, warp owns 32 q-rows (mi=2).
// K tiles [key][dim], V pre-transposed [dim][token]. Per-mi softmax/PV keeps
// live registers under the 3-blocks/SM budget -> 300 blocks in ONE wave.
#define FLASH_SMEM (3 * 64 * 72 * 2 * 2 + 2 * 64 * 4)   // K,V,P bf16 + mask f32

__global__ void __launch_bounds__(128, 3) flash_kernel(
    const __nv_bfloat16* __restrict__ qkv, const __nv_bfloat16* __restrict__ vt,
    const float* __restrict__ maskf, __nv_bfloat16* __restrict__ attout)
{
    extern __shared__ char smc[];
    __nv_bfloat16* Ks = (__nv_bfloat16*)smc;        // 2 * 64*72
    __nv_bfloat16* Vs = Ks + 2 * 64 * 72;           // 2 * 64*72 (rows = dims)
    __nv_bfloat16* Ps = Vs + 2 * 64 * 72;           // 4 warps * 32*72
    float* Ms = (float*)(Ps + 4 * 32 * 72);         // 2 * 64

    int h  = blockIdx.y;
    int m0 = blockIdx.x * 128;
    int tid = threadIdx.x, wid = tid >> 5, lane = tid & 31;
    int g = lane >> 2, t = lane & 3;

    const __nv_bfloat16* Qp  = qkv + h * HD;
    const __nv_bfloat16* Kp  = qkv + CD + h * HD;
    const __nv_bfloat16* Vtp = vt + (long)h * HD * NSEQ;

    // Q fragments (bf16 pairs, unscaled; scores scaled by 0.125 in fp32)
    unsigned qf[4][2][4];
#pragma unroll
    for (int mi = 0; mi < 2; mi++) {
        int r0 = m0 + wid * 32 + mi * 16 + g; if (r0 >= NSEQ) r0 = NSEQ - 1;
        int r1 = r0 + 8;                      if (r1 >= NSEQ) r1 = NSEQ - 1;
        const __nv_bfloat16* q0 = Qp + (long)r0 * C3;
        const __nv_bfloat16* q1 = Qp + (long)r1 * C3;
#pragma unroll
        for (int kb = 0; kb < 4; kb++) {
            qf[kb][mi][0] = *(const unsigned*)&q0[kb * 16 + 2 * t];
            qf[kb][mi][1] = *(const unsigned*)&q1[kb * 16 + 2 * t];
            qf[kb][mi][2] = *(const unsigned*)&q0[kb * 16 + 8 + 2 * t];
            qf[kb][mi][3] = *(const unsigned*)&q1[kb * 16 + 8 + 2 * t];
        }
    }

    float o[2][8][4];
#pragma unroll
    for (int mi = 0; mi < 2; mi++)
#pragma unroll
        for (int ni = 0; ni < 8; ni++)
#pragma unroll
            for (int e = 0; e < 4; e++) o[mi][ni][e] = 0.f;
    float mr[2][2], lr[2][2];
#pragma unroll
    for (int mi = 0; mi < 2; mi++) {
        mr[mi][0] = mr[mi][1] = -3.4e38f;
        lr[mi][0] = lr[mi][1] = 0.f;
    }

    auto loadKV = [&](int buf, int j0) {
#pragma unroll
        for (int i = 0; i < 4; i++) {
            int idx = tid + i * 128;            // 0..511
            int r = idx >> 3, c = (idx & 7) * 8;
            cp16(&Ks[buf * 64 * 72 + r * 72 + c], &Kp[(long)(j0 + r) * C3 + c]);
            cp16(&Vs[buf * 64 * 72 + r * 72 + c], &Vtp[(long)r * NSEQ + j0 + c]);
        }
        if (tid < 16) cp16(&Ms[buf * 64 + tid * 4], &maskf[j0 + tid * 4]);
    };

    loadKV(0, 0);
    asm volatile("cp.async.commit_group;");

    const int NJ = NSEQ / 64;   // 49
    unsigned* pw = (unsigned*)(Ps + wid * 32 * 72);    // word stride 36

    for (int j = 0; j < NJ; j++) {
        int cur = j & 1;
        asm volatile("cp.async.wait_group 0;");
        __syncthreads();
        if (j + 1 < NJ) {
            loadKV(cur ^ 1, (j + 1) * 64);
            asm volatile("cp.async.commit_group;");
        }

        const unsigned* ks = (const unsigned*)(Ks + cur * 64 * 72);   // stride 36 words
        const unsigned* vs = (const unsigned*)(Vs + cur * 64 * 72);
        const float* ms = Ms + cur * 64;

#pragma unroll
        for (int mi = 0; mi < 2; mi++) {
            // S = Q @ K^T for this row fragment
            float s[8][4];
#pragma unroll
            for (int ni = 0; ni < 8; ni++)
                s[ni][0] = s[ni][1] = s[ni][2] = s[ni][3] = 0.f;
#pragma unroll
            for (int kb = 0; kb < 4; kb++) {
#pragma unroll
                for (int ni = 0; ni < 8; ni++) {
                    unsigned b0 = ks[(ni * 8 + g) * 36 + kb * 8 + t];
                    unsigned b1 = ks[(ni * 8 + g) * 36 + kb * 8 + 4 + t];
                    mma_bf16(s[ni], qf[kb][mi], b0, b1);
                }
            }

            // scale + mask + row max
            float rm0 = -3.4e38f, rm1 = -3.4e38f;
#pragma unroll
            for (int ni = 0; ni < 8; ni++) {
                int c0 = ni * 8 + 2 * t;
                float a0 = ms[c0], a1 = ms[c0 + 1];
                s[ni][0] = s[ni][0] * 0.125f + a0;
                s[ni][1] = s[ni][1] * 0.125f + a1;
                s[ni][2] = s[ni][2] * 0.125f + a0;
                s[ni][3] = s[ni][3] * 0.125f + a1;
                rm0 = fmaxf(rm0, fmaxf(s[ni][0], s[ni][1]));
                rm1 = fmaxf(rm1, fmaxf(s[ni][2], s[ni][3]));
            }
            rm0 = fmaxf(rm0, __shfl_xor_sync(0xffffffffu, rm0, 1));
            rm0 = fmaxf(rm0, __shfl_xor_sync(0xffffffffu, rm0, 2));
            rm1 = fmaxf(rm1, __shfl_xor_sync(0xffffffffu, rm1, 1));
            rm1 = fmaxf(rm1, __shfl_xor_sync(0xffffffffu, rm1, 2));
            float mn0 = fmaxf(mr[mi][0], rm0), mn1 = fmaxf(mr[mi][1], rm1);
            float f0 = __expf(mr[mi][0] - mn0), f1 = __expf(mr[mi][1] - mn1);
            mr[mi][0] = mn0; mr[mi][1] = mn1;

            float rs0 = 0.f, rs1 = 0.f;
#pragma unroll
            for (int ni = 0; ni < 8; ni++) {
                float p00 = __expf(s[ni][0] - mn0), p01 = __expf(s[ni][1] - mn0);
                float p10 = __expf(s[ni][2] - mn1), p11 = __expf(s[ni][3] - mn1);
                rs0 += p00 + p01; rs1 += p10 + p11;
                pw[(mi * 16 + g) * 36 + ni * 4 + t]     = packbf(p00, p01);
                pw[(mi * 16 + g + 8) * 36 + ni * 4 + t] = packbf(p10, p11);
            }
            rs0 += __shfl_xor_sync(0xffffffffu, rs0, 1);
            rs0 += __shfl_xor_sync(0xffffffffu, rs0, 2);
            rs1 += __shfl_xor_sync(0xffffffffu, rs1, 1);
            rs1 += __shfl_xor_sync(0xffffffffu, rs1, 2);
            lr[mi][0] = lr[mi][0] * f0 + rs0;
            lr[mi][1] = lr[mi][1] * f1 + rs1;

#pragma unroll
            for (int ni = 0; ni < 8; ni++) {
                o[mi][ni][0] *= f0; o[mi][ni][1] *= f0;
                o[mi][ni][2] *= f1; o[mi][ni][3] *= f1;
            }
            __syncwarp();

            // O += P @ V  (V transposed: b-fragments contiguous)
#pragma unroll
            for (int kb = 0; kb < 4; kb++) {
                unsigned af[4];
                af[0] = pw[(mi * 16 + g) * 36 + kb * 8 + t];
                af[1] = pw[(mi * 16 + g + 8) * 36 + kb * 8 + t];
                af[2] = pw[(mi * 16 + g) * 36 + kb * 8 + 4 + t];
                af[3] = pw[(mi * 16 + g + 8) * 36 + kb * 8 + 4 + t];
#pragma unroll
                for (int ni = 0; ni < 8; ni++) {
                    unsigned b0 = vs[(ni * 8 + g) * 36 + kb * 8 + t];
                    unsigned b1 = vs[(ni * 8 + g) * 36 + kb * 8 + 4 + t];
                    mma_bf16(o[mi][ni], af, b0, b1);
                }
            }
        }
        // no bottom sync: next top barrier protects buffers
    }

    // normalize + store (bf16, feeds proj GEMM)
#pragma unroll
    for (int mi = 0; mi < 2; mi++) {
        float inv0 = 1.f / lr[mi][0], inv1 = 1.f / lr[mi][1];
        int r0 = m0 + wid * 32 + mi * 16 + g, r1 = r0 + 8;
#pragma unroll
        for (int ni = 0; ni < 8; ni++) {
            int col = h * HD + ni * 8 + 2 * t;
            if (r0 < NSEQ)
                *(unsigned*)&attout[(long)r0 * CD + col] =
                    packbf(o[mi][ni][0] * inv0, o[mi][ni][1] * inv0);
            if (r1 < NSEQ)
                *(unsigned*)&attout[(long)r1 * CD + col] =
                    packbf(o[mi][ni][2] * inv1, o[mi][ni][3] * inv1);
        }
    }
}

// ---------------- bf16 mma GEMM with fused epilogues ---------------------------
// C[M,N] = A[M,K] @ B[N,K]^T. BK=32 (two k16 steps). Warp tile 64x32.
// BM=128: 8 warps (2x4), 256 thr, 2 blk/SM.  BM=64: 4 warps (1x4), 128 thr, 4 blk/SM.
enum { EPI_QKV = 2, EPI_GELU = 4, EPI_RES = 5 };

template<int EPI, int BM>
__global__ void __launch_bounds__(BM * 2, 256 / (BM / 64) / 64) mmgemm(
    const __nv_bfloat16* __restrict__ A, const __nv_bfloat16* __restrict__ B,
    void* __restrict__ Cout,
    int M, int N, int K, int lda, int ldb, int ldc,
    const float* __restrict__ bias, const float* __restrict__ bias2,
    const float* __restrict__ res, const float* __restrict__ gamma,
    __nv_bfloat16* __restrict__ vt)
{
    constexpr int THREADS = BM * 2;
    constexpr int WROWS = BM / 64;
    constexpr int MI = 4, NI = 4;
    constexpr int LDE = 40;            // bf16 elems per smem row (32 + 8 pad)
    constexpr int LDW = 20;            // words per row

    __shared__ __nv_bfloat16 As[2][BM * LDE];
    __shared__ __nv_bfloat16 Bs[2][128 * LDE];

    int tid  = threadIdx.x;
    int wid  = tid >> 5;
    int lane = tid & 31;
    int g = lane >> 2, t = lane & 3;
    int wm = (wid % WROWS) * 64;
    int wn = (wid / WROWS) * 32;
    int m0 = blockIdx.x * BM, n0 = blockIdx.y * 128;

    auto ldA = [&](int buf, int k0) {
#pragma unroll
        for (int i = 0; i < 2; i++) {
            int idx = tid + i * THREADS;       // BM*4 chunks
            int r = idx >> 2, c = (idx & 3) * 8;
            int row = m0 + r; if (row >= M) row = M - 1;
            cp16(&As[buf][r * LDE + c], &A[(long)row * lda + k0 + c]);
        }
    };
    auto ldB = [&](int buf, int k0) {
#pragma unroll
        for (int i = 0; i < 256 / BM; i++) {
            int idx = tid + i * THREADS;       // 512 chunks
            int r = idx >> 2, c = (idx & 3) * 8;
            int row = n0 + r; if (row >= N) row = N - 1;
            cp16(&Bs[buf][r * LDE + c], &B[(long)row * ldb + k0 + c]);
        }
    };

    float acc[MI][NI][4];
#pragma unroll
    for (int mi = 0; mi < MI; mi++)
#pragma unroll
        for (int ni = 0; ni < NI; ni++)
#pragma unroll
            for (int e = 0; e < 4; e++) acc[mi][ni][e] = 0.f;

    int KT = K / 32;
    ldA(0, 0); ldB(0, 0);
    asm volatile("cp.async.commit_group;");

    for (int kt = 0; kt < KT; kt++) {
        int cur = kt & 1;
        asm volatile("cp.async.wait_group 0;");
        __syncthreads();
        if (kt + 1 < KT) {
            ldA(cur ^ 1, (kt + 1) * 32);
            ldB(cur ^ 1, (kt + 1) * 32);
            asm volatile("cp.async.commit_group;");
        }

        const unsigned* as = (const unsigned*)As[cur];
        const unsigned* bs = (const unsigned*)Bs[cur];
#pragma unroll
        for (int kb = 0; kb < 16; kb += 8) {    // two k16 steps (word offset 0, 8)
            unsigned af[MI][4], bf[NI][2];
#pragma unroll
            for (int mi = 0; mi < MI; mi++) {
                int r = wm + mi * 16 + g;
                af[mi][0] = as[r * LDW + kb + t];
                af[mi][1] = as[(r + 8) * LDW + kb + t];
                af[mi][2] = as[r * LDW + kb + 4 + t];
                af[mi][3] = as[(r + 8) * LDW + kb + 4 + t];
            }
#pragma unroll
            for (int ni = 0; ni < NI; ni++) {
                int n = wn + ni * 8 + g;
                bf[ni][0] = bs[n * LDW + kb + t];
                bf[ni][1] = bs[n * LDW + kb + 4 + t];
            }
#pragma unroll
            for (int mi = 0; mi < MI; mi++)
#pragma unroll
                for (int ni = 0; ni < NI; ni++)
                    mma_bf16(acc[mi][ni], af[mi], bf[ni][0], bf[ni][1]);
        }
        // no bottom sync: next top barrier protects buffers
    }

#pragma unroll
    for (int mi = 0; mi < MI; mi++) {
#pragma unroll
        for (int ni = 0; ni < NI; ni++) {
            int col = n0 + wn + ni * 8 + 2 * t;
            if (col >= N) continue;
#pragma unroll
            for (int half = 0; half < 2; half++) {
                int row = m0 + wm + mi * 16 + g + half * 8;
                if (row >= M) continue;
                float v0 = acc[mi][ni][half * 2 + 0];
                float v1 = acc[mi][ni][half * 2 + 1];
                if (EPI == EPI_QKV) {
                    float b0 = (col < CD) ? bias[col]
                             : (col < 2 * CD) ? 0.f : bias2[col - 2 * CD];
                    int c1 = col + 1;
                    float b1 = (c1 < CD) ? bias[c1]
                             : (c1 < 2 * CD) ? 0.f : bias2[c1 - 2 * CD];
                    v0 += b0; v1 += b1;
                    if (col < 2 * CD) {
                        __nv_bfloat16* q = (__nv_bfloat16*)Cout;
                        *(unsigned*)&q[(long)row * ldc + col] = packbf(v0, v1);
                    } else {
                        int d = col - 2 * CD;
                        vt[(long)d * NSEQ + row]       = __float2bfloat16_rn(v0);
                        vt[(long)(d + 1) * NSEQ + row] = __float2bfloat16_rn(v1);
                    }
                } else if (EPI == EPI_GELU) {
                    v0 += bias[col]; v1 += bias[col + 1];
                    v0 = 0.5f * v0 * (1.f + erff(v0 * 0.70710678118654752f));
                    v1 = 0.5f * v1 * (1.f + erff(v1 * 0.70710678118654752f));
                    __nv_bfloat16* q = (__nv_bfloat16*)Cout;
                    *(unsigned*)&q[(long)row * ldc + col] = packbf(v0, v1);
                } else {  // EPI_RES
                    const float* rr = &res[(long)row * ldc + col];
                    float* q = (float*)Cout;
                    float2 ov;
                    ov.x = rr[0] + gamma[col]     * (v0 + bias[col]);
                    ov.y = rr[1] + gamma[col + 1] * (v1 + bias[col + 1]);
                    *(float2*)&q[(long)row * ldc + col] = ov;
                }
            }
        }
    }
}

// ---------------- launch -------------------------------------------------------
extern "C" void kernel_launch(void* const* d_in, const int* in_sizes, int n_in,
                              void* d_out, int out_size)
{
    const float* x      = (const float*)d_in[0];
    const void*  mask   = d_in[1];
    const float* qkv_w  = (const float*)d_in[2];
    const float* q_bias = (const float*)d_in[3];
    const float* v_bias = (const float*)d_in[4];
    const float* proj_w = (const float*)d_in[5];
    const float* proj_b = (const float*)d_in[6];
    const float* n1s    = (const float*)d_in[7];
    const float* n1b    = (const float*)d_in[8];
    const float* n2s    = (const float*)d_in[9];
    const float* n2b    = (const float*)d_in[10];
    const float* w1     = (const float*)d_in[11];
    const float* b1     = (const float*)d_in[12];
    const float* w2     = (const float*)d_in[13];
    const float* b2     = (const float*)d_in[14];
    const float* g1     = (const float*)d_in[15];
    const float* g2     = (const float*)d_in[16];
    float* out = (float*)d_out;

    __nv_bfloat16 *xn, *qkv, *vt, *attout, *h0, *h1, *w;
    float *x2, *maskf;
    cudaGetSymbolAddress((void**)&xn,     g_xn);
    cudaGetSymbolAddress((void**)&qkv,    g_qkv);
    cudaGetSymbolAddress((void**)&vt,     g_vt);
    cudaGetSymbolAddress((void**)&attout, g_attout);
    cudaGetSymbolAddress((void**)&h0,     g_h0);
    cudaGetSymbolAddress((void**)&h1,     g_h1);
    cudaGetSymbolAddress((void**)&w,      g_w);
    cudaGetSymbolAddress((void**)&x2,     g_x2);
    cudaGetSymbolAddress((void**)&maskf,  g_maskf);

    static int smem_set = 0;
    if (!smem_set) {
        cudaFuncSetAttribute(flash_kernel,
                             cudaFuncAttributeMaxDynamicSharedMemorySize, FLASH_SMEM);
        smem_set = 1;
    }

    // 0. convert weights to bf16
    round_copy_kernel<<<(C3 * CD / 4 + 255) / 256, 256>>>(qkv_w, (unsigned*)(w + WQKV_OFF), C3 * CD / 4);
    round_copy_kernel<<<(CD * CD / 4 + 255) / 256, 256>>>(proj_w, (unsigned*)(w + WPROJ_OFF), CD * CD / 4);
    round_copy_kernel<<<(HID * CD / 4 + 255) / 256, 256>>>(w1, (unsigned*)(w + W1_OFF), HID * CD / 4);
    round_copy_kernel<<<(CD * HID / 4 + 255) / 256, 256>>>(w2, (unsigned*)(w + W2_OFF), CD * HID / 4);

    // 1. LN1 + mask prep
    ln_kernel<<<NSEQ, 256>>>(x, n1s, n1b, xn);
    mask_detect_kernel<<<1, 256>>>((const unsigned int*)mask);
    mask_prep_kernel<<<(NSEQ + 255) / 256, 256>>>(mask, maskf);

    // 2. QKV projection (Q,K -> qkv buffer; V -> vt transposed)
    mmgemm<EPI_QKV, 128><<<dim3(25, C3 / 128, 1), 256>>>(
        xn, w + WQKV_OFF, qkv, NSEQ, C3, CD, CD, CD, C3,
        q_bias, v_bias, nullptr, nullptr, vt);

    // 3-5. flash attention
    flash_kernel<<<dim3(25, NH), 128, FLASH_SMEM>>>(qkv, vt, maskf, attout);

    // 6. proj + residual (BM=64, full-chip single wave)
    mmgemm<EPI_RES, 64><<<dim3(49, CD / 128, 1), 128>>>(
        attout, w + WPROJ_OFF, x2, NSEQ, CD, CD, CD, CD, CD,
        proj_b, nullptr, x, g1, nullptr);

    // 7. LN2
    ln_kernel<<<NSEQ, 256>>>(x2, n2s, n2b, h0);

    // 8. MLP1 + exact GELU
    mmgemm<EPI_GELU, 128><<<dim3(25, HID / 128, 1), 256>>>(
        h0, w + W1_OFF, h1, NSEQ, HID, CD, CD, CD, HID,
        b1, nullptr, nullptr, nullptr, nullptr);

    // 9. MLP2 + final residual (BM=64)
    mmgemm<EPI_RES, 64><<<dim3(49, CD / 128, 1), 128>>>(
        h1, w + W2_OFF, out, NSEQ, CD, HID, HID, HID, CD,
        b2, nullptr, x2, g2, nullptr);
}

// round 10
// speedup vs baseline: 5.6713x; 1.1138x over previous
#include <cuda_runtime.h>
#include <cuda_bf16.h>
#include <math.h>

#define NSEQ 3136
#define CD   768
#define NH   12
#define HD   64
#define HID  3072
#define C3   2304

// rounded-weight scratch offsets (bf16 elements)
#define WQKV_OFF 0
#define WPROJ_OFF 1769472               // 2304*768
#define W1_OFF   (WPROJ_OFF + 589824)   // +768*768
#define W2_OFF   (W1_OFF + 2359296)     // +3072*768
#define W_TOTAL  (W2_OFF + 2359296)

// ---------------- scratch (static device globals; no allocation) -------------
__device__ __nv_bfloat16 g_xn[NSEQ * CD];
__device__ __nv_bfloat16 g_qkv[NSEQ * C3];
__device__ __nv_bfloat16 g_vt[CD * NSEQ];        // V transposed: [dim][token]
__device__ __nv_bfloat16 g_attout[NSEQ * CD];
__device__ __nv_bfloat16 g_h0[NSEQ * CD];
__device__ __nv_bfloat16 g_h1[NSEQ * HID];
__device__ __nv_bfloat16 g_w[W_TOTAL];
__device__ float g_x2[NSEQ * CD];
__device__ float g_maskf[NSEQ];
__device__ int   g_maskByte;

// ---------------- helpers ----------------------------------------------------
__device__ __forceinline__ float warpSum(float v) {
#pragma unroll
    for (int o = 16; o; o >>= 1) v += __shfl_xor_sync(0xffffffffu, v, o);
    return v;
}
__device__ __forceinline__ unsigned packbf(float lo, float hi) {
    unsigned r;
    asm("cvt.rn.bf16x2.f32 %0, %1, %2;" : "=r"(r) : "f"(hi), "f"(lo));
    return r;
}
__device__ __forceinline__ void cp16(void* s, const void* g) {
    unsigned a = (unsigned)__cvta_generic_to_shared(s);
    asm volatile("cp.async.ca.shared.global [%0], [%1], 16;" :: "r"(a), "l"(g));
}
__device__ __forceinline__ unsigned s2u(const void* p) {
    return (unsigned)__cvta_generic_to_shared(p);
}
__device__ __forceinline__ void ldsm4(unsigned& r0, unsigned& r1, unsigned& r2, unsigned& r3,
                                      unsigned addr) {
    asm volatile("ldmatrix.sync.aligned.m8n8.x4.shared.b16 {%0,%1,%2,%3}, [%4];"
        : "=r"(r0), "=r"(r1), "=r"(r2), "=r"(r3) : "r"(addr));
}
__device__ __forceinline__ void mma_bf16(float* c, const unsigned* a, unsigned b0, unsigned b1) {
    asm volatile(
        "mma.sync.aligned.m16n8k16.row.col.f32.bf16.bf16.f32 "
        "{%0,%1,%2,%3}, {%4,%5,%6,%7}, {%8,%9}, {%0,%1,%2,%3};"
        : "+f"(c[0]), "+f"(c[1]), "+f"(c[2]), "+f"(c[3])
        : "r"(a[0]), "r"(a[1]), "r"(a[2]), "r"(a[3]), "r"(b0), "r"(b1));
}

// ---------------- weight conversion to bf16 ------------------------------------
__global__ void __launch_bounds__(256) round_copy_kernel(
    const float* __restrict__ in, unsigned* __restrict__ out, int n4)
{
    int i = blockIdx.x * 256 + threadIdx.x;
    if (i < n4) {
        float4 v = ((const float4*)in)[i];
        uint2 o;
        o.x = packbf(v.x, v.y);
        o.y = packbf(v.z, v.w);
        ((uint2*)out)[i] = o;
    }
}

// ---------------- mask prep ---------------------------------------------------
__global__ void mask_detect_kernel(const unsigned int* __restrict__ m) {
    __shared__ int flag;
    if (threadIdx.x == 0) flag = 0;
    __syncthreads();
    for (int i = threadIdx.x; i < NSEQ / 4; i += 256)
        if (m[i] > 1u) flag = 1;
    __syncthreads();
    if (threadIdx.x == 0) g_maskByte = flag;
}

__global__ void mask_prep_kernel(const void* __restrict__ mask, float* __restrict__ mf) {
    int i = blockIdx.x * 256 + threadIdx.x;
    if (i < NSEQ) {
        bool m = g_maskByte ? (((const unsigned char*)mask)[i] != 0)
                            : (((const int*)mask)[i] != 0);
        mf[i] = m ? -1e30f : 0.f;
    }
}

// ---------------- layernorm (bf16 output) --------------------------------------
__global__ void __launch_bounds__(256) ln_kernel(
    const float* __restrict__ x, const float* __restrict__ sc,
    const float* __restrict__ bi, __nv_bfloat16* __restrict__ y)
{
    int row = blockIdx.x;
    const float* xr = x + (long)row * CD;
    __nv_bfloat16* yr = y + (long)row * CD;
    int t = threadIdx.x;
    float v[3];
    float s = 0.f, s2 = 0.f;
#pragma unroll
    for (int i = 0; i < 3; i++) {
        float a = xr[t + i * 256];
        v[i] = a; s += a; s2 += a * a;
    }
    __shared__ float sh[32], sh2[32];
    float ws = warpSum(s), ws2 = warpSum(s2);
    int lane = t & 31, wid = t >> 5;
    if (lane == 0) { sh[wid] = ws; sh2[wid] = ws2; }
    __syncthreads();
    if (wid == 0) {
        float a = lane < 8 ? sh[lane] : 0.f;
        float b = lane < 8 ? sh2[lane] : 0.f;
        a = warpSum(a); b = warpSum(b);
        if (lane == 0) { sh[0] = a; sh2[0] = b; }
    }
    __syncthreads();
    float mu  = sh[0] * (1.f / CD);
    float var = sh2[0] * (1.f / CD) - mu * mu;
    float inv = rsqrtf(var + 1e-5f);
#pragma unroll
    for (int i = 0; i < 3; i++) {
        int c = t + i * 256;
        yr[c] = __float2bfloat16_rn((v[i] - mu) * inv * sc[c] + bi[c]);
    }
}

// ---------------- flash attention (bf16 + ldmatrix) ----------------------------
// One block = one (q-tile of 128, head). 4 warps, warp owns 32 q-rows (mi=2).
// K tiles [key][dim], V pre-transposed [dim][token]. All smem fragment loads
// via ldmatrix (rows 144B-strided: 16B-aligned, conflict-free). 3 blocks/SM ->
// 300 blocks in ONE wave.
#define FLASH_SMEM (3 * 64 * 72 * 2 * 2 + 2 * 64 * 4)   // K,V,P bf16 + mask f32

__global__ void __launch_bounds__(128, 3) flash_kernel(
    const __nv_bfloat16* __restrict__ qkv, const __nv_bfloat16* __restrict__ vt,
    const float* __restrict__ maskf, __nv_bfloat16* __restrict__ attout)
{
    extern __shared__ __align__(16) char smc[];
    __nv_bfloat16* Ks = (__nv_bfloat16*)smc;        // 2 * 64*72
    __nv_bfloat16* Vs = Ks + 2 * 64 * 72;           // 2 * 64*72 (rows = dims)
    __nv_bfloat16* Ps = Vs + 2 * 64 * 72;           // 4 warps * 32*72
    float* Ms = (float*)(Ps + 4 * 32 * 72);         // 2 * 64

    int h  = blockIdx.y;
    int m0 = blockIdx.x * 128;
    int tid = threadIdx.x, wid = tid >> 5, lane = tid & 31;
    int g = lane >> 2, t = lane & 3;
    int rowA = lane & 15, hiA = lane >> 4;                 // A-pattern ldmatrix
    int rowB = (lane & 7) + (lane >> 4) * 8;               // B-pattern ldmatrix
    int hiB  = (lane >> 3) & 1;

    const __nv_bfloat16* Qp  = qkv + h * HD;
    const __nv_bfloat16* Kp  = qkv + CD + h * HD;
    const __nv_bfloat16* Vtp = vt + (long)h * HD * NSEQ;

    // Q fragments (bf16 pairs, unscaled; scores scaled by 0.125 in fp32)
    unsigned qf[4][2][4];
#pragma unroll
    for (int mi = 0; mi < 2; mi++) {
        int r0 = m0 + wid * 32 + mi * 16 + g; if (r0 >= NSEQ) r0 = NSEQ - 1;
        int r1 = r0 + 8;                      if (r1 >= NSEQ) r1 = NSEQ - 1;
        const __nv_bfloat16* q0 = Qp + (long)r0 * C3;
        const __nv_bfloat16* q1 = Qp + (long)r1 * C3;
#pragma unroll
        for (int kb = 0; kb < 4; kb++) {
            qf[kb][mi][0] = *(const unsigned*)&q0[kb * 16 + 2 * t];
            qf[kb][mi][1] = *(const unsigned*)&q1[kb * 16 + 2 * t];
            qf[kb][mi][2] = *(const unsigned*)&q0[kb * 16 + 8 + 2 * t];
            qf[kb][mi][3] = *(const unsigned*)&q1[kb * 16 + 8 + 2 * t];
        }
    }

    float o[2][8][4];
#pragma unroll
    for (int mi = 0; mi < 2; mi++)
#pragma unroll
        for (int ni = 0; ni < 8; ni++)
#pragma unroll
            for (int e = 0; e < 4; e++) o[mi][ni][e] = 0.f;
    float mr[2][2], lr[2][2];
#pragma unroll
    for (int mi = 0; mi < 2; mi++) {
        mr[mi][0] = mr[mi][1] = -3.4e38f;
        lr[mi][0] = lr[mi][1] = 0.f;
    }

    auto loadKV = [&](int buf, int j0) {
#pragma unroll
        for (int i = 0; i < 4; i++) {
            int idx = tid + i * 128;            // 0..511
            int r = idx >> 3, c = (idx & 7) * 8;
            cp16(&Ks[buf * 64 * 72 + r * 72 + c], &Kp[(long)(j0 + r) * C3 + c]);
            cp16(&Vs[buf * 64 * 72 + r * 72 + c], &Vtp[(long)r * NSEQ + j0 + c]);
        }
        if (tid < 16) cp16(&Ms[buf * 64 + tid * 4], &maskf[j0 + tid * 4]);
    };

    loadKV(0, 0);
    asm volatile("cp.async.commit_group;");

    const int NJ = NSEQ / 64;   // 49
    unsigned* pw = (unsigned*)(Ps + wid * 32 * 72);    // word stride 36
    unsigned pwb = s2u(Ps) + wid * 32 * 72 * 2;        // byte base of warp P tile

    for (int j = 0; j < NJ; j++) {
        int cur = j & 1;
        asm volatile("cp.async.wait_group 0;");
        __syncthreads();
        if (j + 1 < NJ) {
            loadKV(cur ^ 1, (j + 1) * 64);
            asm volatile("cp.async.commit_group;");
        }

        unsigned ksb = s2u(Ks + cur * 64 * 72);
        unsigned vsb = s2u(Vs + cur * 64 * 72);
        const float* ms = Ms + cur * 64;

#pragma unroll
        for (int mi = 0; mi < 2; mi++) {
            // S = Q @ K^T for this row fragment (K frags via ldmatrix.x4 pairs)
            float s[8][4];
#pragma unroll
            for (int ni = 0; ni < 8; ni++)
                s[ni][0] = s[ni][1] = s[ni][2] = s[ni][3] = 0.f;
#pragma unroll
            for (int kb = 0; kb < 4; kb++) {
#pragma unroll
                for (int np = 0; np < 8; np += 2) {
                    unsigned b00, b01, b10, b11;
                    ldsm4(b00, b01, b10, b11,
                          ksb + (unsigned)(((np * 8 + rowB) * 36 + kb * 8 + hiB * 4) * 4));
                    mma_bf16(s[np],     qf[kb][mi], b00, b01);
                    mma_bf16(s[np + 1], qf[kb][mi], b10, b11);
                }
            }

            // scale + mask + row max
            float rm0 = -3.4e38f, rm1 = -3.4e38f;
#pragma unroll
            for (int ni = 0; ni < 8; ni++) {
                int c0 = ni * 8 + 2 * t;
                float a0 = ms[c0], a1 = ms[c0 + 1];
                s[ni][0] = s[ni][0] * 0.125f + a0;
                s[ni][1] = s[ni][1] * 0.125f + a1;
                s[ni][2] = s[ni][2] * 0.125f + a0;
                s[ni][3] = s[ni][3] * 0.125f + a1;
                rm0 = fmaxf(rm0, fmaxf(s[ni][0], s[ni][1]));
                rm1 = fmaxf(rm1, fmaxf(s[ni][2], s[ni][3]));
            }
            rm0 = fmaxf(rm0, __shfl_xor_sync(0xffffffffu, rm0, 1));
            rm0 = fmaxf(rm0, __shfl_xor_sync(0xffffffffu, rm0, 2));
            rm1 = fmaxf(rm1, __shfl_xor_sync(0xffffffffu, rm1, 1));
            rm1 = fmaxf(rm1, __shfl_xor_sync(0xffffffffu, rm1, 2));
            float mn0 = fmaxf(mr[mi][0], rm0), mn1 = fmaxf(mr[mi][1], rm1);
            float f0 = __expf(mr[mi][0] - mn0), f1 = __expf(mr[mi][1] - mn1);
            mr[mi][0] = mn0; mr[mi][1] = mn1;

            float rs0 = 0.f, rs1 = 0.f;
#pragma unroll
            for (int ni = 0; ni < 8; ni++) {
                float p00 = __expf(s[ni][0] - mn0), p01 = __expf(s[ni][1] - mn0);
                float p10 = __expf(s[ni][2] - mn1), p11 = __expf(s[ni][3] - mn1);
                rs0 += p00 + p01; rs1 += p10 + p11;
                pw[(mi * 16 + g) * 36 + ni * 4 + t]     = packbf(p00, p01);
                pw[(mi * 16 + g + 8) * 36 + ni * 4 + t] = packbf(p10, p11);
            }
            rs0 += __shfl_xor_sync(0xffffffffu, rs0, 1);
            rs0 += __shfl_xor_sync(0xffffffffu, rs0, 2);
            rs1 += __shfl_xor_sync(0xffffffffu, rs1, 1);
            rs1 += __shfl_xor_sync(0xffffffffu, rs1, 2);
            lr[mi][0] = lr[mi][0] * f0 + rs0;
            lr[mi][1] = lr[mi][1] * f1 + rs1;

#pragma unroll
            for (int ni = 0; ni < 8; ni++) {
                o[mi][ni][0] *= f0; o[mi][ni][1] *= f0;
                o[mi][ni][2] *= f1; o[mi][ni][3] *= f1;
            }
            __syncwarp();

            // O += P @ V  (P a-frags + V b-frags via ldmatrix)
#pragma unroll
            for (int kb = 0; kb < 4; kb++) {
                unsigned paf[4];
                ldsm4(paf[0], paf[1], paf[2], paf[3],
                      pwb + (unsigned)(((mi * 16 + rowA) * 36 + kb * 8 + hiA * 4) * 4));
#pragma unroll
                for (int np = 0; np < 8; np += 2) {
                    unsigned b00, b01, b10, b11;
                    ldsm4(b00, b01, b10, b11,
                          vsb + (unsigned)(((np * 8 + rowB) * 36 + kb * 8 + hiB * 4) * 4));
                    mma_bf16(o[mi][np],     paf, b00, b01);
                    mma_bf16(o[mi][np + 1], paf, b10, b11);
                }
            }
        }
        // no bottom sync: next top barrier protects buffers
    }

    // normalize + store (bf16, feeds proj GEMM)
#pragma unroll
    for (int mi = 0; mi < 2; mi++) {
        float inv0 = 1.f / lr[mi][0], inv1 = 1.f / lr[mi][1];
        int r0 = m0 + wid * 32 + mi * 16 + g, r1 = r0 + 8;
#pragma unroll
        for (int ni = 0; ni < 8; ni++) {
            int col = h * HD + ni * 8 + 2 * t;
            if (r0 < NSEQ)
                *(unsigned*)&attout[(long)r0 * CD + col] =
                    packbf(o[mi][ni][0] * inv0, o[mi][ni][1] * inv0);
            if (r1 < NSEQ)
                *(unsigned*)&attout[(long)r1 * CD + col] =
                    packbf(o[mi][ni][2] * inv1, o[mi][ni][3] * inv1);
        }
    }
}

// ---------------- bf16 mma GEMM with fused epilogues ---------------------------
// C[M,N] = A[M,K] @ B[N,K]^T. BK=32 (two k16 steps). Warp tile 64x32, ldmatrix.
// BM=128: 8 warps (2x4), 256 thr, 2 blk/SM.  BM=64: 4 warps (1x4), 128 thr, 4 blk/SM.
enum { EPI_QKV = 2, EPI_GELU = 4, EPI_RES = 5 };

template<int EPI, int BM>
__global__ void __launch_bounds__(BM * 2, 256 / (BM / 64) / 64) mmgemm(
    const __nv_bfloat16* __restrict__ A, const __nv_bfloat16* __restrict__ B,
    void* __restrict__ Cout,
    int M, int N, int K, int lda, int ldb, int ldc,
    const float* __restrict__ bias, const float* __restrict__ bias2,
    const float* __restrict__ res, const float* __restrict__ gamma,
    __nv_bfloat16* __restrict__ vt)
{
    constexpr int THREADS = BM * 2;
    constexpr int WROWS = BM / 64;
    constexpr int MI = 4, NI = 4;
    constexpr int LDE = 40;            // bf16 elems per smem row (32 + 8 pad) = 80B
    constexpr int LDW = 20;            // words per row

    __shared__ __align__(16) __nv_bfloat16 As[2][BM * LDE];
    __shared__ __align__(16) __nv_bfloat16 Bs[2][128 * LDE];

    int tid  = threadIdx.x;
    int wid  = tid >> 5;
    int lane = tid & 31;
    int g = lane >> 2, t = lane & 3;
    int rowA = lane & 15, hiA = lane >> 4;
    int rowB = (lane & 7) + (lane >> 4) * 8;
    int hiB  = (lane >> 3) & 1;
    int wm = (wid % WROWS) * 64;
    int wn = (wid / WROWS) * 32;
    int m0 = blockIdx.x * BM, n0 = blockIdx.y * 128;

    auto ldA = [&](int buf, int k0) {
#pragma unroll
        for (int i = 0; i < 2; i++) {
            int idx = tid + i * THREADS;       // BM*4 chunks
            int r = idx >> 2, c = (idx & 3) * 8;
            int row = m0 + r; if (row >= M) row = M - 1;
            cp16(&As[buf][r * LDE + c], &A[(long)row * lda + k0 + c]);
        }
    };
    auto ldB = [&](int buf, int k0) {
#pragma unroll
        for (int i = 0; i < 256 / BM; i++) {
            int idx = tid + i * THREADS;       // 512 chunks
            int r = idx >> 2, c = (idx & 3) * 8;
            int row = n0 + r; if (row >= N) row = N - 1;
            cp16(&Bs[buf][r * LDE + c], &B[(long)row * ldb + k0 + c]);
        }
    };

    float acc[MI][NI][4];
#pragma unroll
    for (int mi = 0; mi < MI; mi++)
#pragma unroll
        for (int ni = 0; ni < NI; ni++)
#pragma unroll
            for (int e = 0; e < 4; e++) acc[mi][ni][e] = 0.f;

    int KT = K / 32;
    ldA(0, 0); ldB(0, 0);
    asm volatile("cp.async.commit_group;");

    for (int kt = 0; kt < KT; kt++) {
        int cur = kt & 1;
        asm volatile("cp.async.wait_group 0;");
        __syncthreads();
        if (kt + 1 < KT) {
            ldA(cur ^ 1, (kt + 1) * 32);
            ldB(cur ^ 1, (kt + 1) * 32);
            asm volatile("cp.async.commit_group;");
        }

        unsigned asb = s2u(As[cur]);
        unsigned bsb = s2u(Bs[cur]);
#pragma unroll
        for (int kb = 0; kb < 16; kb += 8) {    // two k16 steps (word offset 0, 8)
            unsigned af[MI][4], bf[NI][2];
#pragma unroll
            for (int mi = 0; mi < MI; mi++)
                ldsm4(af[mi][0], af[mi][1], af[mi][2], af[mi][3],
                      asb + (unsigned)(((wm + mi * 16 + rowA) * LDW + kb + hiA * 4) * 4));
#pragma unroll
            for (int np = 0; np < NI; np += 2)
                ldsm4(bf[np][0], bf[np][1], bf[np + 1][0], bf[np + 1][1],
                      bsb + (unsigned)(((wn + np * 8 + rowB) * LDW + kb + hiB * 4) * 4));
#pragma unroll
            for (int mi = 0; mi < MI; mi++)
#pragma unroll
                for (int ni = 0; ni < NI; ni++)
                    mma_bf16(acc[mi][ni], af[mi], bf[ni][0], bf[ni][1]);
        }
        // no bottom sync: next top barrier protects buffers
    }

#pragma unroll
    for (int mi = 0; mi < MI; mi++) {
#pragma unroll
        for (int ni = 0; ni < NI; ni++) {
            int col = n0 + wn + ni * 8 + 2 * t;
            if (col >= N) continue;
#pragma unroll
            for (int half = 0; half < 2; half++) {
                int row = m0 + wm + mi * 16 + g + half * 8;
                if (row >= M) continue;
                float v0 = acc[mi][ni][half * 2 + 0];
                float v1 = acc[mi][ni][half * 2 + 1];
                if (EPI == EPI_QKV) {
                    float b0 = (col < CD) ? bias[col]
                             : (col < 2 * CD) ? 0.f : bias2[col - 2 * CD];
                    int c1 = col + 1;
                    float b1 = (c1 < CD) ? bias[c1]
                             : (c1 < 2 * CD) ? 0.f : bias2[c1 - 2 * CD];
                    v0 += b0; v1 += b1;
                    if (col < 2 * CD) {
                        __nv_bfloat16* q = (__nv_bfloat16*)Cout;
                        *(unsigned*)&q[(long)row * ldc + col] = packbf(v0, v1);
                    } else {
                        int d = col - 2 * CD;
                        vt[(long)d * NSEQ + row]       = __float2bfloat16_rn(v0);
                        vt[(long)(d + 1) * NSEQ + row] = __float2bfloat16_rn(v1);
                    }
                } else if (EPI == EPI_GELU) {
                    v0 += bias[col]; v1 += bias[col + 1];
                    v0 = 0.5f * v0 * (1.f + erff(v0 * 0.70710678118654752f));
                    v1 = 0.5f * v1 * (1.f + erff(v1 * 0.70710678118654752f));
                    __nv_bfloat16* q = (__nv_bfloat16*)Cout;
                    *(unsigned*)&q[(long)row * ldc + col] = packbf(v0, v1);
                } else {  // EPI_RES
                    const float* rr = &res[(long)row * ldc + col];
                    float* q = (float*)Cout;
                    float2 ov;
                    ov.x = rr[0] + gamma[col]     * (v0 + bias[col]);
                    ov.y = rr[1] + gamma[col + 1] * (v1 + bias[col + 1]);
                    *(float2*)&q[(long)row * ldc + col] = ov;
                }
            }
        }
    }
}

// ---------------- launch -------------------------------------------------------
extern "C" void kernel_launch(void* const* d_in, const int* in_sizes, int n_in,
                              void* d_out, int out_size)
{
    const float* x      = (const float*)d_in[0];
    const void*  mask   = d_in[1];
    const float* qkv_w  = (const float*)d_in[2];
    const float* q_bias = (const float*)d_in[3];
    const float* v_bias = (const float*)d_in[4];
    const float* proj_w = (const float*)d_in[5];
    const float* proj_b = (const float*)d_in[6];
    const float* n1s    = (const float*)d_in[7];
    const float* n1b    = (const float*)d_in[8];
    const float* n2s    = (const float*)d_in[9];
    const float* n2b    = (const float*)d_in[10];
    const float* w1     = (const float*)d_in[11];
    const float* b1     = (const float*)d_in[12];
    const float* w2     = (const float*)d_in[13];
    const float* b2     = (const float*)d_in[14];
    const float* g1     = (const float*)d_in[15];
    const float* g2     = (const float*)d_in[16];
    float* out = (float*)d_out;

    __nv_bfloat16 *xn, *qkv, *vt, *attout, *h0, *h1, *w;
    float *x2, *maskf;
    cudaGetSymbolAddress((void**)&xn,     g_xn);
    cudaGetSymbolAddress((void**)&qkv,    g_qkv);
    cudaGetSymbolAddress((void**)&vt,     g_vt);
    cudaGetSymbolAddress((void**)&attout, g_attout);
    cudaGetSymbolAddress((void**)&h0,     g_h0);
    cudaGetSymbolAddress((void**)&h1,     g_h1);
    cudaGetSymbolAddress((void**)&w,      g_w);
    cudaGetSymbolAddress((void**)&x2,     g_x2);
    cudaGetSymbolAddress((void**)&maskf,  g_maskf);

    static int smem_set = 0;
    if (!smem_set) {
        cudaFuncSetAttribute(flash_kernel,
                             cudaFuncAttributeMaxDynamicSharedMemorySize, FLASH_SMEM);
        smem_set = 1;
    }

    // 0. convert weights to bf16
    round_copy_kernel<<<(C3 * CD / 4 + 255) / 256, 256>>>(qkv_w, (unsigned*)(w + WQKV_OFF), C3 * CD / 4);
    round_copy_kernel<<<(CD * CD / 4 + 255) / 256, 256>>>(proj_w, (unsigned*)(w + WPROJ_OFF), CD * CD / 4);
    round_copy_kernel<<<(HID * CD / 4 + 255) / 256, 256>>>(w1, (unsigned*)(w + W1_OFF), HID * CD / 4);
    round_copy_kernel<<<(CD * HID / 4 + 255) / 256, 256>>>(w2, (unsigned*)(w + W2_OFF), CD * HID / 4);

    // 1. LN1 + mask prep
    ln_kernel<<<NSEQ, 256>>>(x, n1s, n1b, xn);
    mask_detect_kernel<<<1, 256>>>((const unsigned int*)mask);
    mask_prep_kernel<<<(NSEQ + 255) / 256, 256>>>(mask, maskf);

    // 2. QKV projection (Q,K -> qkv buffer; V -> vt transposed)
    mmgemm<EPI_QKV, 128><<<dim3(25, C3 / 128, 1), 256>>>(
        xn, w + WQKV_OFF, qkv, NSEQ, C3, CD, CD, CD, C3,
        q_bias, v_bias, nullptr, nullptr, vt);

    // 3-5. flash attention
    flash_kernel<<<dim3(25, NH), 128, FLASH_SMEM>>>(qkv, vt, maskf, attout);

    // 6. proj + residual (BM=64, full-chip single wave)
    mmgemm<EPI_RES, 64><<<dim3(49, CD / 128, 1), 128>>>(
        attout, w + WPROJ_OFF, x2, NSEQ, CD, CD, CD, CD, CD,
        proj_b, nullptr, x, g1, nullptr);

    // 7. LN2
    ln_kernel<<<NSEQ, 256>>>(x2, n2s, n2b, h0);

    // 8. MLP1 + exact GELU
    mmgemm<EPI_GELU, 128><<<dim3(25, HID / 128, 1), 256>>>(
        h0, w + W1_OFF, h1, NSEQ, HID, CD, CD, CD, HID,
        b1, nullptr, nullptr, nullptr, nullptr);

    // 9. MLP2 + final residual (BM=64)
    mmgemm<EPI_RES, 64><<<dim3(49, CD / 128, 1), 128>>>(
        h1, w + W2_OFF, out, NSEQ, CD, HID, HID, HID, CD,
        b2, nullptr, x2, g2, nullptr);
}

// round 11
// speedup vs baseline: 6.0771x; 1.0716x over previous
#include <cuda_runtime.h>
#include <cuda_bf16.h>
#include <math.h>

#define NSEQ 3136
#define CD   768
#define NH   12
#define HD   64
#define HID  3072
#define C3   2304

// rounded-weight scratch offsets (bf16 elements)
#define WQKV_OFF 0
#define WPROJ_OFF 1769472               // 2304*768
#define W1_OFF   (WPROJ_OFF + 589824)   // +768*768
#define W2_OFF   (W1_OFF + 2359296)     // +3072*768
#define W_TOTAL  (W2_OFF + 2359296)

// float4-chunk counts per region
#define NC_QKV  (C3 * CD / 4)           // 442368
#define NC_PROJ (CD * CD / 4)           // 147456
#define NC_W1   (HID * CD / 4)          // 589824
#define NC_W2   (CD * HID / 4)          // 589824
#define NC_ALL  (NC_QKV + NC_PROJ + NC_W1 + NC_W2)

// ---------------- scratch (static device globals; no allocation) -------------
__device__ __nv_bfloat16 g_xn[NSEQ * CD];
__device__ __nv_bfloat16 g_qkv[NSEQ * C3];
__device__ __nv_bfloat16 g_vt[CD * NSEQ];        // V transposed: [dim][token]
__device__ __nv_bfloat16 g_attout[NSEQ * CD];
__device__ __nv_bfloat16 g_h0[NSEQ * CD];
__device__ __nv_bfloat16 g_h1[NSEQ * HID];
__device__ __nv_bfloat16 g_w[W_TOTAL];
__device__ float g_x2[NSEQ * CD];
__device__ float g_maskf[NSEQ];

// ---------------- helpers ----------------------------------------------------
__device__ __forceinline__ float warpSum(float v) {
#pragma unroll
    for (int o = 16; o; o >>= 1) v += __shfl_xor_sync(0xffffffffu, v, o);
    return v;
}
__device__ __forceinline__ unsigned packbf(float lo, float hi) {
    unsigned r;
    asm("cvt.rn.bf16x2.f32 %0, %1, %2;" : "=r"(r) : "f"(hi), "f"(lo));
    return r;
}
__device__ __forceinline__ void cp16(void* s, const void* g) {
    unsigned a = (unsigned)__cvta_generic_to_shared(s);
    asm volatile("cp.async.ca.shared.global [%0], [%1], 16;" :: "r"(a), "l"(g));
}
__device__ __forceinline__ unsigned s2u(const void* p) {
    return (unsigned)__cvta_generic_to_shared(p);
}
__device__ __forceinline__ void ldsm4(unsigned& r0, unsigned& r1, unsigned& r2, unsigned& r3,
                                      unsigned addr) {
    asm volatile("ldmatrix.sync.aligned.m8n8.x4.shared.b16 {%0,%1,%2,%3}, [%4];"
        : "=r"(r0), "=r"(r1), "=r"(r2), "=r"(r3) : "r"(addr));
}
__device__ __forceinline__ void mma_bf16(float* c, const unsigned* a, unsigned b0, unsigned b1) {
    asm volatile(
        "mma.sync.aligned.m16n8k16.row.col.f32.bf16.bf16.f32 "
        "{%0,%1,%2,%3}, {%4,%5,%6,%7}, {%8,%9}, {%0,%1,%2,%3};"
        : "+f"(c[0]), "+f"(c[1]), "+f"(c[2]), "+f"(c[3])
        : "r"(a[0]), "r"(a[1]), "r"(a[2]), "r"(a[3]), "r"(b0), "r"(b1));
}

// ---------------- fused weight conversion (ONE launch) --------------------------
__global__ void __launch_bounds__(256) round_copy_all_kernel(
    const float* __restrict__ qkv_w, const float* __restrict__ proj_w,
    const float* __restrict__ w1, const float* __restrict__ w2,
    unsigned* __restrict__ out)
{
    int i = blockIdx.x * 256 + threadIdx.x;
    if (i >= NC_ALL) return;
    const float* src;
    int off;
    if (i < NC_QKV)                       { src = qkv_w;  off = i; }
    else if (i < NC_QKV + NC_PROJ)        { src = proj_w; off = i - NC_QKV; }
    else if (i < NC_QKV + NC_PROJ + NC_W1){ src = w1;     off = i - NC_QKV - NC_PROJ; }
    else                                  { src = w2;     off = i - NC_QKV - NC_PROJ - NC_W1; }
    float4 v = ((const float4*)src)[off];
    uint2 o;
    o.x = packbf(v.x, v.y);
    o.y = packbf(v.z, v.w);
    ((uint2*)out)[i] = o;
}

// ---------------- fused mask detect + prep (per-block detection) ----------------
__global__ void __launch_bounds__(256) mask_fused_kernel(
    const void* __restrict__ mask, float* __restrict__ mf)
{
    __shared__ int flag;
    if (threadIdx.x == 0) flag = 0;
    __syncthreads();
    const unsigned* m32 = (const unsigned*)mask;
    for (int i = threadIdx.x; i < NSEQ / 4; i += 256)
        if (m32[i] > 1u) flag = 1;
    __syncthreads();
    int byteMode = flag;
    int i = blockIdx.x * 256 + threadIdx.x;
    if (i < NSEQ) {
        bool m = byteMode ? (((const unsigned char*)mask)[i] != 0)
                          : (((const int*)mask)[i] != 0);
        mf[i] = m ? -1e30f : 0.f;
    }
}

// ---------------- layernorm (bf16 output) --------------------------------------
__global__ void __launch_bounds__(256) ln_kernel(
    const float* __restrict__ x, const float* __restrict__ sc,
    const float* __restrict__ bi, __nv_bfloat16* __restrict__ y)
{
    int row = blockIdx.x;
    const float* xr = x + (long)row * CD;
    __nv_bfloat16* yr = y + (long)row * CD;
    int t = threadIdx.x;
    float v[3];
    float s = 0.f, s2 = 0.f;
#pragma unroll
    for (int i = 0; i < 3; i++) {
        float a = xr[t + i * 256];
        v[i] = a; s += a; s2 += a * a;
    }
    __shared__ float sh[32], sh2[32];
    float ws = warpSum(s), ws2 = warpSum(s2);
    int lane = t & 31, wid = t >> 5;
    if (lane == 0) { sh[wid] = ws; sh2[wid] = ws2; }
    __syncthreads();
    if (wid == 0) {
        float a = lane < 8 ? sh[lane] : 0.f;
        float b = lane < 8 ? sh2[lane] : 0.f;
        a = warpSum(a); b = warpSum(b);
        if (lane == 0) { sh[0] = a; sh2[0] = b; }
    }
    __syncthreads();
    float mu  = sh[0] * (1.f / CD);
    float var = sh2[0] * (1.f / CD) - mu * mu;
    float inv = rsqrtf(var + 1e-5f);
#pragma unroll
    for (int i = 0; i < 3; i++) {
        int c = t + i * 256;
        yr[c] = __float2bfloat16_rn((v[i] - mu) * inv * sc[c] + bi[c]);
    }
}

// ---------------- flash attention (bf16 + ldmatrix) ----------------------------
// One block = one (q-tile of 128, head). 4 warps, warp owns 32 q-rows (mi=2).
// K tiles [key][dim], V pre-transposed [dim][token]. All smem fragment loads
// via ldmatrix. 3 blocks/SM -> 300 blocks in ONE wave.
#define FLASH_SMEM (3 * 64 * 72 * 2 * 2 + 2 * 64 * 4)   // K,V,P bf16 + mask f32

__global__ void __launch_bounds__(128, 3) flash_kernel(
    const __nv_bfloat16* __restrict__ qkv, const __nv_bfloat16* __restrict__ vt,
    const float* __restrict__ maskf, __nv_bfloat16* __restrict__ attout)
{
    extern __shared__ __align__(16) char smc[];
    __nv_bfloat16* Ks = (__nv_bfloat16*)smc;        // 2 * 64*72
    __nv_bfloat16* Vs = Ks + 2 * 64 * 72;           // 2 * 64*72 (rows = dims)
    __nv_bfloat16* Ps = Vs + 2 * 64 * 72;           // 4 warps * 32*72
    float* Ms = (float*)(Ps + 4 * 32 * 72);         // 2 * 64

    int h  = blockIdx.y;
    int m0 = blockIdx.x * 128;
    int tid = threadIdx.x, wid = tid >> 5, lane = tid & 31;
    int g = lane >> 2, t = lane & 3;
    int rowA = lane & 15, hiA = lane >> 4;                 // A-pattern ldmatrix
    int rowB = (lane & 7) + (lane >> 4) * 8;               // B-pattern ldmatrix
    int hiB  = (lane >> 3) & 1;

    const __nv_bfloat16* Qp  = qkv + h * HD;
    const __nv_bfloat16* Kp  = qkv + CD + h * HD;
    const __nv_bfloat16* Vtp = vt + (long)h * HD * NSEQ;

    // Q fragments (bf16 pairs, unscaled; scores scaled by 0.125 in fp32)
    unsigned qf[4][2][4];
#pragma unroll
    for (int mi = 0; mi < 2; mi++) {
        int r0 = m0 + wid * 32 + mi * 16 + g; if (r0 >= NSEQ) r0 = NSEQ - 1;
        int r1 = r0 + 8;                      if (r1 >= NSEQ) r1 = NSEQ - 1;
        const __nv_bfloat16* q0 = Qp + (long)r0 * C3;
        const __nv_bfloat16* q1 = Qp + (long)r1 * C3;
#pragma unroll
        for (int kb = 0; kb < 4; kb++) {
            qf[kb][mi][0] = *(const unsigned*)&q0[kb * 16 + 2 * t];
            qf[kb][mi][1] = *(const unsigned*)&q1[kb * 16 + 2 * t];
            qf[kb][mi][2] = *(const unsigned*)&q0[kb * 16 + 8 + 2 * t];
            qf[kb][mi][3] = *(const unsigned*)&q1[kb * 16 + 8 + 2 * t];
        }
    }

    float o[2][8][4];
#pragma unroll
    for (int mi = 0; mi < 2; mi++)
#pragma unroll
        for (int ni = 0; ni < 8; ni++)
#pragma unroll
            for (int e = 0; e < 4; e++) o[mi][ni][e] = 0.f;
    float mr[2][2], lr[2][2];
#pragma unroll
    for (int mi = 0; mi < 2; mi++) {
        mr[mi][0] = mr[mi][1] = -3.4e38f;
        lr[mi][0] = lr[mi][1] = 0.f;
    }

    auto loadKV = [&](int buf, int j0) {
#pragma unroll
        for (int i = 0; i < 4; i++) {
            int idx = tid + i * 128;            // 0..511
            int r = idx >> 3, c = (idx & 7) * 8;
            cp16(&Ks[buf * 64 * 72 + r * 72 + c], &Kp[(long)(j0 + r) * C3 + c]);
            cp16(&Vs[buf * 64 * 72 + r * 72 + c], &Vtp[(long)r * NSEQ + j0 + c]);
        }
        if (tid < 16) cp16(&Ms[buf * 64 + tid * 4], &maskf[j0 + tid * 4]);
    };

    loadKV(0, 0);
    asm volatile("cp.async.commit_group;");

    const int NJ = NSEQ / 64;   // 49
    unsigned* pw = (unsigned*)(Ps + wid * 32 * 72);    // word stride 36
    unsigned pwb = s2u(Ps) + wid * 32 * 72 * 2;        // byte base of warp P tile

    for (int j = 0; j < NJ; j++) {
        int cur = j & 1;
        asm volatile("cp.async.wait_group 0;");
        __syncthreads();
        if (j + 1 < NJ) {
            loadKV(cur ^ 1, (j + 1) * 64);
            asm volatile("cp.async.commit_group;");
        }

        unsigned ksb = s2u(Ks + cur * 64 * 72);
        unsigned vsb = s2u(Vs + cur * 64 * 72);
        const float* ms = Ms + cur * 64;

#pragma unroll
        for (int mi = 0; mi < 2; mi++) {
            // S = Q @ K^T for this row fragment (K frags via ldmatrix.x4 pairs)
            float s[8][4];
#pragma unroll
            for (int ni = 0; ni < 8; ni++)
                s[ni][0] = s[ni][1] = s[ni][2] = s[ni][3] = 0.f;
#pragma unroll
            for (int kb = 0; kb < 4; kb++) {
#pragma unroll
                for (int np = 0; np < 8; np += 2) {
                    unsigned b00, b01, b10, b11;
                    ldsm4(b00, b01, b10, b11,
                          ksb + (unsigned)(((np * 8 + rowB) * 36 + kb * 8 + hiB * 4) * 4));
                    mma_bf16(s[np],     qf[kb][mi], b00, b01);
                    mma_bf16(s[np + 1], qf[kb][mi], b10, b11);
                }
            }

            // scale + mask + row max
            float rm0 = -3.4e38f, rm1 = -3.4e38f;
#pragma unroll
            for (int ni = 0; ni < 8; ni++) {
                int c0 = ni * 8 + 2 * t;
                float a0 = ms[c0], a1 = ms[c0 + 1];
                s[ni][0] = s[ni][0] * 0.125f + a0;
                s[ni][1] = s[ni][1] * 0.125f + a1;
                s[ni][2] = s[ni][2] * 0.125f + a0;
                s[ni][3] = s[ni][3] * 0.125f + a1;
                rm0 = fmaxf(rm0, fmaxf(s[ni][0], s[ni][1]));
                rm1 = fmaxf(rm1, fmaxf(s[ni][2], s[ni][3]));
            }
            rm0 = fmaxf(rm0, __shfl_xor_sync(0xffffffffu, rm0, 1));
            rm0 = fmaxf(rm0, __shfl_xor_sync(0xffffffffu, rm0, 2));
            rm1 = fmaxf(rm1, __shfl_xor_sync(0xffffffffu, rm1, 1));
            rm1 = fmaxf(rm1, __shfl_xor_sync(0xffffffffu, rm1, 2));
            float mn0 = fmaxf(mr[mi][0], rm0), mn1 = fmaxf(mr[mi][1], rm1);
            float f0 = __expf(mr[mi][0] - mn0), f1 = __expf(mr[mi][1] - mn1);
            mr[mi][0] = mn0; mr[mi][1] = mn1;

            float rs0 = 0.f, rs1 = 0.f;
#pragma unroll
            for (int ni = 0; ni < 8; ni++) {
                float p00 = __expf(s[ni][0] - mn0), p01 = __expf(s[ni][1] - mn0);
                float p10 = __expf(s[ni][2] - mn1), p11 = __expf(s[ni][3] - mn1);
                rs0 += p00 + p01; rs1 += p10 + p11;
                pw[(mi * 16 + g) * 36 + ni * 4 + t]     = packbf(p00, p01);
                pw[(mi * 16 + g + 8) * 36 + ni * 4 + t] = packbf(p10, p11);
            }
            rs0 += __shfl_xor_sync(0xffffffffu, rs0, 1);
            rs0 += __shfl_xor_sync(0xffffffffu, rs0, 2);
            rs1 += __shfl_xor_sync(0xffffffffu, rs1, 1);
            rs1 += __shfl_xor_sync(0xffffffffu, rs1, 2);
            lr[mi][0] = lr[mi][0] * f0 + rs0;
            lr[mi][1] = lr[mi][1] * f1 + rs1;

#pragma unroll
            for (int ni = 0; ni < 8; ni++) {
                o[mi][ni][0] *= f0; o[mi][ni][1] *= f0;
                o[mi][ni][2] *= f1; o[mi][ni][3] *= f1;
            }
            __syncwarp();

            // O += P @ V  (P a-frags + V b-frags via ldmatrix)
#pragma unroll
            for (int kb = 0; kb < 4; kb++) {
                unsigned paf[4];
                ldsm4(paf[0], paf[1], paf[2], paf[3],
                      pwb + (unsigned)(((mi * 16 + rowA) * 36 + kb * 8 + hiA * 4) * 4));
#pragma unroll
                for (int np = 0; np < 8; np += 2) {
                    unsigned b00, b01, b10, b11;
                    ldsm4(b00, b01, b10, b11,
                          vsb + (unsigned)(((np * 8 + rowB) * 36 + kb * 8 + hiB * 4) * 4));
                    mma_bf16(o[mi][np],     paf, b00, b01);
                    mma_bf16(o[mi][np + 1], paf, b10, b11);
                }
            }
        }
        // no bottom sync: next top barrier protects buffers
    }

    // normalize + store (bf16, feeds proj GEMM)
#pragma unroll
    for (int mi = 0; mi < 2; mi++) {
        float inv0 = 1.f / lr[mi][0], inv1 = 1.f / lr[mi][1];
        int r0 = m0 + wid * 32 + mi * 16 + g, r1 = r0 + 8;
#pragma unroll
        for (int ni = 0; ni < 8; ni++) {
            int col = h * HD + ni * 8 + 2 * t;
            if (r0 < NSEQ)
                *(unsigned*)&attout[(long)r0 * CD + col] =
                    packbf(o[mi][ni][0] * inv0, o[mi][ni][1] * inv0);
            if (r1 < NSEQ)
                *(unsigned*)&attout[(long)r1 * CD + col] =
                    packbf(o[mi][ni][2] * inv1, o[mi][ni][3] * inv1);
        }
    }
}

// ---------------- bf16 mma GEMM with fused epilogues ---------------------------
// C[M,N] = A[M,K] @ B[N,K]^T. BK=32 (two k16 steps). Warp tile 64x32, ldmatrix.
// BM=64 everywhere: 4 warps (1x4), 128 thr, 4 blk/SM -> 592 concurrent blocks.
// Tile counts: QKV 882 (1.49 rounds), proj/MLP2 294 (1), MLP1 1176 (1.99).
enum { EPI_QKV = 2, EPI_GELU = 4, EPI_RES = 5 };

template<int EPI, int BM>
__global__ void __launch_bounds__(BM * 2, 256 / (BM / 64) / 64) mmgemm(
    const __nv_bfloat16* __restrict__ A, const __nv_bfloat16* __restrict__ B,
    void* __restrict__ Cout,
    int M, int N, int K, int lda, int ldb, int ldc,
    const float* __restrict__ bias, const float* __restrict__ bias2,
    const float* __restrict__ res, const float* __restrict__ gamma,
    __nv_bfloat16* __restrict__ vt)
{
    constexpr int THREADS = BM * 2;
    constexpr int WROWS = BM / 64;
    constexpr int MI = 4, NI = 4;
    constexpr int LDE = 40;            // bf16 elems per smem row (32 + 8 pad) = 80B
    constexpr int LDW = 20;            // words per row

    __shared__ __align__(16) __nv_bfloat16 As[2][BM * LDE];
    __shared__ __align__(16) __nv_bfloat16 Bs[2][128 * LDE];

    int tid  = threadIdx.x;
    int wid  = tid >> 5;
    int lane = tid & 31;
    int g = lane >> 2, t = lane & 3;
    int rowA = lane & 15, hiA = lane >> 4;
    int rowB = (lane & 7) + (lane >> 4) * 8;
    int hiB  = (lane >> 3) & 1;
    int wm = (wid % WROWS) * 64;
    int wn = (wid / WROWS) * 32;
    int m0 = blockIdx.x * BM, n0 = blockIdx.y * 128;

    auto ldA = [&](int buf, int k0) {
#pragma unroll
        for (int i = 0; i < 2; i++) {
            int idx = tid + i * THREADS;       // BM*4 chunks
            int r = idx >> 2, c = (idx & 3) * 8;
            int row = m0 + r; if (row >= M) row = M - 1;
            cp16(&As[buf][r * LDE + c], &A[(long)row * lda + k0 + c]);
        }
    };
    auto ldB = [&](int buf, int k0) {
#pragma unroll
        for (int i = 0; i < 256 / BM; i++) {
            int idx = tid + i * THREADS;       // 512 chunks
            int r = idx >> 2, c = (idx & 3) * 8;
            int row = n0 + r; if (row >= N) row = N - 1;
            cp16(&Bs[buf][r * LDE + c], &B[(long)row * ldb + k0 + c]);
        }
    };

    float acc[MI][NI][4];
#pragma unroll
    for (int mi = 0; mi < MI; mi++)
#pragma unroll
        for (int ni = 0; ni < NI; ni++)
#pragma unroll
            for (int e = 0; e < 4; e++) acc[mi][ni][e] = 0.f;

    int KT = K / 32;
    ldA(0, 0); ldB(0, 0);
    asm volatile("cp.async.commit_group;");

    for (int kt = 0; kt < KT; kt++) {
        int cur = kt & 1;
        asm volatile("cp.async.wait_group 0;");
        __syncthreads();
        if (kt + 1 < KT) {
            ldA(cur ^ 1, (kt + 1) * 32);
            ldB(cur ^ 1, (kt + 1) * 32);
            asm volatile("cp.async.commit_group;");
        }

        unsigned asb = s2u(As[cur]);
        unsigned bsb = s2u(Bs[cur]);
#pragma unroll
        for (int kb = 0; kb < 16; kb += 8) {    // two k16 steps (word offset 0, 8)
            unsigned af[MI][4], bf[NI][2];
#pragma unroll
            for (int mi = 0; mi < MI; mi++)
                ldsm4(af[mi][0], af[mi][1], af[mi][2], af[mi][3],
                      asb + (unsigned)(((wm + mi * 16 + rowA) * LDW + kb + hiA * 4) * 4));
#pragma unroll
            for (int np = 0; np < NI; np += 2)
                ldsm4(bf[np][0], bf[np][1], bf[np + 1][0], bf[np + 1][1],
                      bsb + (unsigned)(((wn + np * 8 + rowB) * LDW + kb + hiB * 4) * 4));
#pragma unroll
            for (int mi = 0; mi < MI; mi++)
#pragma unroll
                for (int ni = 0; ni < NI; ni++)
                    mma_bf16(acc[mi][ni], af[mi], bf[ni][0], bf[ni][1]);
        }
        // no bottom sync: next top barrier protects buffers
    }

#pragma unroll
    for (int mi = 0; mi < MI; mi++) {
#pragma unroll
        for (int ni = 0; ni < NI; ni++) {
            int col = n0 + wn + ni * 8 + 2 * t;
            if (col >= N) continue;
#pragma unroll
            for (int half = 0; half < 2; half++) {
                int row = m0 + wm + mi * 16 + g + half * 8;
                if (row >= M) continue;
                float v0 = acc[mi][ni][half * 2 + 0];
                float v1 = acc[mi][ni][half * 2 + 1];
                if (EPI == EPI_QKV) {
                    float b0 = (col < CD) ? bias[col]
                             : (col < 2 * CD) ? 0.f : bias2[col - 2 * CD];
                    int c1 = col + 1;
                    float b1 = (c1 < CD) ? bias[c1]
                             : (c1 < 2 * CD) ? 0.f : bias2[c1 - 2 * CD];
                    v0 += b0; v1 += b1;
                    if (col < 2 * CD) {
                        __nv_bfloat16* q = (__nv_bfloat16*)Cout;
                        *(unsigned*)&q[(long)row * ldc + col] = packbf(v0, v1);
                    } else {
                        int d = col - 2 * CD;
                        vt[(long)d * NSEQ + row]       = __float2bfloat16_rn(v0);
                        vt[(long)(d + 1) * NSEQ + row] = __float2bfloat16_rn(v1);
                    }
                } else if (EPI == EPI_GELU) {
                    v0 += bias[col]; v1 += bias[col + 1];
                    v0 = 0.5f * v0 * (1.f + erff(v0 * 0.70710678118654752f));
                    v1 = 0.5f * v1 * (1.f + erff(v1 * 0.70710678118654752f));
                    __nv_bfloat16* q = (__nv_bfloat16*)Cout;
                    *(unsigned*)&q[(long)row * ldc + col] = packbf(v0, v1);
                } else {  // EPI_RES
                    const float* rr = &res[(long)row * ldc + col];
                    float* q = (float*)Cout;
                    float2 ov;
                    ov.x = rr[0] + gamma[col]     * (v0 + bias[col]);
                    ov.y = rr[1] + gamma[col + 1] * (v1 + bias[col + 1]);
                    *(float2*)&q[(long)row * ldc + col] = ov;
                }
            }
        }
    }
}

// ---------------- launch -------------------------------------------------------
extern "C" void kernel_launch(void* const* d_in, const int* in_sizes, int n_in,
                              void* d_out, int out_size)
{
    const float* x      = (const float*)d_in[0];
    const void*  mask   = d_in[1];
    const float* qkv_w  = (const float*)d_in[2];
    const float* q_bias = (const float*)d_in[3];
    const float* v_bias = (const float*)d_in[4];
    const float* proj_w = (const float*)d_in[5];
    const float* proj_b = (const float*)d_in[6];
    const float* n1s    = (const float*)d_in[7];
    const float* n1b    = (const float*)d_in[8];
    const float* n2s    = (const float*)d_in[9];
    const float* n2b    = (const float*)d_in[10];
    const float* w1     = (const float*)d_in[11];
    const float* b1     = (const float*)d_in[12];
    const float* w2     = (const float*)d_in[13];
    const float* b2     = (const float*)d_in[14];
    const float* g1     = (const float*)d_in[15];
    const float* g2     = (const float*)d_in[16];
    float* out = (float*)d_out;

    __nv_bfloat16 *xn, *qkv, *vt, *attout, *h0, *h1, *w;
    float *x2, *maskf;
    cudaGetSymbolAddress((void**)&xn,     g_xn);
    cudaGetSymbolAddress((void**)&qkv,    g_qkv);
    cudaGetSymbolAddress((void**)&vt,     g_vt);
    cudaGetSymbolAddress((void**)&attout, g_attout);
    cudaGetSymbolAddress((void**)&h0,     g_h0);
    cudaGetSymbolAddress((void**)&h1,     g_h1);
    cudaGetSymbolAddress((void**)&w,      g_w);
    cudaGetSymbolAddress((void**)&x2,     g_x2);
    cudaGetSymbolAddress((void**)&maskf,  g_maskf);

    static int smem_set = 0;
    if (!smem_set) {
        cudaFuncSetAttribute(flash_kernel,
                             cudaFuncAttributeMaxDynamicSharedMemorySize, FLASH_SMEM);
        smem_set = 1;
    }

    // 0. convert all weights to bf16 in ONE launch
    round_copy_all_kernel<<<(NC_ALL + 255) / 256, 256>>>(
        qkv_w, proj_w, w1, w2, (unsigned*)w);

    // 1. LN1 + fused mask prep
    ln_kernel<<<NSEQ, 256>>>(x, n1s, n1b, xn);
    mask_fused_kernel<<<(NSEQ + 255) / 256, 256>>>(mask, maskf);

    // 2. QKV projection (BM=64: 882 tiles over 592 slots)
    mmgemm<EPI_QKV, 64><<<dim3(49, C3 / 128, 1), 128>>>(
        xn, w + WQKV_OFF, qkv, NSEQ, C3, CD, CD, CD, C3,
        q_bias, v_bias, nullptr, nullptr, vt);

    // 3-5. flash attention
    flash_kernel<<<dim3(25, NH), 128, FLASH_SMEM>>>(qkv, vt, maskf, attout);

    // 6. proj + residual (BM=64, 294 tiles, single round)
    mmgemm<EPI_RES, 64><<<dim3(49, CD / 128, 1), 128>>>(
        attout, w + WPROJ_OFF, x2, NSEQ, CD, CD, CD, CD, CD,
        proj_b, nullptr, x, g1, nullptr);

    // 7. LN2
    ln_kernel<<<NSEQ, 256>>>(x2, n2s, n2b, h0);

    // 8. MLP1 + exact GELU (BM=64: 1176 tiles = 1.99 rounds, near-perfect)
    mmgemm<EPI_GELU, 64><<<dim3(49, HID / 128, 1), 128>>>(
        h0, w + W1_OFF, h1, NSEQ, HID, CD, CD, CD, HID,
        b1, nullptr, nullptr, nullptr, nullptr);

    // 9. MLP2 + final residual (BM=64)
    mmgemm<EPI_RES, 64><<<dim3(49, CD / 128, 1), 128>>>(
        h1, w + W2_OFF, out, NSEQ, CD, HID, HID, HID, CD,
        b2, nullptr, x2, g2, nullptr);
}